// round 1
// baseline (speedup 1.0000x reference)
#include <cuda_runtime.h>
#include <cstdint>

// ---------------------------------------------------------------------------
// Problem dimensions (fixed by the reference)
// ---------------------------------------------------------------------------
#define BATCH    256
#define SEQL     8
#define HIDD     1024            // HID
#define D_INNER  2048
#define DSTATE   128
#define NHEADS   32
#define HEADDIM  64
#define CONV_DIM 2304            // D_INNER + 2*DSTATE
#define DPROJ    4384            // 2*D_INNER + 2*DSTATE + NHEADS
#define ROWS     (BATCH * SEQL)  // 2048

// ---------------------------------------------------------------------------
// Scratch (static device buffers; no allocation allowed in kernel_launch)
// ---------------------------------------------------------------------------
__device__ float g_a  [BATCH * 8192];     // MLP intermediate (256 x 8192)
__device__ float g_h  [ROWS  * HIDD];     // sequence activations (2048 x 1024)
__device__ float g_zx [ROWS  * DPROJ];    // zxbcdt (2048 x 4384)
__device__ float g_xbc[ROWS  * CONV_DIM]; // conv+silu output (2048 x 2304)
__device__ float g_dt [ROWS  * NHEADS];
__device__ float g_dA [ROWS  * NHEADS];
__device__ float g_y  [ROWS  * D_INNER];  // SSM output / gated-normed (2048 x 2048)

// ---------------------------------------------------------------------------
// Generic fp32 tiled GEMM: C = act(A @ W + bias)
// A: (M,K) row-major, W: (K,N) row-major. BM=128, BN=64, BK=16, 256 threads,
// 8x4 microtile per thread. Requires K % 16 == 0 (true for all call sites).
// ---------------------------------------------------------------------------
#define BM 128
#define BN 64
#define BK 16

template <int ACT>
__global__ void __launch_bounds__(256)
gemm_kernel(const float* __restrict__ A, const float* __restrict__ W,
            const float* __restrict__ bias, float* __restrict__ C,
            int M, int N, int K)
{
    __shared__ float As[BK][BM + 1];   // +1 pad: conflict-free transposed stores
    __shared__ float Ws[BK][BN];

    const int tid  = threadIdx.x;
    const int bm   = blockIdx.y * BM;
    const int bn   = blockIdx.x * BN;
    const int tx   = tid & 15;         // 0..15 -> 4 output cols each
    const int ty   = tid >> 4;         // 0..15 -> 8 output rows each
    const int arow = tid >> 2;         // 0..63
    const int acol = (tid & 3) * 4;    // 0,4,8,12
    const int wrow = tid >> 4;         // 0..15
    const int wcol = (tid & 15) * 4;   // 0..60

    float acc[8][4];
#pragma unroll
    for (int i = 0; i < 8; i++)
#pragma unroll
        for (int j = 0; j < 4; j++) acc[i][j] = 0.f;

    for (int k0 = 0; k0 < K; k0 += BK) {
        // --- load A tile (128 x 16), stored transposed [k][m]
#pragma unroll
        for (int half = 0; half < 2; half++) {
            int m = bm + arow + half * 64;
            float4 v = make_float4(0.f, 0.f, 0.f, 0.f);
            if (m < M)
                v = *(const float4*)(A + (size_t)m * K + k0 + acol);
            As[acol + 0][arow + half * 64] = v.x;
            As[acol + 1][arow + half * 64] = v.y;
            As[acol + 2][arow + half * 64] = v.z;
            As[acol + 3][arow + half * 64] = v.w;
        }
        // --- load W tile (16 x 64)
        {
            int kk = k0 + wrow;
            int n  = bn + wcol;
            if (n + 3 < N) {
                float4 v = *(const float4*)(W + (size_t)kk * N + n);
                Ws[wrow][wcol + 0] = v.x;
                Ws[wrow][wcol + 1] = v.y;
                Ws[wrow][wcol + 2] = v.z;
                Ws[wrow][wcol + 3] = v.w;
            } else {
#pragma unroll
                for (int j = 0; j < 4; j++)
                    Ws[wrow][wcol + j] = (n + j < N) ? W[(size_t)kk * N + n + j] : 0.f;
            }
        }
        __syncthreads();

#pragma unroll
        for (int k = 0; k < BK; k++) {
            float ra[8];
#pragma unroll
            for (int i = 0; i < 8; i++) ra[i] = As[k][ty * 8 + i];   // broadcast reads
            float4 rbv = *(const float4*)&Ws[k][tx * 4];             // LDS.128
            float rb[4] = {rbv.x, rbv.y, rbv.z, rbv.w};
#pragma unroll
            for (int i = 0; i < 8; i++)
#pragma unroll
                for (int j = 0; j < 4; j++)
                    acc[i][j] = fmaf(ra[i], rb[j], acc[i][j]);
        }
        __syncthreads();
    }

#pragma unroll
    for (int i = 0; i < 8; i++) {
        int m = bm + ty * 8 + i;
        if (m >= M) continue;
#pragma unroll
        for (int j = 0; j < 4; j++) {
            int n = bn + tx * 4 + j;
            if (n >= N) continue;
            float v = acc[i][j];
            if (bias) v += bias[n];
            if (ACT == 1) v = fmaxf(v, 0.f);
            C[(size_t)m * N + n] = v;
        }
    }
}

// ---------------------------------------------------------------------------
// Causal depthwise conv (DCONV=4) + bias + SiLU over the xBC slice of zxbcdt.
// out[b,l,c] = silu( sum_k xBC[b, l-3+k, c] * w[c,k] + conv_b[c] )
// ---------------------------------------------------------------------------
__global__ void conv_silu_kernel(const float* __restrict__ zx,
                                 const float* __restrict__ conv_w,
                                 const float* __restrict__ conv_b,
                                 float* __restrict__ xbc)
{
    int c = blockIdx.x * blockDim.x + threadIdx.x;
    int b = blockIdx.y;
    if (c >= CONV_DIM) return;

    float w0 = conv_w[c * 4 + 0], w1 = conv_w[c * 4 + 1];
    float w2 = conv_w[c * 4 + 2], w3 = conv_w[c * 4 + 3];
    float bb = conv_b[c];

    const float* src = zx + (size_t)b * SEQL * DPROJ + D_INNER + c;
    float v[SEQL];
#pragma unroll
    for (int l = 0; l < SEQL; l++) v[l] = src[(size_t)l * DPROJ];

#pragma unroll
    for (int l = 0; l < SEQL; l++) {
        float s = bb + v[l] * w3;
        if (l >= 1) s += v[l - 1] * w2;
        if (l >= 2) s += v[l - 2] * w1;
        if (l >= 3) s += v[l - 3] * w0;
        s = s / (1.f + expf(-s));   // silu
        xbc[((size_t)b * SEQL + l) * CONV_DIM + c] = s;
    }
}

// ---------------------------------------------------------------------------
// dt = softplus(dt_raw + dt_bias); dA = exp(-exp(A_log) * dt)
// dt_raw lives at zxbcdt[..., 4352 + h]
// ---------------------------------------------------------------------------
__global__ void dt_kernel(const float* __restrict__ zx,
                          const float* __restrict__ dt_bias,
                          const float* __restrict__ A_log,
                          float* __restrict__ dtb, float* __restrict__ dAb)
{
    int i = blockIdx.x * blockDim.x + threadIdx.x;
    if (i >= ROWS * NHEADS) return;
    int row = i >> 5, h = i & 31;
    float x = zx[(size_t)row * DPROJ + (D_INNER + CONV_DIM) + h] + dt_bias[h];
    float dt = (x > 20.f) ? x : log1pf(expf(x));
    float dA = expf(-expf(A_log[h]) * dt);
    dtb[i] = dt;
    dAb[i] = dA;
}

// ---------------------------------------------------------------------------
// SSM scan: one CTA per (batch, head). State h[64][128] in registers:
// thread t owns p = t>>2 and the s-subset { (t&3) + 4*i : i=0..31 }.
// Per step: st = dA*st + (dt*x[p])*B[s]; partial y[p] = sum st*C[s];
// reduce the 4 partials with shuffles; y_out = y + x[p]*D[h].
// ---------------------------------------------------------------------------
__global__ void __launch_bounds__(256)
scan_kernel(const float* __restrict__ xbc,
            const float* __restrict__ dtb, const float* __restrict__ dAb,
            const float* __restrict__ Dp, float* __restrict__ y)
{
    const int b = blockIdx.x;
    const int h = blockIdx.y;
    const int t = threadIdx.x;
    const int p = t >> 2;
    const int q = t & 3;

    __shared__ float Bsh[DSTATE];
    __shared__ float Csh[DSTATE];
    __shared__ float xsh[HEADDIM];
    __shared__ float sc[2];

    float st[32];
#pragma unroll
    for (int i = 0; i < 32; i++) st[i] = 0.f;
    const float Dh = Dp[h];

    for (int l = 0; l < SEQL; l++) {
        const int row = b * SEQL + l;
        const float* base = xbc + (size_t)row * CONV_DIM;
        if (t < 128) Bsh[t] = base[D_INNER + t];
        else         Csh[t - 128] = base[D_INNER + DSTATE + (t - 128)];
        if (t < HEADDIM) xsh[t] = base[h * HEADDIM + t];
        if (t == 0) { sc[0] = dAb[row * NHEADS + h]; sc[1] = dtb[row * NHEADS + h]; }
        __syncthreads();

        const float xv   = xsh[p];
        const float coef = sc[1] * xv;
        const float dAv  = sc[0];
        float part = 0.f;
#pragma unroll
        for (int i = 0; i < 32; i++) {
            const int s = q + 4 * i;               // interleaved: no bank conflicts
            st[i] = fmaf(dAv, st[i], coef * Bsh[s]);
            part  = fmaf(st[i], Csh[s], part);
        }
        part += __shfl_down_sync(0xffffffffu, part, 2);
        part += __shfl_down_sync(0xffffffffu, part, 1);
        if (q == 0)
            y[(size_t)row * D_INNER + h * HEADDIM + p] = part + xv * Dh;
        __syncthreads();
    }
}

// ---------------------------------------------------------------------------
// y = y * silu(z); y *= rsqrt(mean(y^2) + 1e-5) * norm_w   (per row, D=2048)
// In-place on ybuf. One CTA per row, 256 threads x 8 elements.
// ---------------------------------------------------------------------------
__global__ void __launch_bounds__(256)
gated_rmsnorm_kernel(float* __restrict__ ybuf, const float* __restrict__ zx,
                     const float* __restrict__ norm_w)
{
    const int row = blockIdx.x;
    const int t   = threadIdx.x;
    float* yb       = ybuf + (size_t)row * D_INNER;
    const float* zb = zx   + (size_t)row * DPROJ;   // z = zxbcdt[..., :D_INNER]

    float v[8];
    float ss = 0.f;
#pragma unroll
    for (int j = 0; j < 8; j++) {
        int d = t + j * 256;
        float z   = zb[d];
        float val = yb[d] * (z / (1.f + expf(-z)));
        v[j] = val;
        ss  = fmaf(val, val, ss);
    }
#pragma unroll
    for (int o = 16; o > 0; o >>= 1)
        ss += __shfl_down_sync(0xffffffffu, ss, o);

    __shared__ float red[8];
    __shared__ float s_scale;
    if ((t & 31) == 0) red[t >> 5] = ss;
    __syncthreads();
    if (t == 0) {
        float s = 0.f;
        for (int i = 0; i < 8; i++) s += red[i];
        s_scale = rsqrtf(s / (float)D_INNER + 1e-5f);
    }
    __syncthreads();
    const float scale = s_scale;
#pragma unroll
    for (int j = 0; j < 8; j++) {
        int d = t + j * 256;
        yb[d] = v[j] * scale * norm_w[d];
    }
}

// ---------------------------------------------------------------------------
// Host-side orchestration
// ---------------------------------------------------------------------------
struct MambaW {
    const float *in_proj, *conv_w, *conv_b, *dt_bias, *A_log, *D, *norm_w, *out_proj;
};

static inline dim3 gemm_grid(int M, int N)
{
    return dim3((unsigned)((N + BN - 1) / BN), (unsigned)((M + BM - 1) / BM));
}

static void run_mamba(const MambaW& p,
                      float* h_ptr, float* zx, float* xbc,
                      float* dtb, float* dAb, float* ybuf)
{
    // zxbcdt = h @ in_proj : (2048,1024)@(1024,4384)
    gemm_kernel<0><<<gemm_grid(ROWS, DPROJ), 256>>>(h_ptr, p.in_proj, nullptr, zx,
                                                    ROWS, DPROJ, HIDD);
    conv_silu_kernel<<<dim3(CONV_DIM / 256, BATCH), 256>>>(zx, p.conv_w, p.conv_b, xbc);
    dt_kernel<<<(ROWS * NHEADS) / 256, 256>>>(zx, p.dt_bias, p.A_log, dtb, dAb);
    scan_kernel<<<dim3(BATCH, NHEADS), 256>>>(xbc, dtb, dAb, p.D, ybuf);
    gated_rmsnorm_kernel<<<ROWS, 256>>>(ybuf, zx, p.norm_w);
    // h = y @ out_proj : (2048,2048)@(2048,1024)
    gemm_kernel<0><<<gemm_grid(ROWS, HIDD), 256>>>(ybuf, p.out_proj, nullptr, h_ptr,
                                                   ROWS, HIDD, D_INNER);
}

extern "C" void kernel_launch(void* const* d_in, const int* in_sizes, int n_in,
                              void* d_out, int out_size)
{
    const float* x      = (const float*)d_in[0];
    const float* w_in1  = (const float*)d_in[1];
    const float* b_in1  = (const float*)d_in[2];
    const float* w_in2  = (const float*)d_in[3];
    const float* b_in2  = (const float*)d_in[4];
    MambaW m1 = { (const float*)d_in[5],  (const float*)d_in[6],  (const float*)d_in[7],
                  (const float*)d_in[8],  (const float*)d_in[9],  (const float*)d_in[10],
                  (const float*)d_in[11], (const float*)d_in[12] };
    MambaW m2 = { (const float*)d_in[13], (const float*)d_in[14], (const float*)d_in[15],
                  (const float*)d_in[16], (const float*)d_in[17], (const float*)d_in[18],
                  (const float*)d_in[19], (const float*)d_in[20] };
    const float* w_out1 = (const float*)d_in[21];
    const float* b_out1 = (const float*)d_in[22];
    const float* w_out2 = (const float*)d_in[23];
    const float* b_out2 = (const float*)d_in[24];
    float* out = (float*)d_out;

    float *a, *h, *zx, *xbc, *dtb, *dAb, *ybuf;
    cudaGetSymbolAddress((void**)&a,    g_a);
    cudaGetSymbolAddress((void**)&h,    g_h);
    cudaGetSymbolAddress((void**)&zx,   g_zx);
    cudaGetSymbolAddress((void**)&xbc,  g_xbc);
    cudaGetSymbolAddress((void**)&dtb,  g_dt);
    cudaGetSymbolAddress((void**)&dAb,  g_dA);
    cudaGetSymbolAddress((void**)&ybuf, g_y);

    // MLP in: a = relu(x @ w_in1 + b_in1); h = a @ w_in2 + b_in2
    gemm_kernel<1><<<gemm_grid(BATCH, 8192), 256>>>(x, w_in1, b_in1, a,
                                                    BATCH, 8192, 1024);
    gemm_kernel<0><<<gemm_grid(BATCH, 8192), 256>>>(a, w_in2, b_in2, h,
                                                    BATCH, 8192, 8192);

    // 2x Mamba2 layers (h viewed as (2048, 1024) == (256, 8, 1024))
    run_mamba(m1, h, zx, xbc, dtb, dAb, ybuf);
    run_mamba(m2, h, zx, xbc, dtb, dAb, ybuf);

    // MLP out: a = relu(h(256,8192) @ w_out1 + b_out1); out = a @ w_out2 + b_out2
    gemm_kernel<1><<<gemm_grid(BATCH, 1024), 256>>>(h, w_out1, b_out1, a,
                                                    BATCH, 1024, 8192);
    gemm_kernel<0><<<gemm_grid(BATCH, 2), 256>>>(a, w_out2, b_out2, out,
                                                 BATCH, 2, 1024);
}

// round 3
// speedup vs baseline: 1.2681x; 1.2681x over previous
#include <cuda_runtime.h>
#include <cstdint>

// ---------------------------------------------------------------------------
// Problem dimensions (fixed by the reference)
// ---------------------------------------------------------------------------
#define BATCH    256
#define SEQL     8
#define HIDD     1024            // HID
#define D_INNER  2048
#define DSTATE   128
#define NHEADS   32
#define HEADDIM  64
#define CONV_DIM 2304            // D_INNER + 2*DSTATE
#define DPROJ    4384            // 2*D_INNER + 2*DSTATE + NHEADS
#define ROWS     (BATCH * SEQL)  // 2048

// ---------------------------------------------------------------------------
// Scratch (static device buffers; no allocation allowed in kernel_launch)
// ---------------------------------------------------------------------------
__device__ float g_a  [BATCH * 8192];     // MLP intermediate (256 x 8192)
__device__ float g_h  [ROWS  * HIDD];     // sequence activations (2048 x 1024)
__device__ float g_zx [ROWS  * DPROJ];    // zxbcdt (2048 x 4384)
__device__ float g_xbc[ROWS  * CONV_DIM]; // conv+silu output (2048 x 2304)
__device__ float g_dt [ROWS  * NHEADS];
__device__ float g_dA [ROWS  * NHEADS];
__device__ float g_y  [ROWS  * D_INNER];  // SSM output / gated-normed (2048 x 2048)

// ---------------------------------------------------------------------------
// 3xTF32 tensor-core GEMM: C = act(A @ W + bias), fp32-accurate.
// Each fp32 operand is split x = hi + lo (hi = tf32(x), lo = tf32(x-hi));
// product uses hi*hi + hi*lo + lo*hi (3 MMAs), giving ~22-bit effective
// operand mantissa with fp32 accumulation.
// A: (M,K) row-major fp32, W: (K,N) row-major fp32.
// CTA tile 128x128, BK=32, 256 threads = 8 warps (2 x 4), warp tile 64x32.
// mma.sync.aligned.m16n8k8.row.col.f32.tf32.tf32.f32
// Requires: K % 32 == 0, N % 4 == 0 (true at all call sites).
// Dynamic smem: hi/lo tiles for A and W.
// ---------------------------------------------------------------------------
#define TBM 128
#define TBN 128
#define TBK 32
#define AS_STRIDE 36    // (4g+q) bank map bijective -> conflict-free A frags
#define WS_STRIDE 136   // (8q+g) bank map bijective -> conflict-free B frags
#define A_TILE (TBM * AS_STRIDE)        // 4608 floats
#define W_TILE (TBK * WS_STRIDE)        // 4352 floats
#define GEMM_SMEM_BYTES ((A_TILE + W_TILE) * 2 * 4)   // 71680 bytes

__device__ __forceinline__ float to_tf32(float x) {
    float r;
    asm("cvt.rna.tf32.f32 %0, %1;" : "=f"(r) : "f"(x));
    return r;
}

#define MMA_TF32(ACCP, A0, A1, A2, A3, B0, B1)                              \
    asm volatile(                                                           \
        "mma.sync.aligned.m16n8k8.row.col.f32.tf32.tf32.f32 "               \
        "{%0,%1,%2,%3}, {%4,%5,%6,%7}, {%8,%9}, {%0,%1,%2,%3};\n"           \
        : "+f"((ACCP)[0]), "+f"((ACCP)[1]), "+f"((ACCP)[2]), "+f"((ACCP)[3])\
        : "r"(A0), "r"(A1), "r"(A2), "r"(A3), "r"(B0), "r"(B1))

template <int ACT>
__global__ void __launch_bounds__(256)
mma_gemm_kernel(const float* __restrict__ A, const float* __restrict__ W,
                const float* __restrict__ bias, float* __restrict__ C,
                int M, int N, int K)
{
    extern __shared__ float smem[];
    float* Ah = smem;                       // [m][k] hi, stride 36
    float* Al = Ah + A_TILE;                // [m][k] lo
    float* Wh = Al + A_TILE;                // [k][n] hi, stride 136
    float* Wl = Wh + W_TILE;                // [k][n] lo

    const int tid  = threadIdx.x;
    const int lane = tid & 31;
    const int warp = tid >> 5;
    const int wm   = warp >> 2;        // 0..1  (M dir)
    const int wn   = warp & 3;         // 0..3  (N dir)
    const int bm   = blockIdx.y * TBM;
    const int bn   = blockIdx.x * TBN;

    const int g = lane >> 2;           // 0..7
    const int q = lane & 3;            // 0..3

    float acc[4][4][4];                // [mi][ni][frag]
#pragma unroll
    for (int mi = 0; mi < 4; mi++)
#pragma unroll
        for (int ni = 0; ni < 4; ni++)
#pragma unroll
            for (int f = 0; f < 4; f++) acc[mi][ni][f] = 0.f;

    const uint32_t* Ahu = (const uint32_t*)Ah;
    const uint32_t* Alu = (const uint32_t*)Al;
    const uint32_t* Whu = (const uint32_t*)Wh;
    const uint32_t* Wlu = (const uint32_t*)Wl;

    for (int k0 = 0; k0 < K; k0 += TBK) {
        // ---- fill A tiles: 128 x 32 floats = 1024 float4, 4 per thread
#pragma unroll
        for (int i = 0; i < 4; i++) {
            int s    = tid + i * 256;      // 0..1023
            int row  = s >> 3;             // 0..127
            int col  = (s & 7) * 4;        // 0..28
            float4 v = make_float4(0.f, 0.f, 0.f, 0.f);
            int m = bm + row;
            if (m < M)
                v = *(const float4*)(A + (size_t)m * K + k0 + col);
            float hx = to_tf32(v.x), hy = to_tf32(v.y);
            float hz = to_tf32(v.z), hw = to_tf32(v.w);
            float* dh = &Ah[row * AS_STRIDE + col];
            float* dl = &Al[row * AS_STRIDE + col];
            dh[0] = hx; dh[1] = hy; dh[2] = hz; dh[3] = hw;
            dl[0] = to_tf32(v.x - hx); dl[1] = to_tf32(v.y - hy);
            dl[2] = to_tf32(v.z - hz); dl[3] = to_tf32(v.w - hw);
        }
        // ---- fill W tiles: 32 x 128 floats = 1024 float4, 4 per thread
#pragma unroll
        for (int i = 0; i < 4; i++) {
            int s   = tid + i * 256;
            int row = s >> 5;              // 0..31
            int col = (s & 31) * 4;        // 0..124
            float4 v = make_float4(0.f, 0.f, 0.f, 0.f);
            int n = bn + col;
            if (n < N)                     // N % 4 == 0 -> all-or-nothing
                v = *(const float4*)(W + (size_t)(k0 + row) * N + n);
            float hx = to_tf32(v.x), hy = to_tf32(v.y);
            float hz = to_tf32(v.z), hw = to_tf32(v.w);
            float* dh = &Wh[row * WS_STRIDE + col];
            float* dl = &Wl[row * WS_STRIDE + col];
            dh[0] = hx; dh[1] = hy; dh[2] = hz; dh[3] = hw;
            dl[0] = to_tf32(v.x - hx); dl[1] = to_tf32(v.y - hy);
            dl[2] = to_tf32(v.z - hz); dl[3] = to_tf32(v.w - hw);
        }
        __syncthreads();

#pragma unroll
        for (int ks = 0; ks < TBK / 8; ks++) {
            const int kb = ks * 8;
            uint32_t afh[4][4], afl[4][4];
#pragma unroll
            for (int mi = 0; mi < 4; mi++) {
                int r0 = wm * 64 + mi * 16;
                int i00 = (r0 + g    ) * AS_STRIDE + kb + q;
                int i10 = (r0 + g + 8) * AS_STRIDE + kb + q;
                afh[mi][0] = Ahu[i00];     afh[mi][1] = Ahu[i10];
                afh[mi][2] = Ahu[i00 + 4]; afh[mi][3] = Ahu[i10 + 4];
                afl[mi][0] = Alu[i00];     afl[mi][1] = Alu[i10];
                afl[mi][2] = Alu[i00 + 4]; afl[mi][3] = Alu[i10 + 4];
            }
            uint32_t bfh[4][2], bfl[4][2];
#pragma unroll
            for (int ni = 0; ni < 4; ni++) {
                int c0 = wn * 32 + ni * 8;
                int j0 = (kb + q    ) * WS_STRIDE + c0 + g;
                int j1 = (kb + q + 4) * WS_STRIDE + c0 + g;
                bfh[ni][0] = Whu[j0]; bfh[ni][1] = Whu[j1];
                bfl[ni][0] = Wlu[j0]; bfl[ni][1] = Wlu[j1];
            }
#pragma unroll
            for (int mi = 0; mi < 4; mi++)
#pragma unroll
                for (int ni = 0; ni < 4; ni++) {
                    float* ap = acc[mi][ni];
                    // hi*hi
                    MMA_TF32(ap, afh[mi][0], afh[mi][1], afh[mi][2], afh[mi][3],
                             bfh[ni][0], bfh[ni][1]);
                    // hi*lo
                    MMA_TF32(ap, afh[mi][0], afh[mi][1], afh[mi][2], afh[mi][3],
                             bfl[ni][0], bfl[ni][1]);
                    // lo*hi
                    MMA_TF32(ap, afl[mi][0], afl[mi][1], afl[mi][2], afl[mi][3],
                             bfh[ni][0], bfh[ni][1]);
                }
        }
        __syncthreads();
    }

    // ---- epilogue (N always even at call sites -> pairwise guard ok)
#pragma unroll
    for (int mi = 0; mi < 4; mi++) {
        int r0 = bm + wm * 64 + mi * 16;
#pragma unroll
        for (int ni = 0; ni < 4; ni++) {
            int c0 = bn + wn * 32 + ni * 8 + 2 * q;
            if (c0 >= N) continue;
            float b0 = bias ? bias[c0]     : 0.f;
            float b1 = bias ? bias[c0 + 1] : 0.f;
#pragma unroll
            for (int half = 0; half < 2; half++) {
                int m = r0 + g + half * 8;
                if (m >= M) continue;
                float v0 = acc[mi][ni][half * 2 + 0] + b0;
                float v1 = acc[mi][ni][half * 2 + 1] + b1;
                if (ACT == 1) { v0 = fmaxf(v0, 0.f); v1 = fmaxf(v1, 0.f); }
                float2* dst = (float2*)(C + (size_t)m * N + c0);
                *dst = make_float2(v0, v1);
            }
        }
    }
}

// ---------------------------------------------------------------------------
// Small fp32 SIMT GEMM (kept for the tiny final layer N=2)
// ---------------------------------------------------------------------------
#define BM 128
#define BN 64
#define BK 16

template <int ACT>
__global__ void __launch_bounds__(256)
gemm_kernel(const float* __restrict__ A, const float* __restrict__ W,
            const float* __restrict__ bias, float* __restrict__ C,
            int M, int N, int K)
{
    __shared__ float As[BK][BM + 1];
    __shared__ float Ws[BK][BN];

    const int tid  = threadIdx.x;
    const int bm   = blockIdx.y * BM;
    const int bn   = blockIdx.x * BN;
    const int tx   = tid & 15;
    const int ty   = tid >> 4;
    const int arow = tid >> 2;
    const int acol = (tid & 3) * 4;
    const int wrow = tid >> 4;
    const int wcol = (tid & 15) * 4;

    float acc[8][4];
#pragma unroll
    for (int i = 0; i < 8; i++)
#pragma unroll
        for (int j = 0; j < 4; j++) acc[i][j] = 0.f;

    for (int k0 = 0; k0 < K; k0 += BK) {
#pragma unroll
        for (int half = 0; half < 2; half++) {
            int m = bm + arow + half * 64;
            float4 v = make_float4(0.f, 0.f, 0.f, 0.f);
            if (m < M)
                v = *(const float4*)(A + (size_t)m * K + k0 + acol);
            As[acol + 0][arow + half * 64] = v.x;
            As[acol + 1][arow + half * 64] = v.y;
            As[acol + 2][arow + half * 64] = v.z;
            As[acol + 3][arow + half * 64] = v.w;
        }
        {
            int kk = k0 + wrow;
            int n  = bn + wcol;
#pragma unroll
            for (int j = 0; j < 4; j++)
                Ws[wrow][wcol + j] = (n + j < N) ? W[(size_t)kk * N + n + j] : 0.f;
        }
        __syncthreads();

#pragma unroll
        for (int k = 0; k < BK; k++) {
            float ra[8];
#pragma unroll
            for (int i = 0; i < 8; i++) ra[i] = As[k][ty * 8 + i];
            float rb[4];
#pragma unroll
            for (int j = 0; j < 4; j++) rb[j] = Ws[k][tx * 4 + j];
#pragma unroll
            for (int i = 0; i < 8; i++)
#pragma unroll
                for (int j = 0; j < 4; j++)
                    acc[i][j] = fmaf(ra[i], rb[j], acc[i][j]);
        }
        __syncthreads();
    }

#pragma unroll
    for (int i = 0; i < 8; i++) {
        int m = bm + ty * 8 + i;
        if (m >= M) continue;
#pragma unroll
        for (int j = 0; j < 4; j++) {
            int n = bn + tx * 4 + j;
            if (n >= N) continue;
            float v = acc[i][j];
            if (bias) v += bias[n];
            if (ACT == 1) v = fmaxf(v, 0.f);
            C[(size_t)m * N + n] = v;
        }
    }
}

// ---------------------------------------------------------------------------
// Causal depthwise conv (DCONV=4) + bias + SiLU over the xBC slice of zxbcdt.
// ---------------------------------------------------------------------------
__global__ void conv_silu_kernel(const float* __restrict__ zx,
                                 const float* __restrict__ conv_w,
                                 const float* __restrict__ conv_b,
                                 float* __restrict__ xbc)
{
    int c = blockIdx.x * blockDim.x + threadIdx.x;
    int b = blockIdx.y;
    if (c >= CONV_DIM) return;

    float w0 = conv_w[c * 4 + 0], w1 = conv_w[c * 4 + 1];
    float w2 = conv_w[c * 4 + 2], w3 = conv_w[c * 4 + 3];
    float bb = conv_b[c];

    const float* src = zx + (size_t)b * SEQL * DPROJ + D_INNER + c;
    float v[SEQL];
#pragma unroll
    for (int l = 0; l < SEQL; l++) v[l] = src[(size_t)l * DPROJ];

#pragma unroll
    for (int l = 0; l < SEQL; l++) {
        float s = bb + v[l] * w3;
        if (l >= 1) s += v[l - 1] * w2;
        if (l >= 2) s += v[l - 2] * w1;
        if (l >= 3) s += v[l - 3] * w0;
        s = s / (1.f + expf(-s));   // silu
        xbc[((size_t)b * SEQL + l) * CONV_DIM + c] = s;
    }
}

// ---------------------------------------------------------------------------
// dt = softplus(dt_raw + dt_bias); dA = exp(-exp(A_log) * dt)
// ---------------------------------------------------------------------------
__global__ void dt_kernel(const float* __restrict__ zx,
                          const float* __restrict__ dt_bias,
                          const float* __restrict__ A_log,
                          float* __restrict__ dtb, float* __restrict__ dAb)
{
    int i = blockIdx.x * blockDim.x + threadIdx.x;
    if (i >= ROWS * NHEADS) return;
    int row = i >> 5, h = i & 31;
    float x = zx[(size_t)row * DPROJ + (D_INNER + CONV_DIM) + h] + dt_bias[h];
    float dt = (x > 20.f) ? x : log1pf(expf(x));
    float dA = expf(-expf(A_log[h]) * dt);
    dtb[i] = dt;
    dAb[i] = dA;
}

// ---------------------------------------------------------------------------
// SSM scan: one CTA per (batch, head). State h[64][128] in registers.
// ---------------------------------------------------------------------------
__global__ void __launch_bounds__(256)
scan_kernel(const float* __restrict__ xbc,
            const float* __restrict__ dtb, const float* __restrict__ dAb,
            const float* __restrict__ Dp, float* __restrict__ y)
{
    const int b = blockIdx.x;
    const int h = blockIdx.y;
    const int t = threadIdx.x;
    const int p = t >> 2;
    const int q = t & 3;

    __shared__ float Bsh[DSTATE];
    __shared__ float Csh[DSTATE];
    __shared__ float xsh[HEADDIM];
    __shared__ float sc[2];

    float st[32];
#pragma unroll
    for (int i = 0; i < 32; i++) st[i] = 0.f;
    const float Dh = Dp[h];

    for (int l = 0; l < SEQL; l++) {
        const int row = b * SEQL + l;
        const float* base = xbc + (size_t)row * CONV_DIM;
        if (t < 128) Bsh[t] = base[D_INNER + t];
        else         Csh[t - 128] = base[D_INNER + DSTATE + (t - 128)];
        if (t < HEADDIM) xsh[t] = base[h * HEADDIM + t];
        if (t == 0) { sc[0] = dAb[row * NHEADS + h]; sc[1] = dtb[row * NHEADS + h]; }
        __syncthreads();

        const float xv   = xsh[p];
        const float coef = sc[1] * xv;
        const float dAv  = sc[0];
        float part = 0.f;
#pragma unroll
        for (int i = 0; i < 32; i++) {
            const int s = q + 4 * i;
            st[i] = fmaf(dAv, st[i], coef * Bsh[s]);
            part  = fmaf(st[i], Csh[s], part);
        }
        part += __shfl_down_sync(0xffffffffu, part, 2);
        part += __shfl_down_sync(0xffffffffu, part, 1);
        if (q == 0)
            y[(size_t)row * D_INNER + h * HEADDIM + p] = part + xv * Dh;
        __syncthreads();
    }
}

// ---------------------------------------------------------------------------
// y = y * silu(z); y *= rsqrt(mean(y^2) + 1e-5) * norm_w
// ---------------------------------------------------------------------------
__global__ void __launch_bounds__(256)
gated_rmsnorm_kernel(float* __restrict__ ybuf, const float* __restrict__ zx,
                     const float* __restrict__ norm_w)
{
    const int row = blockIdx.x;
    const int t   = threadIdx.x;
    float* yb       = ybuf + (size_t)row * D_INNER;
    const float* zb = zx   + (size_t)row * DPROJ;

    float v[8];
    float ss = 0.f;
#pragma unroll
    for (int j = 0; j < 8; j++) {
        int d = t + j * 256;
        float z   = zb[d];
        float val = yb[d] * (z / (1.f + expf(-z)));
        v[j] = val;
        ss  = fmaf(val, val, ss);
    }
#pragma unroll
    for (int o = 16; o > 0; o >>= 1)
        ss += __shfl_down_sync(0xffffffffu, ss, o);

    __shared__ float red[8];
    __shared__ float s_scale;
    if ((t & 31) == 0) red[t >> 5] = ss;
    __syncthreads();
    if (t == 0) {
        float s = 0.f;
        for (int i = 0; i < 8; i++) s += red[i];
        s_scale = rsqrtf(s / (float)D_INNER + 1e-5f);
    }
    __syncthreads();
    const float scale = s_scale;
#pragma unroll
    for (int j = 0; j < 8; j++) {
        int d = t + j * 256;
        yb[d] = v[j] * scale * norm_w[d];
    }
}

// ---------------------------------------------------------------------------
// Host-side orchestration
// ---------------------------------------------------------------------------
struct MambaW {
    const float *in_proj, *conv_w, *conv_b, *dt_bias, *A_log, *D, *norm_w, *out_proj;
};

static inline dim3 mma_grid(int M, int N)
{
    return dim3((unsigned)((N + TBN - 1) / TBN), (unsigned)((M + TBM - 1) / TBM));
}

static void run_mamba(const MambaW& p,
                      float* h_ptr, float* zx, float* xbc,
                      float* dtb, float* dAb, float* ybuf)
{
    // zxbcdt = h @ in_proj : (2048,1024)@(1024,4384)
    mma_gemm_kernel<0><<<mma_grid(ROWS, DPROJ), 256, GEMM_SMEM_BYTES>>>(
        h_ptr, p.in_proj, nullptr, zx, ROWS, DPROJ, HIDD);
    conv_silu_kernel<<<dim3(CONV_DIM / 256, BATCH), 256>>>(zx, p.conv_w, p.conv_b, xbc);
    dt_kernel<<<(ROWS * NHEADS) / 256, 256>>>(zx, p.dt_bias, p.A_log, dtb, dAb);
    scan_kernel<<<dim3(BATCH, NHEADS), 256>>>(xbc, dtb, dAb, p.D, ybuf);
    gated_rmsnorm_kernel<<<ROWS, 256>>>(ybuf, zx, p.norm_w);
    // h = y @ out_proj : (2048,2048)@(2048,1024)
    mma_gemm_kernel<0><<<mma_grid(ROWS, HIDD), 256, GEMM_SMEM_BYTES>>>(
        ybuf, p.out_proj, nullptr, h_ptr, ROWS, HIDD, D_INNER);
}

extern "C" void kernel_launch(void* const* d_in, const int* in_sizes, int n_in,
                              void* d_out, int out_size)
{
    const float* x      = (const float*)d_in[0];
    const float* w_in1  = (const float*)d_in[1];
    const float* b_in1  = (const float*)d_in[2];
    const float* w_in2  = (const float*)d_in[3];
    const float* b_in2  = (const float*)d_in[4];
    MambaW m1 = { (const float*)d_in[5],  (const float*)d_in[6],  (const float*)d_in[7],
                  (const float*)d_in[8],  (const float*)d_in[9],  (const float*)d_in[10],
                  (const float*)d_in[11], (const float*)d_in[12] };
    MambaW m2 = { (const float*)d_in[13], (const float*)d_in[14], (const float*)d_in[15],
                  (const float*)d_in[16], (const float*)d_in[17], (const float*)d_in[18],
                  (const float*)d_in[19], (const float*)d_in[20] };
    const float* w_out1 = (const float*)d_in[21];
    const float* b_out1 = (const float*)d_in[22];
    const float* w_out2 = (const float*)d_in[23];
    const float* b_out2 = (const float*)d_in[24];
    float* out = (float*)d_out;

    // raise dynamic smem limit for the MMA GEMM (idempotent, capture-safe)
    cudaFuncSetAttribute(mma_gemm_kernel<0>,
                         cudaFuncAttributeMaxDynamicSharedMemorySize, GEMM_SMEM_BYTES);
    cudaFuncSetAttribute(mma_gemm_kernel<1>,
                         cudaFuncAttributeMaxDynamicSharedMemorySize, GEMM_SMEM_BYTES);

    float *a, *h, *zx, *xbc, *dtb, *dAb, *ybuf;
    cudaGetSymbolAddress((void**)&a,    g_a);
    cudaGetSymbolAddress((void**)&h,    g_h);
    cudaGetSymbolAddress((void**)&zx,   g_zx);
    cudaGetSymbolAddress((void**)&xbc,  g_xbc);
    cudaGetSymbolAddress((void**)&dtb,  g_dt);
    cudaGetSymbolAddress((void**)&dAb,  g_dA);
    cudaGetSymbolAddress((void**)&ybuf, g_y);

    // MLP in: a = relu(x @ w_in1 + b_in1); h = a @ w_in2 + b_in2
    mma_gemm_kernel<1><<<mma_grid(BATCH, 8192), 256, GEMM_SMEM_BYTES>>>(
        x, w_in1, b_in1, a, BATCH, 8192, 1024);
    mma_gemm_kernel<0><<<mma_grid(BATCH, 8192), 256, GEMM_SMEM_BYTES>>>(
        a, w_in2, b_in2, h, BATCH, 8192, 8192);

    // 2x Mamba2 layers (h viewed as (2048, 1024) == (256, 8, 1024))
    run_mamba(m1, h, zx, xbc, dtb, dAb, ybuf);
    run_mamba(m2, h, zx, xbc, dtb, dAb, ybuf);

    // MLP out: a = relu(h(256,8192) @ w_out1 + b_out1); out = a @ w_out2 + b_out2
    mma_gemm_kernel<1><<<mma_grid(BATCH, 1024), 256, GEMM_SMEM_BYTES>>>(
        h, w_out1, b_out1, a, BATCH, 1024, 8192);
    gemm_kernel<0><<<dim3(1, (BATCH + BM - 1) / BM), 256>>>(a, w_out2, b_out2, out,
                                                            BATCH, 2, 1024);
}

// round 4
// speedup vs baseline: 1.2864x; 1.0144x over previous
#include <cuda_runtime.h>
#include <cstdint>

// ---------------------------------------------------------------------------
// Problem dimensions (fixed by the reference)
// ---------------------------------------------------------------------------
#define BATCH    256
#define SEQL     8
#define HIDD     1024            // HID
#define D_INNER  2048
#define DSTATE   128
#define NHEADS   32
#define HEADDIM  64
#define CONV_DIM 2304            // D_INNER + 2*DSTATE
#define DPROJ    4384            // 2*D_INNER + 2*DSTATE + NHEADS
#define ROWS     (BATCH * SEQL)  // 2048

// ---------------------------------------------------------------------------
// Scratch (static device buffers; no allocation allowed in kernel_launch)
// ---------------------------------------------------------------------------
__device__ float g_a  [BATCH * 8192];     // MLP intermediate (256 x 8192)
__device__ float g_h  [ROWS  * HIDD];     // sequence activations (2048 x 1024)
__device__ float g_zx [ROWS  * DPROJ];    // zxbcdt (2048 x 4384)
__device__ float g_xbc[ROWS  * CONV_DIM]; // conv+silu output (2048 x 2304)
__device__ float g_dt [ROWS  * NHEADS];
__device__ float g_dA [ROWS  * NHEADS];
__device__ float g_y  [ROWS  * D_INNER];  // SSM output / gated-normed (2048 x 2048)

// ---------------------------------------------------------------------------
// 3xTF32 tensor-core GEMM, cp.async double-buffered.
// smem holds RAW fp32 tiles (single copy, 2 stages); the hi/lo tf32 split
// (x = hi + lo, products hi*hi + hi*lo + lo*hi) happens in registers at
// fragment-load time. fp32 accumulate -> ~22-bit effective operand mantissa.
// A: (M,K) row-major fp32, W: (K,N) row-major fp32.
// CTA tile 128x128, BK=32, 256 threads = 8 warps (2x4), warp tile 64x32.
// mma.sync.aligned.m16n8k8.row.col.f32.tf32.tf32.f32
// Requires: M % 128 == 0, K % 32 == 0, N % 4 == 0 (true at all call sites).
// ---------------------------------------------------------------------------
#define TBM 128
#define TBN 128
#define TBK 32
#define AS_STRIDE 36    // (4g+q) bank map bijective -> conflict-free A frags
#define WS_STRIDE 136   // (8q+g) bank map bijective -> conflict-free B frags
#define A_TILE (TBM * AS_STRIDE)        // 4608 floats
#define W_TILE (TBK * WS_STRIDE)        // 4352 floats
#define GEMM_SMEM_BYTES ((A_TILE + W_TILE) * 2 * 4)   // 71680 bytes (2 stages)

__device__ __forceinline__ float to_tf32(float x) {
    float r;
    asm("cvt.rna.tf32.f32 %0, %1;" : "=f"(r) : "f"(x));
    return r;
}

// split x into (hi, lo) tf32 bit-patterns
__device__ __forceinline__ void split_tf32(float x, uint32_t& hi, uint32_t& lo) {
    float h = to_tf32(x);
    hi = __float_as_uint(h);
    lo = __float_as_uint(to_tf32(x - h));
}

__device__ __forceinline__ void cp_async16(void* smem_dst, const void* gsrc, bool pred) {
    uint32_t saddr = (uint32_t)__cvta_generic_to_shared(smem_dst);
    int sz = pred ? 16 : 0;
    asm volatile("cp.async.cg.shared.global [%0], [%1], 16, %2;\n"
                 :: "r"(saddr), "l"(gsrc), "r"(sz));
}
__device__ __forceinline__ void cp_commit() {
    asm volatile("cp.async.commit_group;\n");
}

#define MMA_TF32(ACCP, A0, A1, A2, A3, B0, B1)                              \
    asm volatile(                                                           \
        "mma.sync.aligned.m16n8k8.row.col.f32.tf32.tf32.f32 "               \
        "{%0,%1,%2,%3}, {%4,%5,%6,%7}, {%8,%9}, {%0,%1,%2,%3};\n"           \
        : "+f"((ACCP)[0]), "+f"((ACCP)[1]), "+f"((ACCP)[2]), "+f"((ACCP)[3])\
        : "r"(A0), "r"(A1), "r"(A2), "r"(A3), "r"(B0), "r"(B1))

template <int ACT>
__global__ void __launch_bounds__(256)
mma_gemm_kernel(const float* __restrict__ A, const float* __restrict__ W,
                const float* __restrict__ bias, float* __restrict__ C,
                int M, int N, int K)
{
    extern __shared__ float smem[];
    float* Abuf[2] = { smem,                     smem + A_TILE };
    float* Wbuf[2] = { smem + 2 * A_TILE,        smem + 2 * A_TILE + W_TILE };

    const int tid  = threadIdx.x;
    const int lane = tid & 31;
    const int warp = tid >> 5;
    const int wm   = warp >> 2;        // 0..1  (M dir)
    const int wn   = warp & 3;         // 0..3  (N dir)
    const int bm   = blockIdx.y * TBM;
    const int bn   = blockIdx.x * TBN;

    const int g = lane >> 2;           // 0..7
    const int q = lane & 3;            // 0..3

    // fill-index precompute (4 chunks per thread per tile)
    const int a_row = tid >> 3;              // will add i*... see loop
    (void)a_row;

    float acc[4][4][4];                // [mi][ni][frag]
#pragma unroll
    for (int mi = 0; mi < 4; mi++)
#pragma unroll
        for (int ni = 0; ni < 4; ni++)
#pragma unroll
            for (int f = 0; f < 4; f++) acc[mi][ni][f] = 0.f;

    const int nslabs = K / TBK;

    // ---- slab fill: A 128x32 (1024 f4), W 32x128 (1024 f4); 4 f4/thread each
    auto issue_slab = [&](int slab, int buf) {
        const int k0 = slab * TBK;
#pragma unroll
        for (int i = 0; i < 4; i++) {
            int s   = tid + i * 256;       // 0..1023
            int row = s >> 3;              // 0..127
            int col = (s & 7) * 4;         // 0..28
            const float* src = A + (size_t)(bm + row) * K + k0 + col; // M full tiles
            cp_async16(&Abuf[buf][row * AS_STRIDE + col], src, true);
        }
#pragma unroll
        for (int i = 0; i < 4; i++) {
            int s   = tid + i * 256;
            int row = s >> 5;              // 0..31
            int col = (s & 31) * 4;        // 0..124
            int n   = bn + col;
            bool p  = (n < N);             // N % 4 == 0 -> all-or-nothing
            const float* src = p ? (W + (size_t)(k0 + row) * N + n) : W;
            cp_async16(&Wbuf[buf][row * WS_STRIDE + col], src, p);
        }
        cp_commit();
    };

    issue_slab(0, 0);

    for (int slab = 0; slab < nslabs; slab++) {
        const int buf = slab & 1;
        if (slab + 1 < nslabs) {
            issue_slab(slab + 1, (slab + 1) & 1);
            asm volatile("cp.async.wait_group 1;\n");
        } else {
            asm volatile("cp.async.wait_group 0;\n");
        }
        __syncthreads();

        const float* As = Abuf[buf];
        const float* Ws = Wbuf[buf];

#pragma unroll
        for (int ks = 0; ks < TBK / 8; ks++) {
            const int kb = ks * 8;
            uint32_t afh[4][4], afl[4][4];
#pragma unroll
            for (int mi = 0; mi < 4; mi++) {
                int r0 = wm * 64 + mi * 16;
                int i00 = (r0 + g    ) * AS_STRIDE + kb + q;
                int i10 = (r0 + g + 8) * AS_STRIDE + kb + q;
                split_tf32(As[i00],     afh[mi][0], afl[mi][0]);
                split_tf32(As[i10],     afh[mi][1], afl[mi][1]);
                split_tf32(As[i00 + 4], afh[mi][2], afl[mi][2]);
                split_tf32(As[i10 + 4], afh[mi][3], afl[mi][3]);
            }
            uint32_t bfh[4][2], bfl[4][2];
#pragma unroll
            for (int ni = 0; ni < 4; ni++) {
                int c0 = wn * 32 + ni * 8;
                int j0 = (kb + q    ) * WS_STRIDE + c0 + g;
                int j1 = (kb + q + 4) * WS_STRIDE + c0 + g;
                split_tf32(Ws[j0], bfh[ni][0], bfl[ni][0]);
                split_tf32(Ws[j1], bfh[ni][1], bfl[ni][1]);
            }
#pragma unroll
            for (int mi = 0; mi < 4; mi++)
#pragma unroll
                for (int ni = 0; ni < 4; ni++) {
                    float* ap = acc[mi][ni];
                    MMA_TF32(ap, afh[mi][0], afh[mi][1], afh[mi][2], afh[mi][3],
                             bfh[ni][0], bfh[ni][1]);                       // hi*hi
                    MMA_TF32(ap, afh[mi][0], afh[mi][1], afh[mi][2], afh[mi][3],
                             bfl[ni][0], bfl[ni][1]);                       // hi*lo
                    MMA_TF32(ap, afl[mi][0], afl[mi][1], afl[mi][2], afl[mi][3],
                             bfh[ni][0], bfh[ni][1]);                       // lo*hi
                }
        }
        __syncthreads();   // all reads of buf done before it is refilled
    }

    // ---- epilogue (N always even at call sites -> pairwise guard ok)
#pragma unroll
    for (int mi = 0; mi < 4; mi++) {
        int r0 = bm + wm * 64 + mi * 16;
#pragma unroll
        for (int ni = 0; ni < 4; ni++) {
            int c0 = bn + wn * 32 + ni * 8 + 2 * q;
            if (c0 >= N) continue;
            float b0 = bias ? bias[c0]     : 0.f;
            float b1 = bias ? bias[c0 + 1] : 0.f;
#pragma unroll
            for (int half = 0; half < 2; half++) {
                int m = r0 + g + half * 8;
                if (m >= M) continue;
                float v0 = acc[mi][ni][half * 2 + 0] + b0;
                float v1 = acc[mi][ni][half * 2 + 1] + b1;
                if (ACT == 1) { v0 = fmaxf(v0, 0.f); v1 = fmaxf(v1, 0.f); }
                float2* dst = (float2*)(C + (size_t)m * N + c0);
                *dst = make_float2(v0, v1);
            }
        }
    }
}

// ---------------------------------------------------------------------------
// Small fp32 SIMT GEMM (kept for the tiny final layer N=2)
// ---------------------------------------------------------------------------
#define BM 128
#define BN 64
#define BK 16

template <int ACT>
__global__ void __launch_bounds__(256)
gemm_kernel(const float* __restrict__ A, const float* __restrict__ W,
            const float* __restrict__ bias, float* __restrict__ C,
            int M, int N, int K)
{
    __shared__ float As[BK][BM + 1];
    __shared__ float Ws[BK][BN];

    const int tid  = threadIdx.x;
    const int bm   = blockIdx.y * BM;
    const int bn   = blockIdx.x * BN;
    const int tx   = tid & 15;
    const int ty   = tid >> 4;
    const int arow = tid >> 2;
    const int acol = (tid & 3) * 4;
    const int wrow = tid >> 4;
    const int wcol = (tid & 15) * 4;

    float acc[8][4];
#pragma unroll
    for (int i = 0; i < 8; i++)
#pragma unroll
        for (int j = 0; j < 4; j++) acc[i][j] = 0.f;

    for (int k0 = 0; k0 < K; k0 += BK) {
#pragma unroll
        for (int half = 0; half < 2; half++) {
            int m = bm + arow + half * 64;
            float4 v = make_float4(0.f, 0.f, 0.f, 0.f);
            if (m < M)
                v = *(const float4*)(A + (size_t)m * K + k0 + acol);
            As[acol + 0][arow + half * 64] = v.x;
            As[acol + 1][arow + half * 64] = v.y;
            As[acol + 2][arow + half * 64] = v.z;
            As[acol + 3][arow + half * 64] = v.w;
        }
        {
            int kk = k0 + wrow;
            int n  = bn + wcol;
#pragma unroll
            for (int j = 0; j < 4; j++)
                Ws[wrow][wcol + j] = (n + j < N) ? W[(size_t)kk * N + n + j] : 0.f;
        }
        __syncthreads();

#pragma unroll
        for (int k = 0; k < BK; k++) {
            float ra[8];
#pragma unroll
            for (int i = 0; i < 8; i++) ra[i] = As[k][ty * 8 + i];
            float rb[4];
#pragma unroll
            for (int j = 0; j < 4; j++) rb[j] = Ws[k][tx * 4 + j];
#pragma unroll
            for (int i = 0; i < 8; i++)
#pragma unroll
                for (int j = 0; j < 4; j++)
                    acc[i][j] = fmaf(ra[i], rb[j], acc[i][j]);
        }
        __syncthreads();
    }

#pragma unroll
    for (int i = 0; i < 8; i++) {
        int m = bm + ty * 8 + i;
        if (m >= M) continue;
#pragma unroll
        for (int j = 0; j < 4; j++) {
            int n = bn + tx * 4 + j;
            if (n >= N) continue;
            float v = acc[i][j];
            if (bias) v += bias[n];
            if (ACT == 1) v = fmaxf(v, 0.f);
            C[(size_t)m * N + n] = v;
        }
    }
}

// ---------------------------------------------------------------------------
// Causal depthwise conv (DCONV=4) + bias + SiLU over the xBC slice of zxbcdt.
// ---------------------------------------------------------------------------
__global__ void conv_silu_kernel(const float* __restrict__ zx,
                                 const float* __restrict__ conv_w,
                                 const float* __restrict__ conv_b,
                                 float* __restrict__ xbc)
{
    int c = blockIdx.x * blockDim.x + threadIdx.x;
    int b = blockIdx.y;
    if (c >= CONV_DIM) return;

    float w0 = conv_w[c * 4 + 0], w1 = conv_w[c * 4 + 1];
    float w2 = conv_w[c * 4 + 2], w3 = conv_w[c * 4 + 3];
    float bb = conv_b[c];

    const float* src = zx + (size_t)b * SEQL * DPROJ + D_INNER + c;
    float v[SEQL];
#pragma unroll
    for (int l = 0; l < SEQL; l++) v[l] = src[(size_t)l * DPROJ];

#pragma unroll
    for (int l = 0; l < SEQL; l++) {
        float s = bb + v[l] * w3;
        if (l >= 1) s += v[l - 1] * w2;
        if (l >= 2) s += v[l - 2] * w1;
        if (l >= 3) s += v[l - 3] * w0;
        s = s / (1.f + expf(-s));   // silu
        xbc[((size_t)b * SEQL + l) * CONV_DIM + c] = s;
    }
}

// ---------------------------------------------------------------------------
// dt = softplus(dt_raw + dt_bias); dA = exp(-exp(A_log) * dt)
// ---------------------------------------------------------------------------
__global__ void dt_kernel(const float* __restrict__ zx,
                          const float* __restrict__ dt_bias,
                          const float* __restrict__ A_log,
                          float* __restrict__ dtb, float* __restrict__ dAb)
{
    int i = blockIdx.x * blockDim.x + threadIdx.x;
    if (i >= ROWS * NHEADS) return;
    int row = i >> 5, h = i & 31;
    float x = zx[(size_t)row * DPROJ + (D_INNER + CONV_DIM) + h] + dt_bias[h];
    float dt = (x > 20.f) ? x : log1pf(expf(x));
    float dA = expf(-expf(A_log[h]) * dt);
    dtb[i] = dt;
    dAb[i] = dA;
}

// ---------------------------------------------------------------------------
// SSM scan: one CTA per (batch, head). State h[64][128] in registers.
// ---------------------------------------------------------------------------
__global__ void __launch_bounds__(256)
scan_kernel(const float* __restrict__ xbc,
            const float* __restrict__ dtb, const float* __restrict__ dAb,
            const float* __restrict__ Dp, float* __restrict__ y)
{
    const int b = blockIdx.x;
    const int h = blockIdx.y;
    const int t = threadIdx.x;
    const int p = t >> 2;
    const int q = t & 3;

    __shared__ float Bsh[DSTATE];
    __shared__ float Csh[DSTATE];
    __shared__ float xsh[HEADDIM];
    __shared__ float sc[2];

    float st[32];
#pragma unroll
    for (int i = 0; i < 32; i++) st[i] = 0.f;
    const float Dh = Dp[h];

    for (int l = 0; l < SEQL; l++) {
        const int row = b * SEQL + l;
        const float* base = xbc + (size_t)row * CONV_DIM;
        if (t < 128) Bsh[t] = base[D_INNER + t];
        else         Csh[t - 128] = base[D_INNER + DSTATE + (t - 128)];
        if (t < HEADDIM) xsh[t] = base[h * HEADDIM + t];
        if (t == 0) { sc[0] = dAb[row * NHEADS + h]; sc[1] = dtb[row * NHEADS + h]; }
        __syncthreads();

        const float xv   = xsh[p];
        const float coef = sc[1] * xv;
        const float dAv  = sc[0];
        float part = 0.f;
#pragma unroll
        for (int i = 0; i < 32; i++) {
            const int s = q + 4 * i;
            st[i] = fmaf(dAv, st[i], coef * Bsh[s]);
            part  = fmaf(st[i], Csh[s], part);
        }
        part += __shfl_down_sync(0xffffffffu, part, 2);
        part += __shfl_down_sync(0xffffffffu, part, 1);
        if (q == 0)
            y[(size_t)row * D_INNER + h * HEADDIM + p] = part + xv * Dh;
        __syncthreads();
    }
}

// ---------------------------------------------------------------------------
// y = y * silu(z); y *= rsqrt(mean(y^2) + 1e-5) * norm_w
// ---------------------------------------------------------------------------
__global__ void __launch_bounds__(256)
gated_rmsnorm_kernel(float* __restrict__ ybuf, const float* __restrict__ zx,
                     const float* __restrict__ norm_w)
{
    const int row = blockIdx.x;
    const int t   = threadIdx.x;
    float* yb       = ybuf + (size_t)row * D_INNER;
    const float* zb = zx   + (size_t)row * DPROJ;

    float v[8];
    float ss = 0.f;
#pragma unroll
    for (int j = 0; j < 8; j++) {
        int d = t + j * 256;
        float z   = zb[d];
        float val = yb[d] * (z / (1.f + expf(-z)));
        v[j] = val;
        ss  = fmaf(val, val, ss);
    }
#pragma unroll
    for (int o = 16; o > 0; o >>= 1)
        ss += __shfl_down_sync(0xffffffffu, ss, o);

    __shared__ float red[8];
    __shared__ float s_scale;
    if ((t & 31) == 0) red[t >> 5] = ss;
    __syncthreads();
    if (t == 0) {
        float s = 0.f;
        for (int i = 0; i < 8; i++) s += red[i];
        s_scale = rsqrtf(s / (float)D_INNER + 1e-5f);
    }
    __syncthreads();
    const float scale = s_scale;
#pragma unroll
    for (int j = 0; j < 8; j++) {
        int d = t + j * 256;
        yb[d] = v[j] * scale * norm_w[d];
    }
}

// ---------------------------------------------------------------------------
// Host-side orchestration
// ---------------------------------------------------------------------------
struct MambaW {
    const float *in_proj, *conv_w, *conv_b, *dt_bias, *A_log, *D, *norm_w, *out_proj;
};

static inline dim3 mma_grid(int M, int N)
{
    return dim3((unsigned)((N + TBN - 1) / TBN), (unsigned)((M + TBM - 1) / TBM));
}

static void run_mamba(const MambaW& p,
                      float* h_ptr, float* zx, float* xbc,
                      float* dtb, float* dAb, float* ybuf)
{
    // zxbcdt = h @ in_proj : (2048,1024)@(1024,4384)
    mma_gemm_kernel<0><<<mma_grid(ROWS, DPROJ), 256, GEMM_SMEM_BYTES>>>(
        h_ptr, p.in_proj, nullptr, zx, ROWS, DPROJ, HIDD);
    conv_silu_kernel<<<dim3(CONV_DIM / 256, BATCH), 256>>>(zx, p.conv_w, p.conv_b, xbc);
    dt_kernel<<<(ROWS * NHEADS) / 256, 256>>>(zx, p.dt_bias, p.A_log, dtb, dAb);
    scan_kernel<<<dim3(BATCH, NHEADS), 256>>>(xbc, dtb, dAb, p.D, ybuf);
    gated_rmsnorm_kernel<<<ROWS, 256>>>(ybuf, zx, p.norm_w);
    // h = y @ out_proj : (2048,2048)@(2048,1024)
    mma_gemm_kernel<0><<<mma_grid(ROWS, HIDD), 256, GEMM_SMEM_BYTES>>>(
        ybuf, p.out_proj, nullptr, h_ptr, ROWS, HIDD, D_INNER);
}

extern "C" void kernel_launch(void* const* d_in, const int* in_sizes, int n_in,
                              void* d_out, int out_size)
{
    const float* x      = (const float*)d_in[0];
    const float* w_in1  = (const float*)d_in[1];
    const float* b_in1  = (const float*)d_in[2];
    const float* w_in2  = (const float*)d_in[3];
    const float* b_in2  = (const float*)d_in[4];
    MambaW m1 = { (const float*)d_in[5],  (const float*)d_in[6],  (const float*)d_in[7],
                  (const float*)d_in[8],  (const float*)d_in[9],  (const float*)d_in[10],
                  (const float*)d_in[11], (const float*)d_in[12] };
    MambaW m2 = { (const float*)d_in[13], (const float*)d_in[14], (const float*)d_in[15],
                  (const float*)d_in[16], (const float*)d_in[17], (const float*)d_in[18],
                  (const float*)d_in[19], (const float*)d_in[20] };
    const float* w_out1 = (const float*)d_in[21];
    const float* b_out1 = (const float*)d_in[22];
    const float* w_out2 = (const float*)d_in[23];
    const float* b_out2 = (const float*)d_in[24];
    float* out = (float*)d_out;

    // raise dynamic smem limit for the MMA GEMM (idempotent, capture-safe)
    cudaFuncSetAttribute(mma_gemm_kernel<0>,
                         cudaFuncAttributeMaxDynamicSharedMemorySize, GEMM_SMEM_BYTES);
    cudaFuncSetAttribute(mma_gemm_kernel<1>,
                         cudaFuncAttributeMaxDynamicSharedMemorySize, GEMM_SMEM_BYTES);

    float *a, *h, *zx, *xbc, *dtb, *dAb, *ybuf;
    cudaGetSymbolAddress((void**)&a,    g_a);
    cudaGetSymbolAddress((void**)&h,    g_h);
    cudaGetSymbolAddress((void**)&zx,   g_zx);
    cudaGetSymbolAddress((void**)&xbc,  g_xbc);
    cudaGetSymbolAddress((void**)&dtb,  g_dt);
    cudaGetSymbolAddress((void**)&dAb,  g_dA);
    cudaGetSymbolAddress((void**)&ybuf, g_y);

    // MLP in: a = relu(x @ w_in1 + b_in1); h = a @ w_in2 + b_in2
    mma_gemm_kernel<1><<<mma_grid(BATCH, 8192), 256, GEMM_SMEM_BYTES>>>(
        x, w_in1, b_in1, a, BATCH, 8192, 1024);
    mma_gemm_kernel<0><<<mma_grid(BATCH, 8192), 256, GEMM_SMEM_BYTES>>>(
        a, w_in2, b_in2, h, BATCH, 8192, 8192);

    // 2x Mamba2 layers (h viewed as (2048, 1024) == (256, 8, 1024))
    run_mamba(m1, h, zx, xbc, dtb, dAb, ybuf);
    run_mamba(m2, h, zx, xbc, dtb, dAb, ybuf);

    // MLP out: a = relu(h(256,8192) @ w_out1 + b_out1); out = a @ w_out2 + b_out2
    mma_gemm_kernel<1><<<mma_grid(BATCH, 1024), 256, GEMM_SMEM_BYTES>>>(
        h, w_out1, b_out1, a, BATCH, 1024, 8192);
    gemm_kernel<0><<<dim3(1, (BATCH + BM - 1) / BM), 256>>>(a, w_out2, b_out2, out,
                                                            BATCH, 2, 1024);
}

// round 5
// speedup vs baseline: 2.0251x; 1.5743x over previous
#include <cuda_runtime.h>
#include <cuda_bf16.h>
#include <cstdint>

// ---------------------------------------------------------------------------
// Problem dimensions (fixed by the reference)
// ---------------------------------------------------------------------------
#define BATCH    256
#define SEQL     8
#define HIDD     1024            // HID
#define D_INNER  2048
#define DSTATE   128
#define NHEADS   32
#define HEADDIM  64
#define CONV_DIM 2304            // D_INNER + 2*DSTATE
#define DPROJ    4384            // 2*D_INNER + 2*DSTATE + NHEADS
#define ROWS     (BATCH * SEQL)  // 2048

// ---------------------------------------------------------------------------
// Scratch (static device buffers; no allocation allowed in kernel_launch)
// ---------------------------------------------------------------------------
__device__ float g_a  [BATCH * 8192];     // MLP intermediate (256 x 8192)
__device__ float g_h  [ROWS  * HIDD];     // sequence activations (2048 x 1024)
__device__ float g_zx [ROWS  * DPROJ];    // zxbcdt (2048 x 4384)
__device__ float g_xbc[ROWS  * CONV_DIM]; // conv+silu output (2048 x 2304)
__device__ float g_dt [ROWS  * NHEADS];
__device__ float g_dA [ROWS  * NHEADS];
__device__ float g_y  [ROWS  * D_INNER];  // SSM output / gated-normed (2048 x 2048)

// Split-bf16 transposed weights (N,K layout), hi and lo parts.
// Offsets (elements):
//   win1T      @ 0          (8192*1024  = 8,388,608)
//   win2T      @ 8388608    (8192*8192  = 67,108,864)
//   m1_inprojT @ 75497472   (4384*1024  = 4,489,216)
//   m2_inprojT @ 79986688   (4384*1024  = 4,489,216)
//   m1_outprojT@ 84475904   (1024*2048  = 2,097,152)
//   m2_outprojT@ 86573056   (1024*2048  = 2,097,152)
//   wout1T     @ 88670208   (1024*8192  = 8,388,608)
// total 97,058,816
#define WT_TOTAL     97058816
#define OFF_WIN1     0
#define OFF_WIN2     8388608
#define OFF_M1_INP   75497472
#define OFF_M2_INP   79986688
#define OFF_M1_OUTP  84475904
#define OFF_M2_OUTP  86573056
#define OFF_WOUT1    88670208
__device__ __nv_bfloat16 g_whi[WT_TOTAL];
__device__ __nv_bfloat16 g_wlo[WT_TOTAL];

// ---------------------------------------------------------------------------
// Weight preprocessing: W (K,N) fp32 -> WT hi/lo (N,K) bf16.
// 32x32 smem-tiled transpose. All K,N here are multiples of 32 (no guards).
// hi = bf16_rn(x), lo = bf16_rn(x - hi).
// ---------------------------------------------------------------------------
__global__ void __launch_bounds__(256)
transpose_split_kernel(const float* __restrict__ W,
                       __nv_bfloat16* __restrict__ Thi,
                       __nv_bfloat16* __restrict__ Tlo,
                       int K, int N)
{
    __shared__ float t[32][33];
    const int tx = threadIdx.x & 31;
    const int ty = threadIdx.x >> 5;      // 0..7
    const int nbase = blockIdx.x * 32;
    const int kbase = blockIdx.y * 32;

#pragma unroll
    for (int r = 0; r < 4; r++) {
        int k = kbase + ty + r * 8;
        t[ty + r * 8][tx] = W[(size_t)k * N + nbase + tx];
    }
    __syncthreads();
#pragma unroll
    for (int r = 0; r < 4; r++) {
        int n = nbase + ty + r * 8;
        int k = kbase + tx;
        float v = t[tx][ty + r * 8];
        __nv_bfloat16 hi = __float2bfloat16(v);
        float lo = v - __bfloat162float(hi);
        Thi[(size_t)n * K + k] = hi;
        Tlo[(size_t)n * K + k] = __float2bfloat16(lo);
    }
}

// ---------------------------------------------------------------------------
// 3xBF16 split GEMM: C = act(A @ W + bias), ~fp32-accurate.
// A: (M,K) fp32 row-major (split to bf16 hi/lo during smem fill).
// WThi/WTlo: (N,K) bf16 row-major (preprocessed; cp.async'ed raw).
// D += Ahi*Whi + Ahi*Wlo + Alo*Whi via mma.sync.m16n8k16 bf16, fp32 accum.
// CTA tile 128x128, BK=32, 256 threads = 8 warps (2x4), warp tile 64x32.
// Requires: M % 128 == 0, K % 32 == 0 (true at all call sites). N arbitrary
// mult of 8 (edge handled by cp.async zfill predicate + epilogue guard).
// smem rows padded to 40 halves: fragment-LDS bank map {20g+q} bijective.
// ---------------------------------------------------------------------------
#define TBM 128
#define TBN 128
#define TBK 32
#define RSTR 40                           // halves per smem row
#define TILE_H (128 * RSTR)               // 5120 halves per tile array
#define STAGE_H (4 * TILE_H)              // Ah, Al, Wh, Wl
#define GEMM_SMEM_BYTES (2 * STAGE_H * 2) // 2 stages * halves*2B = 81920

__device__ __forceinline__ void cp_async16(__nv_bfloat16* smem_dst,
                                           const __nv_bfloat16* gsrc, bool pred) {
    uint32_t saddr = (uint32_t)__cvta_generic_to_shared(smem_dst);
    int sz = pred ? 16 : 0;
    asm volatile("cp.async.cg.shared.global [%0], [%1], 16, %2;\n"
                 :: "r"(saddr), "l"(gsrc), "r"(sz));
}

#define MMA_BF16(ACCP, A0, A1, A2, A3, B0, B1)                              \
    asm volatile(                                                           \
        "mma.sync.aligned.m16n8k16.row.col.f32.bf16.bf16.f32 "              \
        "{%0,%1,%2,%3}, {%4,%5,%6,%7}, {%8,%9}, {%0,%1,%2,%3};\n"           \
        : "+f"((ACCP)[0]), "+f"((ACCP)[1]), "+f"((ACCP)[2]), "+f"((ACCP)[3])\
        : "r"(A0), "r"(A1), "r"(A2), "r"(A3), "r"(B0), "r"(B1))

template <int ACT>
__global__ void __launch_bounds__(256)
mma_gemm_kernel(const float* __restrict__ A,
                const __nv_bfloat16* __restrict__ Whi,
                const __nv_bfloat16* __restrict__ Wlo,
                const float* __restrict__ bias, float* __restrict__ C,
                int M, int N, int K)
{
    extern __shared__ __nv_bfloat16 smem_h[];

    const int tid  = threadIdx.x;
    const int lane = tid & 31;
    const int warp = tid >> 5;
    const int wm   = warp >> 2;        // 0..1  (M dir)
    const int wn   = warp & 3;         // 0..3  (N dir)
    const int bm   = blockIdx.y * TBM;
    const int bn   = blockIdx.x * TBN;

    const int g = lane >> 2;           // 0..7
    const int q = lane & 3;            // 0..3

    float acc[4][4][4];
#pragma unroll
    for (int mi = 0; mi < 4; mi++)
#pragma unroll
        for (int ni = 0; ni < 4; ni++)
#pragma unroll
            for (int f = 0; f < 4; f++) acc[mi][ni][f] = 0.f;

    const int nslabs = K / TBK;

    // A fill indices: 1024 float4 chunks, 4 per thread
    const int a_row = tid >> 3;          // base row (adds 32*i)
    const int a_col = (tid & 7) * 4;     // k offset (floats)
    // W fill indices: 512 16B chunks per array, 2 per thread
    const int w_row = tid >> 2;          // base row (adds 64*i)
    const int w_off = (tid & 3) * 8;     // k offset (halves)

    float4 areg[4];

    auto ldg_A = [&](int slab) {
#pragma unroll
        for (int i = 0; i < 4; i++) {
            int row = a_row + i * 32;
            areg[i] = *(const float4*)(A + (size_t)(bm + row) * K
                                       + slab * TBK + a_col);
        }
    };

    auto issue_W = [&](int slab, int stg) {
        __nv_bfloat16* Wh = smem_h + stg * STAGE_H + 2 * TILE_H;
        __nv_bfloat16* Wl = Wh + TILE_H;
        const int k0 = slab * TBK;
#pragma unroll
        for (int i = 0; i < 2; i++) {
            int row = w_row + i * 64;
            int n   = bn + row;
            bool p  = (n < N);
            size_t goff = p ? ((size_t)n * K + k0 + w_off) : 0;
            cp_async16(Wh + row * RSTR + w_off, Whi + goff, p);
            cp_async16(Wl + row * RSTR + w_off, Wlo + goff, p);
        }
        asm volatile("cp.async.commit_group;\n");
    };

    auto sts_A = [&](int stg) {
        __nv_bfloat16* Ah = smem_h + stg * STAGE_H;
        __nv_bfloat16* Al = Ah + TILE_H;
#pragma unroll
        for (int i = 0; i < 4; i++) {
            int row = a_row + i * 32;
            float4 v = areg[i];
            __nv_bfloat16 h0 = __float2bfloat16(v.x);
            __nv_bfloat16 h1 = __float2bfloat16(v.y);
            __nv_bfloat16 h2 = __float2bfloat16(v.z);
            __nv_bfloat16 h3 = __float2bfloat16(v.w);
            __nv_bfloat162* dh = (__nv_bfloat162*)(Ah + row * RSTR + a_col);
            dh[0] = __halves2bfloat162(h0, h1);
            dh[1] = __halves2bfloat162(h2, h3);
            __nv_bfloat162* dl = (__nv_bfloat162*)(Al + row * RSTR + a_col);
            dl[0] = __halves2bfloat162(
                __float2bfloat16(v.x - __bfloat162float(h0)),
                __float2bfloat16(v.y - __bfloat162float(h1)));
            dl[1] = __halves2bfloat162(
                __float2bfloat16(v.z - __bfloat162float(h2)),
                __float2bfloat16(v.w - __bfloat162float(h3)));
        }
    };

    // prologue
    issue_W(0, 0);
    ldg_A(0);

    for (int slab = 0; slab < nslabs; slab++) {
        const int stg = slab & 1;
        sts_A(stg);
        if (slab + 1 < nslabs) {
            issue_W(slab + 1, stg ^ 1);
            ldg_A(slab + 1);
            asm volatile("cp.async.wait_group 1;\n");
        } else {
            asm volatile("cp.async.wait_group 0;\n");
        }
        __syncthreads();

        const uint32_t* AhU = (const uint32_t*)(smem_h + stg * STAGE_H);
        const uint32_t* AlU = AhU + TILE_H / 2;
        const uint32_t* WhU = AlU + TILE_H / 2;
        const uint32_t* WlU = WhU + TILE_H / 2;
        const int SW = RSTR / 2;           // 20 words per row

#pragma unroll
        for (int ks = 0; ks < 2; ks++) {
            const int kw = ks * 8;         // word offset within row
            uint32_t afh[4][4], afl[4][4];
#pragma unroll
            for (int mi = 0; mi < 4; mi++) {
                int r0 = wm * 64 + mi * 16;
                int i00 = (r0 + g    ) * SW + kw + q;
                int i10 = (r0 + g + 8) * SW + kw + q;
                afh[mi][0] = AhU[i00];     afh[mi][1] = AhU[i10];
                afh[mi][2] = AhU[i00 + 4]; afh[mi][3] = AhU[i10 + 4];
                afl[mi][0] = AlU[i00];     afl[mi][1] = AlU[i10];
                afl[mi][2] = AlU[i00 + 4]; afl[mi][3] = AlU[i10 + 4];
            }
            uint32_t bfh[4][2], bfl[4][2];
#pragma unroll
            for (int ni = 0; ni < 4; ni++) {
                int n0 = wn * 32 + ni * 8;
                int j0 = (n0 + g) * SW + kw + q;
                bfh[ni][0] = WhU[j0]; bfh[ni][1] = WhU[j0 + 4];
                bfl[ni][0] = WlU[j0]; bfl[ni][1] = WlU[j0 + 4];
            }
#pragma unroll
            for (int mi = 0; mi < 4; mi++)
#pragma unroll
                for (int ni = 0; ni < 4; ni++) {
                    float* ap = acc[mi][ni];
                    MMA_BF16(ap, afh[mi][0], afh[mi][1], afh[mi][2], afh[mi][3],
                             bfh[ni][0], bfh[ni][1]);                 // hi*hi
                    MMA_BF16(ap, afh[mi][0], afh[mi][1], afh[mi][2], afh[mi][3],
                             bfl[ni][0], bfl[ni][1]);                 // hi*lo
                    MMA_BF16(ap, afl[mi][0], afl[mi][1], afl[mi][2], afl[mi][3],
                             bfh[ni][0], bfh[ni][1]);                 // lo*hi
                }
        }
        __syncthreads();
    }

    // ---- epilogue (N always even at call sites -> pairwise guard ok)
#pragma unroll
    for (int mi = 0; mi < 4; mi++) {
        int r0 = bm + wm * 64 + mi * 16;
#pragma unroll
        for (int ni = 0; ni < 4; ni++) {
            int c0 = bn + wn * 32 + ni * 8 + 2 * q;
            if (c0 >= N) continue;
            float b0 = bias ? bias[c0]     : 0.f;
            float b1 = bias ? bias[c0 + 1] : 0.f;
#pragma unroll
            for (int half = 0; half < 2; half++) {
                int m = r0 + g + half * 8;
                float v0 = acc[mi][ni][half * 2 + 0] + b0;
                float v1 = acc[mi][ni][half * 2 + 1] + b1;
                if (ACT == 1) { v0 = fmaxf(v0, 0.f); v1 = fmaxf(v1, 0.f); }
                float2* dst = (float2*)(C + (size_t)m * N + c0);
                *dst = make_float2(v0, v1);
            }
        }
    }
}

// ---------------------------------------------------------------------------
// Small fp32 SIMT GEMM (kept for the tiny final layer N=2)
// ---------------------------------------------------------------------------
#define BM 128
#define BN 64
#define BK 16

template <int ACT>
__global__ void __launch_bounds__(256)
gemm_kernel(const float* __restrict__ A, const float* __restrict__ W,
            const float* __restrict__ bias, float* __restrict__ C,
            int M, int N, int K)
{
    __shared__ float As[BK][BM + 1];
    __shared__ float Ws[BK][BN];

    const int tid  = threadIdx.x;
    const int bm   = blockIdx.y * BM;
    const int bn   = blockIdx.x * BN;
    const int tx   = tid & 15;
    const int ty   = tid >> 4;
    const int arow = tid >> 2;
    const int acol = (tid & 3) * 4;
    const int wrow = tid >> 4;
    const int wcol = (tid & 15) * 4;

    float acc[8][4];
#pragma unroll
    for (int i = 0; i < 8; i++)
#pragma unroll
        for (int j = 0; j < 4; j++) acc[i][j] = 0.f;

    for (int k0 = 0; k0 < K; k0 += BK) {
#pragma unroll
        for (int half = 0; half < 2; half++) {
            int m = bm + arow + half * 64;
            float4 v = make_float4(0.f, 0.f, 0.f, 0.f);
            if (m < M)
                v = *(const float4*)(A + (size_t)m * K + k0 + acol);
            As[acol + 0][arow + half * 64] = v.x;
            As[acol + 1][arow + half * 64] = v.y;
            As[acol + 2][arow + half * 64] = v.z;
            As[acol + 3][arow + half * 64] = v.w;
        }
        {
            int kk = k0 + wrow;
            int n  = bn + wcol;
#pragma unroll
            for (int j = 0; j < 4; j++)
                Ws[wrow][wcol + j] = (n + j < N) ? W[(size_t)kk * N + n + j] : 0.f;
        }
        __syncthreads();

#pragma unroll
        for (int k = 0; k < BK; k++) {
            float ra[8];
#pragma unroll
            for (int i = 0; i < 8; i++) ra[i] = As[k][ty * 8 + i];
            float rb[4];
#pragma unroll
            for (int j = 0; j < 4; j++) rb[j] = Ws[k][tx * 4 + j];
#pragma unroll
            for (int i = 0; i < 8; i++)
#pragma unroll
                for (int j = 0; j < 4; j++)
                    acc[i][j] = fmaf(ra[i], rb[j], acc[i][j]);
        }
        __syncthreads();
    }

#pragma unroll
    for (int i = 0; i < 8; i++) {
        int m = bm + ty * 8 + i;
        if (m >= M) continue;
#pragma unroll
        for (int j = 0; j < 4; j++) {
            int n = bn + tx * 4 + j;
            if (n >= N) continue;
            float v = acc[i][j];
            if (bias) v += bias[n];
            if (ACT == 1) v = fmaxf(v, 0.f);
            C[(size_t)m * N + n] = v;
        }
    }
}

// ---------------------------------------------------------------------------
// Causal depthwise conv (DCONV=4) + bias + SiLU over the xBC slice of zxbcdt.
// ---------------------------------------------------------------------------
__global__ void conv_silu_kernel(const float* __restrict__ zx,
                                 const float* __restrict__ conv_w,
                                 const float* __restrict__ conv_b,
                                 float* __restrict__ xbc)
{
    int c = blockIdx.x * blockDim.x + threadIdx.x;
    int b = blockIdx.y;
    if (c >= CONV_DIM) return;

    float w0 = conv_w[c * 4 + 0], w1 = conv_w[c * 4 + 1];
    float w2 = conv_w[c * 4 + 2], w3 = conv_w[c * 4 + 3];
    float bb = conv_b[c];

    const float* src = zx + (size_t)b * SEQL * DPROJ + D_INNER + c;
    float v[SEQL];
#pragma unroll
    for (int l = 0; l < SEQL; l++) v[l] = src[(size_t)l * DPROJ];

#pragma unroll
    for (int l = 0; l < SEQL; l++) {
        float s = bb + v[l] * w3;
        if (l >= 1) s += v[l - 1] * w2;
        if (l >= 2) s += v[l - 2] * w1;
        if (l >= 3) s += v[l - 3] * w0;
        s = s / (1.f + expf(-s));   // silu
        xbc[((size_t)b * SEQL + l) * CONV_DIM + c] = s;
    }
}

// ---------------------------------------------------------------------------
// dt = softplus(dt_raw + dt_bias); dA = exp(-exp(A_log) * dt)
// ---------------------------------------------------------------------------
__global__ void dt_kernel(const float* __restrict__ zx,
                          const float* __restrict__ dt_bias,
                          const float* __restrict__ A_log,
                          float* __restrict__ dtb, float* __restrict__ dAb)
{
    int i = blockIdx.x * blockDim.x + threadIdx.x;
    if (i >= ROWS * NHEADS) return;
    int row = i >> 5, h = i & 31;
    float x = zx[(size_t)row * DPROJ + (D_INNER + CONV_DIM) + h] + dt_bias[h];
    float dt = (x > 20.f) ? x : log1pf(expf(x));
    float dA = expf(-expf(A_log[h]) * dt);
    dtb[i] = dt;
    dAb[i] = dA;
}

// ---------------------------------------------------------------------------
// SSM scan: one CTA per (batch, head). State h[64][128] in registers.
// ---------------------------------------------------------------------------
__global__ void __launch_bounds__(256)
scan_kernel(const float* __restrict__ xbc,
            const float* __restrict__ dtb, const float* __restrict__ dAb,
            const float* __restrict__ Dp, float* __restrict__ y)
{
    const int b = blockIdx.x;
    const int h = blockIdx.y;
    const int t = threadIdx.x;
    const int p = t >> 2;
    const int q = t & 3;

    __shared__ float Bsh[DSTATE];
    __shared__ float Csh[DSTATE];
    __shared__ float xsh[HEADDIM];
    __shared__ float sc[2];

    float st[32];
#pragma unroll
    for (int i = 0; i < 32; i++) st[i] = 0.f;
    const float Dh = Dp[h];

    for (int l = 0; l < SEQL; l++) {
        const int row = b * SEQL + l;
        const float* base = xbc + (size_t)row * CONV_DIM;
        if (t < 128) Bsh[t] = base[D_INNER + t];
        else         Csh[t - 128] = base[D_INNER + DSTATE + (t - 128)];
        if (t < HEADDIM) xsh[t] = base[h * HEADDIM + t];
        if (t == 0) { sc[0] = dAb[row * NHEADS + h]; sc[1] = dtb[row * NHEADS + h]; }
        __syncthreads();

        const float xv   = xsh[p];
        const float coef = sc[1] * xv;
        const float dAv  = sc[0];
        float part = 0.f;
#pragma unroll
        for (int i = 0; i < 32; i++) {
            const int s = q + 4 * i;
            st[i] = fmaf(dAv, st[i], coef * Bsh[s]);
            part  = fmaf(st[i], Csh[s], part);
        }
        part += __shfl_down_sync(0xffffffffu, part, 2);
        part += __shfl_down_sync(0xffffffffu, part, 1);
        if (q == 0)
            y[(size_t)row * D_INNER + h * HEADDIM + p] = part + xv * Dh;
        __syncthreads();
    }
}

// ---------------------------------------------------------------------------
// y = y * silu(z); y *= rsqrt(mean(y^2) + 1e-5) * norm_w
// ---------------------------------------------------------------------------
__global__ void __launch_bounds__(256)
gated_rmsnorm_kernel(float* __restrict__ ybuf, const float* __restrict__ zx,
                     const float* __restrict__ norm_w)
{
    const int row = blockIdx.x;
    const int t   = threadIdx.x;
    float* yb       = ybuf + (size_t)row * D_INNER;
    const float* zb = zx   + (size_t)row * DPROJ;

    float v[8];
    float ss = 0.f;
#pragma unroll
    for (int j = 0; j < 8; j++) {
        int d = t + j * 256;
        float z   = zb[d];
        float val = yb[d] * (z / (1.f + expf(-z)));
        v[j] = val;
        ss  = fmaf(val, val, ss);
    }
#pragma unroll
    for (int o = 16; o > 0; o >>= 1)
        ss += __shfl_down_sync(0xffffffffu, ss, o);

    __shared__ float red[8];
    __shared__ float s_scale;
    if ((t & 31) == 0) red[t >> 5] = ss;
    __syncthreads();
    if (t == 0) {
        float s = 0.f;
        for (int i = 0; i < 8; i++) s += red[i];
        s_scale = rsqrtf(s / (float)D_INNER + 1e-5f);
    }
    __syncthreads();
    const float scale = s_scale;
#pragma unroll
    for (int j = 0; j < 8; j++) {
        int d = t + j * 256;
        yb[d] = v[j] * scale * norm_w[d];
    }
}

// ---------------------------------------------------------------------------
// Host-side orchestration
// ---------------------------------------------------------------------------
struct MambaW {
    const float *in_proj, *conv_w, *conv_b, *dt_bias, *A_log, *D, *norm_w, *out_proj;
};

static inline dim3 mma_grid(int M, int N)
{
    return dim3((unsigned)((N + TBN - 1) / TBN), (unsigned)((M + TBM - 1) / TBM));
}

extern "C" void kernel_launch(void* const* d_in, const int* in_sizes, int n_in,
                              void* d_out, int out_size)
{
    const float* x      = (const float*)d_in[0];
    const float* w_in1  = (const float*)d_in[1];
    const float* b_in1  = (const float*)d_in[2];
    const float* w_in2  = (const float*)d_in[3];
    const float* b_in2  = (const float*)d_in[4];
    MambaW m1 = { (const float*)d_in[5],  (const float*)d_in[6],  (const float*)d_in[7],
                  (const float*)d_in[8],  (const float*)d_in[9],  (const float*)d_in[10],
                  (const float*)d_in[11], (const float*)d_in[12] };
    MambaW m2 = { (const float*)d_in[13], (const float*)d_in[14], (const float*)d_in[15],
                  (const float*)d_in[16], (const float*)d_in[17], (const float*)d_in[18],
                  (const float*)d_in[19], (const float*)d_in[20] };
    const float* w_out1 = (const float*)d_in[21];
    const float* b_out1 = (const float*)d_in[22];
    const float* w_out2 = (const float*)d_in[23];
    const float* b_out2 = (const float*)d_in[24];
    float* out = (float*)d_out;

    cudaFuncSetAttribute(mma_gemm_kernel<0>,
                         cudaFuncAttributeMaxDynamicSharedMemorySize, GEMM_SMEM_BYTES);
    cudaFuncSetAttribute(mma_gemm_kernel<1>,
                         cudaFuncAttributeMaxDynamicSharedMemorySize, GEMM_SMEM_BYTES);

    float *a, *h, *zx, *xbc, *dtb, *dAb, *ybuf;
    __nv_bfloat16 *whi, *wlo;
    cudaGetSymbolAddress((void**)&a,    g_a);
    cudaGetSymbolAddress((void**)&h,    g_h);
    cudaGetSymbolAddress((void**)&zx,   g_zx);
    cudaGetSymbolAddress((void**)&xbc,  g_xbc);
    cudaGetSymbolAddress((void**)&dtb,  g_dt);
    cudaGetSymbolAddress((void**)&dAb,  g_dA);
    cudaGetSymbolAddress((void**)&ybuf, g_y);
    cudaGetSymbolAddress((void**)&whi,  g_whi);
    cudaGetSymbolAddress((void**)&wlo,  g_wlo);

    // ---- weight preprocessing: fp32 (K,N) -> split-bf16 (N,K)
    auto tsp = [&](const float* W, size_t off, int K, int N) {
        transpose_split_kernel<<<dim3(N / 32, K / 32), 256>>>(
            W, whi + off, wlo + off, K, N);
    };
    tsp(w_in1,       OFF_WIN1,    1024, 8192);
    tsp(w_in2,       OFF_WIN2,    8192, 8192);
    tsp(m1.in_proj,  OFF_M1_INP,  1024, DPROJ);
    tsp(m2.in_proj,  OFF_M2_INP,  1024, DPROJ);
    tsp(m1.out_proj, OFF_M1_OUTP, 2048, 1024);
    tsp(m2.out_proj, OFF_M2_OUTP, 2048, 1024);
    tsp(w_out1,      OFF_WOUT1,   8192, 1024);

    // ---- MLP in: a = relu(x @ w_in1 + b_in1); h = a @ w_in2 + b_in2
    mma_gemm_kernel<1><<<mma_grid(BATCH, 8192), 256, GEMM_SMEM_BYTES>>>(
        x, whi + OFF_WIN1, wlo + OFF_WIN1, b_in1, a, BATCH, 8192, 1024);
    mma_gemm_kernel<0><<<mma_grid(BATCH, 8192), 256, GEMM_SMEM_BYTES>>>(
        a, whi + OFF_WIN2, wlo + OFF_WIN2, b_in2, h, BATCH, 8192, 8192);

    // ---- 2x Mamba2 layers (h viewed as (2048, 1024) == (256, 8, 1024))
    const MambaW* layers[2] = { &m1, &m2 };
    const size_t inp_off[2]  = { OFF_M1_INP,  OFF_M2_INP };
    const size_t outp_off[2] = { OFF_M1_OUTP, OFF_M2_OUTP };
    for (int li = 0; li < 2; li++) {
        const MambaW& p = *layers[li];
        mma_gemm_kernel<0><<<mma_grid(ROWS, DPROJ), 256, GEMM_SMEM_BYTES>>>(
            h, whi + inp_off[li], wlo + inp_off[li], nullptr, zx,
            ROWS, DPROJ, HIDD);
        conv_silu_kernel<<<dim3(CONV_DIM / 256, BATCH), 256>>>(zx, p.conv_w,
                                                               p.conv_b, xbc);
        dt_kernel<<<(ROWS * NHEADS) / 256, 256>>>(zx, p.dt_bias, p.A_log, dtb, dAb);
        scan_kernel<<<dim3(BATCH, NHEADS), 256>>>(xbc, dtb, dAb, p.D, ybuf);
        gated_rmsnorm_kernel<<<ROWS, 256>>>(ybuf, zx, p.norm_w);
        mma_gemm_kernel<0><<<mma_grid(ROWS, HIDD), 256, GEMM_SMEM_BYTES>>>(
            ybuf, whi + outp_off[li], wlo + outp_off[li], nullptr, h,
            ROWS, HIDD, D_INNER);
    }

    // ---- MLP out: a = relu(h @ w_out1 + b_out1); out = a @ w_out2 + b_out2
    mma_gemm_kernel<1><<<mma_grid(BATCH, 1024), 256, GEMM_SMEM_BYTES>>>(
        h, whi + OFF_WOUT1, wlo + OFF_WOUT1, b_out1, a, BATCH, 1024, 8192);
    gemm_kernel<0><<<dim3(1, (BATCH + BM - 1) / BM), 256>>>(a, w_out2, b_out2, out,
                                                            BATCH, 2, 1024);
}

// round 7
// speedup vs baseline: 2.6293x; 1.2983x over previous
#include <cuda_runtime.h>
#include <cuda_bf16.h>
#include <cstdint>

// ---------------------------------------------------------------------------
// Problem dimensions (fixed by the reference)
// ---------------------------------------------------------------------------
#define BATCH    256
#define SEQL     8
#define HIDD     1024            // HID
#define D_INNER  2048
#define DSTATE   128
#define NHEADS   32
#define HEADDIM  64
#define CONV_DIM 2304            // D_INNER + 2*DSTATE
#define DPROJ    4384            // 2*D_INNER + 2*DSTATE + NHEADS
#define ROWS     (BATCH * SEQL)  // 2048

// ---------------------------------------------------------------------------
// Scratch (static device buffers; no allocation allowed in kernel_launch)
// ---------------------------------------------------------------------------
__device__ float g_a  [BATCH * 8192];     // MLP intermediate (256 x 8192)
__device__ float g_h  [ROWS  * HIDD];     // sequence activations (2048 x 1024)
__device__ float g_zx [ROWS  * DPROJ];    // zxbcdt (2048 x 4384)
__device__ float g_xbc[ROWS  * CONV_DIM]; // conv+silu output (2048 x 2304)
__device__ float g_dt [ROWS  * NHEADS];
__device__ float g_dA [ROWS  * NHEADS];
__device__ float g_y  [ROWS  * D_INNER];  // SSM output / gated-normed (2048 x 2048)

// Split-bf16 tiled activations (A operand), max 2048*2048 elements
#define AMAX 4194304
__device__ __nv_bfloat16 g_ahi[AMAX];
__device__ __nv_bfloat16 g_alo[AMAX];

// Split-bf16 tiled weights (tiles of 128 n-rows x 64 k-halves, SW128-swizzled,
// laid out so one (nb,kc) tile is 16KB contiguous). N padded to mult of 128.
#define OFF_WIN1     0ULL
#define OFF_WIN2     8388608ULL      // win1: 8192*1024
#define OFF_M1_INP   75497472ULL     // win2: 8192*8192
#define OFF_M2_INP   80084992ULL     // inproj: 4480*1024
#define OFF_M1_OUTP  84672512ULL
#define OFF_M2_OUTP  86769664ULL     // outproj: 1024*2048
#define OFF_WOUT1    88866816ULL
#define WT_TOTAL     97255424ULL     // + wout1: 1024*8192
__device__ __nv_bfloat16 g_whi[WT_TOTAL];
__device__ __nv_bfloat16 g_wlo[WT_TOTAL];

// ---------------------------------------------------------------------------
// PTX helpers
// ---------------------------------------------------------------------------
__device__ __forceinline__ uint32_t smem_u32(const void* p) {
    uint32_t a;
    asm("{ .reg .u64 t; cvta.to.shared.u64 t, %1; cvt.u32.u64 %0, t; }"
        : "=r"(a) : "l"(p));
    return a;
}

#define MBARRIER_INIT(addr, count) \
    asm volatile("mbarrier.init.shared.b64 [%0], %1;" \
                 :: "r"((uint32_t)(addr)), "r"((uint32_t)(count)) : "memory")
#define MBARRIER_INVAL(addr) \
    asm volatile("mbarrier.inval.shared.b64 [%0];" \
                 :: "r"((uint32_t)(addr)) : "memory")
#define MBARRIER_EXPECT_TX(addr, bytes) \
    asm volatile("mbarrier.arrive.expect_tx.shared.b64 _, [%0], %1;" \
                 :: "r"((uint32_t)(addr)), "r"((uint32_t)(bytes)) : "memory")

#define MBARRIER_WAIT_PARITY(addr, par) do {                                   \
    uint32_t _m = (uint32_t)(addr), _p = (uint32_t)(par), _d;                  \
    asm volatile(                                                              \
        "{\n\t.reg .pred p;\n\t"                                               \
        "mbarrier.try_wait.parity.acquire.cta.shared::cta.b64 p, [%1], %2;\n\t"\
        "selp.b32 %0, 1, 0, p;\n\t}"                                           \
        : "=r"(_d) : "r"(_m), "r"(_p) : "memory");                             \
    if (!_d) {                                                                 \
        asm volatile(                                                          \
            "{\n\t.reg .pred P1;\n\t"                                          \
            "WL_%=:\n\t"                                                       \
            "mbarrier.try_wait.parity.acquire.cta.shared::cta.b64 P1, [%0], %1, 0x989680;\n\t" \
            "@P1 bra.uni WD_%=;\n\t"                                           \
            "bra.uni WL_%=;\n\t"                                               \
            "WD_%=:\n\t}"                                                      \
            :: "r"(_m), "r"(_p) : "memory");                                   \
    }                                                                          \
} while (0)

// 1D bulk async copy gmem -> smem with transaction-count completion
__device__ __forceinline__ void bulk_g2s(uint32_t sdst, const void* gsrc,
                                         uint32_t bytes, uint32_t mbar) {
    asm volatile(
        "cp.async.bulk.shared::cluster.global.mbarrier::complete_tx::bytes "
        "[%0], [%1], %2, [%3];"
        :: "r"(sdst), "l"(gsrc), "r"(bytes), "r"(mbar) : "memory");
}

#define LDSM4(r, addr) \
    asm volatile("ldmatrix.sync.aligned.m8n8.x4.shared.b16 {%0,%1,%2,%3}, [%4];" \
                 : "=r"((r)[0]), "=r"((r)[1]), "=r"((r)[2]), "=r"((r)[3]) \
                 : "r"(addr))

#define MMA_BF16(ACCP, A0, A1, A2, A3, B0, B1)                              \
    asm volatile(                                                           \
        "mma.sync.aligned.m16n8k16.row.col.f32.bf16.bf16.f32 "              \
        "{%0,%1,%2,%3}, {%4,%5,%6,%7}, {%8,%9}, {%0,%1,%2,%3};\n"           \
        : "+f"((ACCP)[0]), "+f"((ACCP)[1]), "+f"((ACCP)[2]), "+f"((ACCP)[3])\
        : "r"(A0), "r"(A1), "r"(A2), "r"(A3), "r"(B0), "r"(B1))

// SW128 swizzle of a byte offset within a 128B-row tile
#define SWZ(o) ((o) ^ (((o) >> 3) & 0x70))

// ---------------------------------------------------------------------------
// Weight preprocessing: W (K,N) fp32 -> hi/lo bf16 tiles.
// Tile (nb,kc) = 128 n-rows x 64 k-halves, 16KB contiguous, SW128-swizzled.
// Grid: (Npad/32, K/64), 256 threads. n >= N rows are zero-filled.
// ---------------------------------------------------------------------------
__global__ void __launch_bounds__(256)
transpose_split_kernel(const float* __restrict__ W,
                       __nv_bfloat16* __restrict__ Thi,
                       __nv_bfloat16* __restrict__ Tlo,
                       int K, int N)
{
    __shared__ float t[64][33];
    const int tx = threadIdx.x & 31;
    const int ty = threadIdx.x >> 5;           // 0..7
    const int nbase = blockIdx.x * 32;
    const int kbase = blockIdx.y * 64;

#pragma unroll
    for (int r = 0; r < 8; r++) {
        int k = kbase + ty + r * 8;
        int n = nbase + tx;
        t[ty + r * 8][tx] = (n < N) ? W[(size_t)k * N + n] : 0.f;
    }
    __syncthreads();

    const size_t tile_base =
        ((size_t)(nbase >> 7) * (size_t)(K >> 6) + (size_t)(kbase >> 6)) << 13;

#pragma unroll
    for (int r = 0; r < 4; r++) {
        int nl  = ty + r * 8;                   // 0..31 within this CTA
        int row = (nbase & 127) + nl;           // row within 128-row tile
        float v0 = t[2 * tx][nl];
        float v1 = t[2 * tx + 1][nl];
        __nv_bfloat16 h0 = __float2bfloat16(v0);
        __nv_bfloat16 h1 = __float2bfloat16(v1);
        __nv_bfloat16 l0 = __float2bfloat16(v0 - __bfloat162float(h0));
        __nv_bfloat16 l1 = __float2bfloat16(v1 - __bfloat162float(h1));
        uint32_t off = (uint32_t)(row * 128 + 4 * tx);
        uint32_t sw  = off ^ ((uint32_t)(row & 7) << 4);
        *(__nv_bfloat162*)(Thi + tile_base + (sw >> 1)) = __halves2bfloat162(h0, h1);
        *(__nv_bfloat162*)(Tlo + tile_base + (sw >> 1)) = __halves2bfloat162(l0, l1);
    }
}

// ---------------------------------------------------------------------------
// Activation split: A (M,K) fp32 -> hi/lo bf16 tiles (same tile layout).
// K is a power of two (1024/2048/8192); kshift = log2(K).
// ---------------------------------------------------------------------------
__global__ void __launch_bounds__(256)
split_a_kernel(const float* __restrict__ A,
               __nv_bfloat16* __restrict__ hi, __nv_bfloat16* __restrict__ lo,
               int n4, int kshift)
{
    int idx = blockIdx.x * 256 + threadIdx.x;
    if (idx >= n4) return;
    const int K = 1 << kshift;
    int idx4 = idx << 2;
    int m = idx4 >> kshift;
    int k = idx4 & (K - 1);

    float4 v = ((const float4*)A)[idx];
    __nv_bfloat16 h0 = __float2bfloat16(v.x);
    __nv_bfloat16 h1 = __float2bfloat16(v.y);
    __nv_bfloat16 h2 = __float2bfloat16(v.z);
    __nv_bfloat16 h3 = __float2bfloat16(v.w);
    __nv_bfloat162 hA = __halves2bfloat162(h0, h1);
    __nv_bfloat162 hB = __halves2bfloat162(h2, h3);
    __nv_bfloat162 lA = __halves2bfloat162(
        __float2bfloat16(v.x - __bfloat162float(h0)),
        __float2bfloat16(v.y - __bfloat162float(h1)));
    __nv_bfloat162 lB = __halves2bfloat162(
        __float2bfloat16(v.z - __bfloat162float(h2)),
        __float2bfloat16(v.w - __bfloat162float(h3)));

    int mb = m >> 7, r = m & 127;
    int kc = k >> 6, kl = k & 63;
    uint32_t off = (uint32_t)(r * 128 + kl * 2);
    uint32_t sw  = off ^ ((uint32_t)(r & 7) << 4);   // stays 8B-aligned
    size_t base = (((size_t)mb * (size_t)(K >> 6) + (size_t)kc) << 13) + (sw >> 1);
    uint2 uh, ul;
    uh.x = *(uint32_t*)&hA; uh.y = *(uint32_t*)&hB;
    ul.x = *(uint32_t*)&lA; ul.y = *(uint32_t*)&lB;
    *(uint2*)(hi + base) = uh;
    *(uint2*)(lo + base) = ul;
}

// ---------------------------------------------------------------------------
// Split-bf16 GEMM on mma.sync.m16n8k16, bulk-copy fed.
// Ahi/Alo: tiled (mb,kc) activations; Bhi/Blo: tiled (nb,kc) weights.
// C = act(A @ W^T + bias).  D += Ah*Bh + Ah*Bl + Al*Bh, fp32 accumulate.
// CTA 128x128 out, 512 threads (4x4 warps, 32x32 warp tile), TBK=64 halves,
// 2-stage double buffer, fills via 4 x 16KB cp.async.bulk per slab.
// ---------------------------------------------------------------------------
#define TILE_BYTES  16384
#define STAGE_BYTES (4 * TILE_BYTES)          // Ah, Al, Bh, Bl
#define TCG_SMEM    (2 * STAGE_BYTES)         // 131072

template <int ACT>
__global__ void __launch_bounds__(512)
tc_gemm_kernel(const __nv_bfloat16* __restrict__ Ahi,
               const __nv_bfloat16* __restrict__ Alo,
               const __nv_bfloat16* __restrict__ Bhi,
               const __nv_bfloat16* __restrict__ Blo,
               const float* __restrict__ bias, float* __restrict__ C,
               int M, int N, int K)
{
    extern __shared__ char dsm[];
    __shared__ uint64_t mbar[2];

    const uint32_t sbase = smem_u32(dsm);
    const uint32_t mb[2] = { smem_u32(&mbar[0]), smem_u32(&mbar[1]) };

    const int tid  = threadIdx.x;
    const int lane = tid & 31;
    const int warp = tid >> 5;
    const int wm   = warp >> 2;               // 0..3 (M dir)
    const int wn   = warp & 3;                // 0..3 (N dir)
    const int bm   = blockIdx.y * 128;
    const int bn   = blockIdx.x * 128;
    const int g    = lane >> 2;
    const int q    = lane & 3;

    // ldmatrix per-lane addressing (within a 128-row x 128B tile)
    const int ar = lane & 15;                 // A row within m16 tile
    const int ac = (lane >> 4) * 16;          // A byte col (k8 group)
    const int br = (lane & 7) + ((lane >> 4) << 3);   // B row within n16 tile
    const int bc = ((lane >> 3) & 1) * 16;    // B byte col
    const uint32_t a_xor = (uint32_t)(ar & 7) << 4;
    const uint32_t b_xor = (uint32_t)(br & 7) << 4;
    uint32_t a_row_off[2], b_row_off[2];
#pragma unroll
    for (int mi = 0; mi < 2; mi++)
        a_row_off[mi] = (uint32_t)((wm * 32 + mi * 16 + ar) * 128);
#pragma unroll
    for (int nj = 0; nj < 2; nj++)
        b_row_off[nj] = (uint32_t)((wn * 32 + nj * 16 + br) * 128);

    if (tid == 0) { MBARRIER_INIT(mb[0], 1); MBARRIER_INIT(mb[1], 1); }
    __syncthreads();

    const int kcn = K >> 6;                    // number of 64-half slabs
    const size_t a_tile0 = (size_t)blockIdx.y * kcn;
    const size_t b_tile0 = (size_t)blockIdx.x * kcn;

    auto fill = [&](int c, int s) {            // tid 0 only
        MBARRIER_EXPECT_TX(mb[s], 4 * TILE_BYTES);
        const uint32_t st = sbase + s * STAGE_BYTES;
        const size_t ao = (a_tile0 + c) << 13; // halves
        const size_t bo = (b_tile0 + c) << 13;
        bulk_g2s(st,                   Ahi + ao, TILE_BYTES, mb[s]);
        bulk_g2s(st + TILE_BYTES,      Alo + ao, TILE_BYTES, mb[s]);
        bulk_g2s(st + 2 * TILE_BYTES,  Bhi + bo, TILE_BYTES, mb[s]);
        bulk_g2s(st + 3 * TILE_BYTES,  Blo + bo, TILE_BYTES, mb[s]);
    };

    float acc[2][4][4];
#pragma unroll
    for (int mi = 0; mi < 2; mi++)
#pragma unroll
        for (int ni = 0; ni < 4; ni++)
#pragma unroll
            for (int f = 0; f < 4; f++) acc[mi][ni][f] = 0.f;

    if (tid == 0) { fill(0, 0); fill(1, 1); }

    int ph0 = 0, ph1 = 0;
    for (int c = 0; c < kcn; c++) {
        const int s = c & 1;
        if (s == 0) { MBARRIER_WAIT_PARITY(mb[0], ph0); ph0 ^= 1; }
        else        { MBARRIER_WAIT_PARITY(mb[1], ph1); ph1 ^= 1; }

        const uint32_t st = sbase + s * STAGE_BYTES;
        const uint32_t Ah = st;
        const uint32_t Al = st + TILE_BYTES;
        const uint32_t Bh = st + 2 * TILE_BYTES;
        const uint32_t Bl = st + 3 * TILE_BYTES;

#pragma unroll
        for (int ks = 0; ks < 4; ks++) {
            const uint32_t kb = ks * 32;
            uint32_t ah[2][4], al[2][4];
#pragma unroll
            for (int mi = 0; mi < 2; mi++) {
                uint32_t off = a_row_off[mi] + (((kb + ac)) ^ a_xor);
                LDSM4(ah[mi], Ah + off);
                LDSM4(al[mi], Al + off);
            }
            uint32_t bh[2][4], bl[2][4];
#pragma unroll
            for (int nj = 0; nj < 2; nj++) {
                uint32_t off = b_row_off[nj] + (((kb + bc)) ^ b_xor);
                LDSM4(bh[nj], Bh + off);
                LDSM4(bl[nj], Bl + off);
            }
#pragma unroll
            for (int mi = 0; mi < 2; mi++)
#pragma unroll
                for (int nj = 0; nj < 2; nj++)
#pragma unroll
                    for (int hf = 0; hf < 2; hf++) {
                        float* ap = acc[mi][nj * 2 + hf];
                        MMA_BF16(ap, ah[mi][0], ah[mi][1], ah[mi][2], ah[mi][3],
                                 bh[nj][hf * 2], bh[nj][hf * 2 + 1]);   // hi*hi
                        MMA_BF16(ap, ah[mi][0], ah[mi][1], ah[mi][2], ah[mi][3],
                                 bl[nj][hf * 2], bl[nj][hf * 2 + 1]);   // hi*lo
                        MMA_BF16(ap, al[mi][0], al[mi][1], al[mi][2], al[mi][3],
                                 bh[nj][hf * 2], bh[nj][hf * 2 + 1]);   // lo*hi
                    }
        }
        __syncthreads();                       // all reads of stage s done
        if (tid == 0 && c + 2 < kcn) fill(c + 2, s);
    }

    // ---- epilogue (N even at all call sites -> pairwise guard ok)
#pragma unroll
    for (int mi = 0; mi < 2; mi++) {
        const int m0 = bm + wm * 32 + mi * 16;
#pragma unroll
        for (int ni = 0; ni < 4; ni++) {
            const int n = bn + wn * 32 + ni * 8 + 2 * q;
            if (n >= N) continue;
            float b0 = bias ? bias[n]     : 0.f;
            float b1 = bias ? bias[n + 1] : 0.f;
#pragma unroll
            for (int hf = 0; hf < 2; hf++) {
                const int m = m0 + g + hf * 8;
                float v0 = acc[mi][ni][hf * 2 + 0] + b0;
                float v1 = acc[mi][ni][hf * 2 + 1] + b1;
                if (ACT == 1) { v0 = fmaxf(v0, 0.f); v1 = fmaxf(v1, 0.f); }
                *(float2*)(C + (size_t)m * N + n) = make_float2(v0, v1);
            }
        }
    }

    __syncthreads();
    if (tid == 0) { MBARRIER_INVAL(mb[0]); MBARRIER_INVAL(mb[1]); }
}

// ---------------------------------------------------------------------------
// Small fp32 SIMT GEMM (kept for the tiny final layer N=2)
// ---------------------------------------------------------------------------
#define BM 128
#define BN 64
#define BK 16

template <int ACT>
__global__ void __launch_bounds__(256)
gemm_kernel(const float* __restrict__ A, const float* __restrict__ W,
            const float* __restrict__ bias, float* __restrict__ C,
            int M, int N, int K)
{
    __shared__ float As[BK][BM + 1];
    __shared__ float Ws[BK][BN];

    const int tid  = threadIdx.x;
    const int bm   = blockIdx.y * BM;
    const int bn   = blockIdx.x * BN;
    const int tx   = tid & 15;
    const int ty   = tid >> 4;
    const int arow = tid >> 2;
    const int acol = (tid & 3) * 4;
    const int wrow = tid >> 4;
    const int wcol = (tid & 15) * 4;

    float acc[8][4];
#pragma unroll
    for (int i = 0; i < 8; i++)
#pragma unroll
        for (int j = 0; j < 4; j++) acc[i][j] = 0.f;

    for (int k0 = 0; k0 < K; k0 += BK) {
#pragma unroll
        for (int half = 0; half < 2; half++) {
            int m = bm + arow + half * 64;
            float4 v = make_float4(0.f, 0.f, 0.f, 0.f);
            if (m < M)
                v = *(const float4*)(A + (size_t)m * K + k0 + acol);
            As[acol + 0][arow + half * 64] = v.x;
            As[acol + 1][arow + half * 64] = v.y;
            As[acol + 2][arow + half * 64] = v.z;
            As[acol + 3][arow + half * 64] = v.w;
        }
        {
            int kk = k0 + wrow;
            int n  = bn + wcol;
#pragma unroll
            for (int j = 0; j < 4; j++)
                Ws[wrow][wcol + j] = (n + j < N) ? W[(size_t)kk * N + n + j] : 0.f;
        }
        __syncthreads();

#pragma unroll
        for (int k = 0; k < BK; k++) {
            float ra[8];
#pragma unroll
            for (int i = 0; i < 8; i++) ra[i] = As[k][ty * 8 + i];
            float rb[4];
#pragma unroll
            for (int j = 0; j < 4; j++) rb[j] = Ws[k][tx * 4 + j];
#pragma unroll
            for (int i = 0; i < 8; i++)
#pragma unroll
                for (int j = 0; j < 4; j++)
                    acc[i][j] = fmaf(ra[i], rb[j], acc[i][j]);
        }
        __syncthreads();
    }

#pragma unroll
    for (int i = 0; i < 8; i++) {
        int m = bm + ty * 8 + i;
        if (m >= M) continue;
#pragma unroll
        for (int j = 0; j < 4; j++) {
            int n = bn + tx * 4 + j;
            if (n >= N) continue;
            float v = acc[i][j];
            if (bias) v += bias[n];
            if (ACT == 1) v = fmaxf(v, 0.f);
            C[(size_t)m * N + n] = v;
        }
    }
}

// ---------------------------------------------------------------------------
// Causal depthwise conv (DCONV=4) + bias + SiLU over the xBC slice of zxbcdt.
// ---------------------------------------------------------------------------
__global__ void conv_silu_kernel(const float* __restrict__ zx,
                                 const float* __restrict__ conv_w,
                                 const float* __restrict__ conv_b,
                                 float* __restrict__ xbc)
{
    int c = blockIdx.x * blockDim.x + threadIdx.x;
    int b = blockIdx.y;
    if (c >= CONV_DIM) return;

    float w0 = conv_w[c * 4 + 0], w1 = conv_w[c * 4 + 1];
    float w2 = conv_w[c * 4 + 2], w3 = conv_w[c * 4 + 3];
    float bb = conv_b[c];

    const float* src = zx + (size_t)b * SEQL * DPROJ + D_INNER + c;
    float v[SEQL];
#pragma unroll
    for (int l = 0; l < SEQL; l++) v[l] = src[(size_t)l * DPROJ];

#pragma unroll
    for (int l = 0; l < SEQL; l++) {
        float s = bb + v[l] * w3;
        if (l >= 1) s += v[l - 1] * w2;
        if (l >= 2) s += v[l - 2] * w1;
        if (l >= 3) s += v[l - 3] * w0;
        s = s / (1.f + expf(-s));   // silu
        xbc[((size_t)b * SEQL + l) * CONV_DIM + c] = s;
    }
}

// ---------------------------------------------------------------------------
// dt = softplus(dt_raw + dt_bias); dA = exp(-exp(A_log) * dt)
// ---------------------------------------------------------------------------
__global__ void dt_kernel(const float* __restrict__ zx,
                          const float* __restrict__ dt_bias,
                          const float* __restrict__ A_log,
                          float* __restrict__ dtb, float* __restrict__ dAb)
{
    int i = blockIdx.x * blockDim.x + threadIdx.x;
    if (i >= ROWS * NHEADS) return;
    int row = i >> 5, h = i & 31;
    float x = zx[(size_t)row * DPROJ + (D_INNER + CONV_DIM) + h] + dt_bias[h];
    float dt = (x > 20.f) ? x : log1pf(expf(x));
    float dA = expf(-expf(A_log[h]) * dt);
    dtb[i] = dt;
    dAb[i] = dA;
}

// ---------------------------------------------------------------------------
// SSM scan: one CTA per (batch, head). State h[64][128] in registers.
// ---------------------------------------------------------------------------
__global__ void __launch_bounds__(256)
scan_kernel(const float* __restrict__ xbc,
            const float* __restrict__ dtb, const float* __restrict__ dAb,
            const float* __restrict__ Dp, float* __restrict__ y)
{
    const int b = blockIdx.x;
    const int h = blockIdx.y;
    const int t = threadIdx.x;
    const int p = t >> 2;
    const int q = t & 3;

    __shared__ float Bsh[DSTATE];
    __shared__ float Csh[DSTATE];
    __shared__ float xsh[HEADDIM];
    __shared__ float sc[2];

    float st[32];
#pragma unroll
    for (int i = 0; i < 32; i++) st[i] = 0.f;
    const float Dh = Dp[h];

    for (int l = 0; l < SEQL; l++) {
        const int row = b * SEQL + l;
        const float* base = xbc + (size_t)row * CONV_DIM;
        if (t < 128) Bsh[t] = base[D_INNER + t];
        else         Csh[t - 128] = base[D_INNER + DSTATE + (t - 128)];
        if (t < HEADDIM) xsh[t] = base[h * HEADDIM + t];
        if (t == 0) { sc[0] = dAb[row * NHEADS + h]; sc[1] = dtb[row * NHEADS + h]; }
        __syncthreads();

        const float xv   = xsh[p];
        const float coef = sc[1] * xv;
        const float dAv  = sc[0];
        float part = 0.f;
#pragma unroll
        for (int i = 0; i < 32; i++) {
            const int s = q + 4 * i;
            st[i] = fmaf(dAv, st[i], coef * Bsh[s]);
            part  = fmaf(st[i], Csh[s], part);
        }
        part += __shfl_down_sync(0xffffffffu, part, 2);
        part += __shfl_down_sync(0xffffffffu, part, 1);
        if (q == 0)
            y[(size_t)row * D_INNER + h * HEADDIM + p] = part + xv * Dh;
        __syncthreads();
    }
}

// ---------------------------------------------------------------------------
// y = y * silu(z); y *= rsqrt(mean(y^2) + 1e-5) * norm_w
// ---------------------------------------------------------------------------
__global__ void __launch_bounds__(256)
gated_rmsnorm_kernel(float* __restrict__ ybuf, const float* __restrict__ zx,
                     const float* __restrict__ norm_w)
{
    const int row = blockIdx.x;
    const int t   = threadIdx.x;
    float* yb       = ybuf + (size_t)row * D_INNER;
    const float* zb = zx   + (size_t)row * DPROJ;

    float v[8];
    float ss = 0.f;
#pragma unroll
    for (int j = 0; j < 8; j++) {
        int d = t + j * 256;
        float z   = zb[d];
        float val = yb[d] * (z / (1.f + expf(-z)));
        v[j] = val;
        ss  = fmaf(val, val, ss);
    }
#pragma unroll
    for (int o = 16; o > 0; o >>= 1)
        ss += __shfl_down_sync(0xffffffffu, ss, o);

    __shared__ float red[8];
    __shared__ float s_scale;
    if ((t & 31) == 0) red[t >> 5] = ss;
    __syncthreads();
    if (t == 0) {
        float s = 0.f;
        for (int i = 0; i < 8; i++) s += red[i];
        s_scale = rsqrtf(s / (float)D_INNER + 1e-5f);
    }
    __syncthreads();
    const float scale = s_scale;
#pragma unroll
    for (int j = 0; j < 8; j++) {
        int d = t + j * 256;
        yb[d] = v[j] * scale * norm_w[d];
    }
}

// ---------------------------------------------------------------------------
// Host-side orchestration
// ---------------------------------------------------------------------------
struct MambaW {
    const float *in_proj, *conv_w, *conv_b, *dt_bias, *A_log, *D, *norm_w, *out_proj;
};

static int ilog2(int x) { int s = 0; while ((1 << s) < x) s++; return s; }

extern "C" void kernel_launch(void* const* d_in, const int* in_sizes, int n_in,
                              void* d_out, int out_size)
{
    const float* x      = (const float*)d_in[0];
    const float* w_in1  = (const float*)d_in[1];
    const float* b_in1  = (const float*)d_in[2];
    const float* w_in2  = (const float*)d_in[3];
    const float* b_in2  = (const float*)d_in[4];
    MambaW m1 = { (const float*)d_in[5],  (const float*)d_in[6],  (const float*)d_in[7],
                  (const float*)d_in[8],  (const float*)d_in[9],  (const float*)d_in[10],
                  (const float*)d_in[11], (const float*)d_in[12] };
    MambaW m2 = { (const float*)d_in[13], (const float*)d_in[14], (const float*)d_in[15],
                  (const float*)d_in[16], (const float*)d_in[17], (const float*)d_in[18],
                  (const float*)d_in[19], (const float*)d_in[20] };
    const float* w_out1 = (const float*)d_in[21];
    const float* b_out1 = (const float*)d_in[22];
    const float* w_out2 = (const float*)d_in[23];
    const float* b_out2 = (const float*)d_in[24];
    float* out = (float*)d_out;

    cudaFuncSetAttribute(tc_gemm_kernel<0>,
                         cudaFuncAttributeMaxDynamicSharedMemorySize, TCG_SMEM);
    cudaFuncSetAttribute(tc_gemm_kernel<1>,
                         cudaFuncAttributeMaxDynamicSharedMemorySize, TCG_SMEM);

    float *a, *h, *zx, *xbc, *dtb, *dAb, *ybuf;
    __nv_bfloat16 *whi, *wlo, *ahi, *alo;
    cudaGetSymbolAddress((void**)&a,    g_a);
    cudaGetSymbolAddress((void**)&h,    g_h);
    cudaGetSymbolAddress((void**)&zx,   g_zx);
    cudaGetSymbolAddress((void**)&xbc,  g_xbc);
    cudaGetSymbolAddress((void**)&dtb,  g_dt);
    cudaGetSymbolAddress((void**)&dAb,  g_dA);
    cudaGetSymbolAddress((void**)&ybuf, g_y);
    cudaGetSymbolAddress((void**)&whi,  g_whi);
    cudaGetSymbolAddress((void**)&wlo,  g_wlo);
    cudaGetSymbolAddress((void**)&ahi,  g_ahi);
    cudaGetSymbolAddress((void**)&alo,  g_alo);

    // ---- weight preprocessing: fp32 (K,N) -> split-bf16 swizzled tiles
    auto tsp = [&](const float* W, size_t off, int K, int N, int Npad) {
        transpose_split_kernel<<<dim3(Npad / 32, K / 64), 256>>>(
            W, whi + off, wlo + off, K, N);
    };
    tsp(w_in1,       OFF_WIN1,    1024, 8192, 8192);
    tsp(w_in2,       OFF_WIN2,    8192, 8192, 8192);
    tsp(m1.in_proj,  OFF_M1_INP,  1024, DPROJ, 4480);
    tsp(m2.in_proj,  OFF_M2_INP,  1024, DPROJ, 4480);
    tsp(m1.out_proj, OFF_M1_OUTP, 2048, 1024, 1024);
    tsp(m2.out_proj, OFF_M2_OUTP, 2048, 1024, 1024);
    tsp(w_out1,      OFF_WOUT1,   8192, 1024, 1024);

    // GEMM wrapper: split+tile A, then bulk-fed MMA GEMM
    auto tcgemm = [&](int act, const float* A, size_t woff, const float* bias,
                      float* C, int M, int N, int Npad, int K) {
        int n4 = (M * K) / 4;
        split_a_kernel<<<(n4 + 255) / 256, 256>>>(A, ahi, alo, n4, ilog2(K));
        dim3 grid(Npad / 128, M / 128);
        if (act)
            tc_gemm_kernel<1><<<grid, 512, TCG_SMEM>>>(
                ahi, alo, whi + woff, wlo + woff, bias, C, M, N, K);
        else
            tc_gemm_kernel<0><<<grid, 512, TCG_SMEM>>>(
                ahi, alo, whi + woff, wlo + woff, bias, C, M, N, K);
    };

    // ---- MLP in: a = relu(x @ w_in1 + b_in1); h = a @ w_in2 + b_in2
    tcgemm(1, x, OFF_WIN1, b_in1, a, BATCH, 8192, 8192, 1024);
    tcgemm(0, a, OFF_WIN2, b_in2, h, BATCH, 8192, 8192, 8192);

    // ---- 2x Mamba2 layers (h viewed as (2048, 1024) == (256, 8, 1024))
    const MambaW* layers[2] = { &m1, &m2 };
    const size_t inp_off[2]  = { OFF_M1_INP,  OFF_M2_INP };
    const size_t outp_off[2] = { OFF_M1_OUTP, OFF_M2_OUTP };
    for (int li = 0; li < 2; li++) {
        const MambaW& p = *layers[li];
        tcgemm(0, h, inp_off[li], nullptr, zx, ROWS, DPROJ, 4480, HIDD);
        conv_silu_kernel<<<dim3(CONV_DIM / 256, BATCH), 256>>>(zx, p.conv_w,
                                                               p.conv_b, xbc);
        dt_kernel<<<(ROWS * NHEADS) / 256, 256>>>(zx, p.dt_bias, p.A_log, dtb, dAb);
        scan_kernel<<<dim3(BATCH, NHEADS), 256>>>(xbc, dtb, dAb, p.D, ybuf);
        gated_rmsnorm_kernel<<<ROWS, 256>>>(ybuf, zx, p.norm_w);
        tcgemm(0, ybuf, outp_off[li], nullptr, h, ROWS, HIDD, 1024, D_INNER);
    }

    // ---- MLP out: a = relu(h @ w_out1 + b_out1); out = a @ w_out2 + b_out2
    tcgemm(1, h, OFF_WOUT1, b_out1, a, BATCH, 1024, 1024, 8192);
    gemm_kernel<0><<<dim3(1, (BATCH + BM - 1) / BM), 256>>>(a, w_out2, b_out2, out,
                                                            BATCH, 2, 1024);
}

// round 8
// speedup vs baseline: 2.6964x; 1.0255x over previous
#include <cuda_runtime.h>
#include <cuda_bf16.h>
#include <cstdint>

// ---------------------------------------------------------------------------
// Problem dimensions (fixed by the reference)
// ---------------------------------------------------------------------------
#define BATCH    256
#define SEQL     8
#define HIDD     1024            // HID
#define D_INNER  2048
#define DSTATE   128
#define NHEADS   32
#define HEADDIM  64
#define CONV_DIM 2304            // D_INNER + 2*DSTATE
#define DPROJ    4384            // 2*D_INNER + 2*DSTATE + NHEADS
#define ROWS     (BATCH * SEQL)  // 2048

// ---------------------------------------------------------------------------
// Scratch (static device buffers; no allocation allowed in kernel_launch)
// ---------------------------------------------------------------------------
__device__ float g_a  [BATCH * 8192];     // fp32 intermediate (out1 output)
__device__ float g_zx [ROWS  * DPROJ];    // zxbcdt (2048 x 4384)
__device__ float g_xbc[ROWS  * CONV_DIM]; // conv+silu output (2048 x 2304)
__device__ float g_dt [ROWS  * NHEADS];
__device__ float g_dA [ROWS  * NHEADS];
__device__ float g_y  [ROWS  * D_INNER];  // SSM output (2048 x 2048)

// Two ping-pong split-bf16 tiled activation buffers (max 2048x2048)
#define AMAX 4194304
__device__ __nv_bfloat16 g_p1hi[AMAX];
__device__ __nv_bfloat16 g_p1lo[AMAX];
__device__ __nv_bfloat16 g_p2hi[AMAX];
__device__ __nv_bfloat16 g_p2lo[AMAX];

// Split-bf16 tiled weights (tiles of 128 n-rows x 64 k-halves, SW128-swizzled,
// one (nb,kc) tile = 16KB contiguous). N padded to mult of 128.
#define OFF_WIN1     0ULL
#define OFF_WIN2     8388608ULL      // win1: 8192*1024
#define OFF_M1_INP   75497472ULL     // win2: 8192*8192
#define OFF_M2_INP   80084992ULL     // inproj: 4480*1024
#define OFF_M1_OUTP  84672512ULL
#define OFF_M2_OUTP  86769664ULL     // outproj: 1024*2048
#define OFF_WOUT1    88866816ULL
#define WT_TOTAL     97255424ULL     // + wout1: 1024*8192
__device__ __nv_bfloat16 g_whi[WT_TOTAL];
__device__ __nv_bfloat16 g_wlo[WT_TOTAL];

// ---------------------------------------------------------------------------
// PTX helpers
// ---------------------------------------------------------------------------
__device__ __forceinline__ uint32_t smem_u32(const void* p) {
    uint32_t a;
    asm("{ .reg .u64 t; cvta.to.shared.u64 t, %1; cvt.u32.u64 %0, t; }"
        : "=r"(a) : "l"(p));
    return a;
}

#define MBARRIER_INIT(addr, count) \
    asm volatile("mbarrier.init.shared.b64 [%0], %1;" \
                 :: "r"((uint32_t)(addr)), "r"((uint32_t)(count)) : "memory")
#define MBARRIER_INVAL(addr) \
    asm volatile("mbarrier.inval.shared.b64 [%0];" \
                 :: "r"((uint32_t)(addr)) : "memory")
#define MBARRIER_EXPECT_TX(addr, bytes) \
    asm volatile("mbarrier.arrive.expect_tx.shared.b64 _, [%0], %1;" \
                 :: "r"((uint32_t)(addr)), "r"((uint32_t)(bytes)) : "memory")

#define MBARRIER_WAIT_PARITY(addr, par) do {                                   \
    uint32_t _m = (uint32_t)(addr), _p = (uint32_t)(par), _d;                  \
    asm volatile(                                                              \
        "{\n\t.reg .pred p;\n\t"                                               \
        "mbarrier.try_wait.parity.acquire.cta.shared::cta.b64 p, [%1], %2;\n\t"\
        "selp.b32 %0, 1, 0, p;\n\t}"                                           \
        : "=r"(_d) : "r"(_m), "r"(_p) : "memory");                             \
    if (!_d) {                                                                 \
        asm volatile(                                                          \
            "{\n\t.reg .pred P1;\n\t"                                          \
            "WL_%=:\n\t"                                                       \
            "mbarrier.try_wait.parity.acquire.cta.shared::cta.b64 P1, [%0], %1, 0x989680;\n\t" \
            "@P1 bra.uni WD_%=;\n\t"                                           \
            "bra.uni WL_%=;\n\t"                                               \
            "WD_%=:\n\t}"                                                      \
            :: "r"(_m), "r"(_p) : "memory");                                   \
    }                                                                          \
} while (0)

__device__ __forceinline__ void bulk_g2s(uint32_t sdst, const void* gsrc,
                                         uint32_t bytes, uint32_t mbar) {
    asm volatile(
        "cp.async.bulk.shared::cluster.global.mbarrier::complete_tx::bytes "
        "[%0], [%1], %2, [%3];"
        :: "r"(sdst), "l"(gsrc), "r"(bytes), "r"(mbar) : "memory");
}

#define LDSM4(r, addr) \
    asm volatile("ldmatrix.sync.aligned.m8n8.x4.shared.b16 {%0,%1,%2,%3}, [%4];" \
                 : "=r"((r)[0]), "=r"((r)[1]), "=r"((r)[2]), "=r"((r)[3]) \
                 : "r"(addr))

#define MMA_BF16(ACCP, A0, A1, A2, A3, B0, B1)                              \
    asm volatile(                                                           \
        "mma.sync.aligned.m16n8k16.row.col.f32.bf16.bf16.f32 "              \
        "{%0,%1,%2,%3}, {%4,%5,%6,%7}, {%8,%9}, {%0,%1,%2,%3};\n"           \
        : "+f"((ACCP)[0]), "+f"((ACCP)[1]), "+f"((ACCP)[2]), "+f"((ACCP)[3])\
        : "r"(A0), "r"(A1), "r"(A2), "r"(A3), "r"(B0), "r"(B1))

// Split-tile address: element (row mr, col kk) of an (M,Kc) operand in
// 128x64 swizzled tiles; returns offset in halves. kk must be even.
__device__ __forceinline__ size_t tile_off(size_t mr, int kk, int kc_n) {
    int mb = (int)(mr >> 7), r = (int)(mr & 127);
    int kc = kk >> 6, kl = kk & 63;
    uint32_t off = (uint32_t)(r * 128 + kl * 2);
    uint32_t sw  = off ^ ((uint32_t)(r & 7) << 4);
    return (((size_t)mb * kc_n + kc) << 13) + (sw >> 1);
}

__device__ __forceinline__ void split_store(__nv_bfloat16* hi, __nv_bfloat16* lo,
                                            size_t base, float v0, float v1) {
    __nv_bfloat16 h0 = __float2bfloat16(v0);
    __nv_bfloat16 h1 = __float2bfloat16(v1);
    *(__nv_bfloat162*)(hi + base) = __halves2bfloat162(h0, h1);
    *(__nv_bfloat162*)(lo + base) = __halves2bfloat162(
        __float2bfloat16(v0 - __bfloat162float(h0)),
        __float2bfloat16(v1 - __bfloat162float(h1)));
}

// ---------------------------------------------------------------------------
// Weight preprocessing: W (K,N) fp32 -> hi/lo bf16 tiles (128 x 64h, SW128).
// Grid: (Npad/32, K/64), 256 threads. n >= N rows zero-filled.
// ---------------------------------------------------------------------------
__global__ void __launch_bounds__(256)
transpose_split_kernel(const float* __restrict__ W,
                       __nv_bfloat16* __restrict__ Thi,
                       __nv_bfloat16* __restrict__ Tlo,
                       int K, int N)
{
    __shared__ float t[64][33];
    const int tx = threadIdx.x & 31;
    const int ty = threadIdx.x >> 5;
    const int nbase = blockIdx.x * 32;
    const int kbase = blockIdx.y * 64;

#pragma unroll
    for (int r = 0; r < 8; r++) {
        int k = kbase + ty + r * 8;
        int n = nbase + tx;
        t[ty + r * 8][tx] = (n < N) ? W[(size_t)k * N + n] : 0.f;
    }
    __syncthreads();

    const size_t tile_base =
        ((size_t)(nbase >> 7) * (size_t)(K >> 6) + (size_t)(kbase >> 6)) << 13;

#pragma unroll
    for (int r = 0; r < 4; r++) {
        int nl  = ty + r * 8;
        int row = (nbase & 127) + nl;
        float v0 = t[2 * tx][nl];
        float v1 = t[2 * tx + 1][nl];
        uint32_t off = (uint32_t)(row * 128 + 4 * tx);
        uint32_t sw  = off ^ ((uint32_t)(row & 7) << 4);
        split_store(Thi, Tlo, tile_base + (sw >> 1), v0, v1);
    }
}

// ---------------------------------------------------------------------------
// Activation split: A (M,K) fp32 -> hi/lo bf16 tiles. K = 1<<kshift.
// ---------------------------------------------------------------------------
__global__ void __launch_bounds__(256)
split_a_kernel(const float* __restrict__ A,
               __nv_bfloat16* __restrict__ hi, __nv_bfloat16* __restrict__ lo,
               int n4, int kshift)
{
    int idx = blockIdx.x * 256 + threadIdx.x;
    if (idx >= n4) return;
    const int K = 1 << kshift;
    int idx4 = idx << 2;
    size_t m = (size_t)(idx4 >> kshift);
    int k = idx4 & (K - 1);
    float4 v = ((const float4*)A)[idx];
    size_t b0 = tile_off(m, k, K >> 6);
    size_t b1 = tile_off(m, k + 2, K >> 6);
    split_store(hi, lo, b0, v.x, v.y);
    split_store(hi, lo, b1, v.z, v.w);
}

// ---------------------------------------------------------------------------
// Split-bf16 GEMM on mma.sync.m16n8k16, 3-stage bulk-copy pipeline.
// Ahi/Alo: tiled (mb,kc) activations; Bhi/Blo: tiled (nb,kc) weights.
// OUT=0: C fp32 (M,N).  OUT=1: split tiles for consumer with K' = 1<<ksh
// (flat remap: element (m,n) -> row (m*N+n)>>ksh, col (m*N+n)&(K'-1)).
// ---------------------------------------------------------------------------
#define TILE_BYTES  16384
#define STAGE_BYTES (4 * TILE_BYTES)          // Ah, Al, Bh, Bl
#define NSTAGE      3
#define TCG_SMEM    (NSTAGE * STAGE_BYTES)    // 196608

template <int ACT, int OUT>
__global__ void __launch_bounds__(512)
tc_gemm_kernel(const __nv_bfloat16* __restrict__ Ahi,
               const __nv_bfloat16* __restrict__ Alo,
               const __nv_bfloat16* __restrict__ Bhi,
               const __nv_bfloat16* __restrict__ Blo,
               const float* __restrict__ bias, float* __restrict__ C,
               __nv_bfloat16* __restrict__ Chi, __nv_bfloat16* __restrict__ Clo,
               int ksh, int M, int N, int K)
{
    extern __shared__ char dsm[];
    __shared__ uint64_t mbar[NSTAGE];

    const uint32_t sbase = smem_u32(dsm);
    uint32_t mb[NSTAGE];
#pragma unroll
    for (int i = 0; i < NSTAGE; i++) mb[i] = smem_u32(&mbar[i]);

    const int tid  = threadIdx.x;
    const int lane = tid & 31;
    const int warp = tid >> 5;
    const int wm   = warp >> 2;
    const int wn   = warp & 3;
    const int bm   = blockIdx.y * 128;
    const int bn   = blockIdx.x * 128;
    const int g    = lane >> 2;
    const int q    = lane & 3;

    const int ar = lane & 15;
    const int ac = (lane >> 4) * 16;
    const int br = (lane & 7) + ((lane >> 4) << 3);
    const int bc = ((lane >> 3) & 1) * 16;
    const uint32_t a_xor = (uint32_t)(ar & 7) << 4;
    const uint32_t b_xor = (uint32_t)(br & 7) << 4;
    uint32_t a_row_off[2], b_row_off[2];
#pragma unroll
    for (int mi = 0; mi < 2; mi++)
        a_row_off[mi] = (uint32_t)((wm * 32 + mi * 16 + ar) * 128);
#pragma unroll
    for (int nj = 0; nj < 2; nj++)
        b_row_off[nj] = (uint32_t)((wn * 32 + nj * 16 + br) * 128);

    if (tid == 0)
#pragma unroll
        for (int i = 0; i < NSTAGE; i++) MBARRIER_INIT(mb[i], 1);
    __syncthreads();

    const int kcn = K >> 6;
    const size_t a_tile0 = (size_t)blockIdx.y * kcn;
    const size_t b_tile0 = (size_t)blockIdx.x * kcn;

    auto fill = [&](int c, int s) {            // tid 0 only
        MBARRIER_EXPECT_TX(mb[s], 4 * TILE_BYTES);
        const uint32_t st = sbase + s * STAGE_BYTES;
        const size_t ao = (a_tile0 + c) << 13;
        const size_t bo = (b_tile0 + c) << 13;
        bulk_g2s(st,                   Ahi + ao, TILE_BYTES, mb[s]);
        bulk_g2s(st + TILE_BYTES,      Alo + ao, TILE_BYTES, mb[s]);
        bulk_g2s(st + 2 * TILE_BYTES,  Bhi + bo, TILE_BYTES, mb[s]);
        bulk_g2s(st + 3 * TILE_BYTES,  Blo + bo, TILE_BYTES, mb[s]);
    };

    float acc[2][4][4];
#pragma unroll
    for (int mi = 0; mi < 2; mi++)
#pragma unroll
        for (int ni = 0; ni < 4; ni++)
#pragma unroll
            for (int f = 0; f < 4; f++) acc[mi][ni][f] = 0.f;

    if (tid == 0)
        for (int c = 0; c < NSTAGE && c < kcn; c++) fill(c, c);

    int ph[NSTAGE] = {0, 0, 0};
    int s = 0;
    for (int c = 0; c < kcn; c++) {
        MBARRIER_WAIT_PARITY(mb[s], ph[s]);
        ph[s] ^= 1;

        const uint32_t st = sbase + s * STAGE_BYTES;
        const uint32_t Ah = st;
        const uint32_t Al = st + TILE_BYTES;
        const uint32_t Bh = st + 2 * TILE_BYTES;
        const uint32_t Bl = st + 3 * TILE_BYTES;

#pragma unroll
        for (int ks = 0; ks < 4; ks++) {
            const uint32_t kb = ks * 32;
            uint32_t ah[2][4], al[2][4];
#pragma unroll
            for (int mi = 0; mi < 2; mi++) {
                uint32_t off = a_row_off[mi] + ((kb + ac) ^ a_xor);
                LDSM4(ah[mi], Ah + off);
                LDSM4(al[mi], Al + off);
            }
            uint32_t bh[2][4], bl[2][4];
#pragma unroll
            for (int nj = 0; nj < 2; nj++) {
                uint32_t off = b_row_off[nj] + ((kb + bc) ^ b_xor);
                LDSM4(bh[nj], Bh + off);
                LDSM4(bl[nj], Bl + off);
            }
#pragma unroll
            for (int mi = 0; mi < 2; mi++)
#pragma unroll
                for (int nj = 0; nj < 2; nj++)
#pragma unroll
                    for (int hf = 0; hf < 2; hf++) {
                        float* ap = acc[mi][nj * 2 + hf];
                        MMA_BF16(ap, ah[mi][0], ah[mi][1], ah[mi][2], ah[mi][3],
                                 bh[nj][hf * 2], bh[nj][hf * 2 + 1]);
                        MMA_BF16(ap, ah[mi][0], ah[mi][1], ah[mi][2], ah[mi][3],
                                 bl[nj][hf * 2], bl[nj][hf * 2 + 1]);
                        MMA_BF16(ap, al[mi][0], al[mi][1], al[mi][2], al[mi][3],
                                 bh[nj][hf * 2], bh[nj][hf * 2 + 1]);
                    }
        }
        __syncthreads();                       // all reads of stage s done
        if (tid == 0 && c + NSTAGE < kcn) fill(c + NSTAGE, s);
        s = (s == NSTAGE - 1) ? 0 : s + 1;
    }

    // ---- epilogue (N even everywhere -> pairwise guard ok)
    const int Kc = 1 << ksh;
#pragma unroll
    for (int mi = 0; mi < 2; mi++) {
        const int m0 = bm + wm * 32 + mi * 16;
#pragma unroll
        for (int ni = 0; ni < 4; ni++) {
            const int n = bn + wn * 32 + ni * 8 + 2 * q;
            if (n >= N) continue;
            float b0 = bias ? bias[n]     : 0.f;
            float b1 = bias ? bias[n + 1] : 0.f;
#pragma unroll
            for (int hf = 0; hf < 2; hf++) {
                const int m = m0 + g + hf * 8;
                float v0 = acc[mi][ni][hf * 2 + 0] + b0;
                float v1 = acc[mi][ni][hf * 2 + 1] + b1;
                if (ACT == 1) { v0 = fmaxf(v0, 0.f); v1 = fmaxf(v1, 0.f); }
                if (OUT == 0) {
                    *(float2*)(C + (size_t)m * N + n) = make_float2(v0, v1);
                } else {
                    size_t flat = (size_t)m * N + n;
                    size_t mr = flat >> ksh;
                    int kk = (int)(flat & (Kc - 1));
                    split_store(Chi, Clo, tile_off(mr, kk, Kc >> 6), v0, v1);
                }
            }
        }
    }

    __syncthreads();
    if (tid == 0)
#pragma unroll
        for (int i = 0; i < NSTAGE; i++) MBARRIER_INVAL(mb[i]);
}

// ---------------------------------------------------------------------------
// Small fp32 SIMT GEMM (tiny final layer N=2)
// ---------------------------------------------------------------------------
#define BM 128
#define BN 64
#define BK 16

template <int ACT>
__global__ void __launch_bounds__(256)
gemm_kernel(const float* __restrict__ A, const float* __restrict__ W,
            const float* __restrict__ bias, float* __restrict__ C,
            int M, int N, int K)
{
    __shared__ float As[BK][BM + 1];
    __shared__ float Ws[BK][BN];

    const int tid  = threadIdx.x;
    const int bm   = blockIdx.y * BM;
    const int bn   = blockIdx.x * BN;
    const int tx   = tid & 15;
    const int ty   = tid >> 4;
    const int arow = tid >> 2;
    const int acol = (tid & 3) * 4;
    const int wrow = tid >> 4;
    const int wcol = (tid & 15) * 4;

    float acc[8][4];
#pragma unroll
    for (int i = 0; i < 8; i++)
#pragma unroll
        for (int j = 0; j < 4; j++) acc[i][j] = 0.f;

    for (int k0 = 0; k0 < K; k0 += BK) {
#pragma unroll
        for (int half = 0; half < 2; half++) {
            int m = bm + arow + half * 64;
            float4 v = make_float4(0.f, 0.f, 0.f, 0.f);
            if (m < M)
                v = *(const float4*)(A + (size_t)m * K + k0 + acol);
            As[acol + 0][arow + half * 64] = v.x;
            As[acol + 1][arow + half * 64] = v.y;
            As[acol + 2][arow + half * 64] = v.z;
            As[acol + 3][arow + half * 64] = v.w;
        }
        {
            int kk = k0 + wrow;
            int n  = bn + wcol;
#pragma unroll
            for (int j = 0; j < 4; j++)
                Ws[wrow][wcol + j] = (n + j < N) ? W[(size_t)kk * N + n + j] : 0.f;
        }
        __syncthreads();

#pragma unroll
        for (int k = 0; k < BK; k++) {
            float ra[8];
#pragma unroll
            for (int i = 0; i < 8; i++) ra[i] = As[k][ty * 8 + i];
            float rb[4];
#pragma unroll
            for (int j = 0; j < 4; j++) rb[j] = Ws[k][tx * 4 + j];
#pragma unroll
            for (int i = 0; i < 8; i++)
#pragma unroll
                for (int j = 0; j < 4; j++)
                    acc[i][j] = fmaf(ra[i], rb[j], acc[i][j]);
        }
        __syncthreads();
    }

#pragma unroll
    for (int i = 0; i < 8; i++) {
        int m = bm + ty * 8 + i;
        if (m >= M) continue;
#pragma unroll
        for (int j = 0; j < 4; j++) {
            int n = bn + tx * 4 + j;
            if (n >= N) continue;
            float v = acc[i][j];
            if (bias) v += bias[n];
            if (ACT == 1) v = fmaxf(v, 0.f);
            C[(size_t)m * N + n] = v;
        }
    }
}

// ---------------------------------------------------------------------------
// Causal depthwise conv (DCONV=4) + bias + SiLU over the xBC slice of zxbcdt.
// ---------------------------------------------------------------------------
__global__ void conv_silu_kernel(const float* __restrict__ zx,
                                 const float* __restrict__ conv_w,
                                 const float* __restrict__ conv_b,
                                 float* __restrict__ xbc)
{
    int c = blockIdx.x * blockDim.x + threadIdx.x;
    int b = blockIdx.y;
    if (c >= CONV_DIM) return;

    float w0 = conv_w[c * 4 + 0], w1 = conv_w[c * 4 + 1];
    float w2 = conv_w[c * 4 + 2], w3 = conv_w[c * 4 + 3];
    float bb = conv_b[c];

    const float* src = zx + (size_t)b * SEQL * DPROJ + D_INNER + c;
    float v[SEQL];
#pragma unroll
    for (int l = 0; l < SEQL; l++) v[l] = src[(size_t)l * DPROJ];

#pragma unroll
    for (int l = 0; l < SEQL; l++) {
        float s = bb + v[l] * w3;
        if (l >= 1) s += v[l - 1] * w2;
        if (l >= 2) s += v[l - 2] * w1;
        if (l >= 3) s += v[l - 3] * w0;
        s = s / (1.f + expf(-s));   // silu
        xbc[((size_t)b * SEQL + l) * CONV_DIM + c] = s;
    }
}

// ---------------------------------------------------------------------------
// dt = softplus(dt_raw + dt_bias); dA = exp(-exp(A_log) * dt)
// ---------------------------------------------------------------------------
__global__ void dt_kernel(const float* __restrict__ zx,
                          const float* __restrict__ dt_bias,
                          const float* __restrict__ A_log,
                          float* __restrict__ dtb, float* __restrict__ dAb)
{
    int i = blockIdx.x * blockDim.x + threadIdx.x;
    if (i >= ROWS * NHEADS) return;
    int row = i >> 5, h = i & 31;
    float x = zx[(size_t)row * DPROJ + (D_INNER + CONV_DIM) + h] + dt_bias[h];
    float dt = (x > 20.f) ? x : log1pf(expf(x));
    float dA = expf(-expf(A_log[h]) * dt);
    dtb[i] = dt;
    dAb[i] = dA;
}

// ---------------------------------------------------------------------------
// SSM scan: one CTA per (batch, head). State h[64][128] in registers.
// ---------------------------------------------------------------------------
__global__ void __launch_bounds__(256)
scan_kernel(const float* __restrict__ xbc,
            const float* __restrict__ dtb, const float* __restrict__ dAb,
            const float* __restrict__ Dp, float* __restrict__ y)
{
    const int b = blockIdx.x;
    const int h = blockIdx.y;
    const int t = threadIdx.x;
    const int p = t >> 2;
    const int q = t & 3;

    __shared__ float Bsh[DSTATE];
    __shared__ float Csh[DSTATE];
    __shared__ float xsh[HEADDIM];
    __shared__ float sc[2];

    float st[32];
#pragma unroll
    for (int i = 0; i < 32; i++) st[i] = 0.f;
    const float Dh = Dp[h];

    for (int l = 0; l < SEQL; l++) {
        const int row = b * SEQL + l;
        const float* base = xbc + (size_t)row * CONV_DIM;
        if (t < 128) Bsh[t] = base[D_INNER + t];
        else         Csh[t - 128] = base[D_INNER + DSTATE + (t - 128)];
        if (t < HEADDIM) xsh[t] = base[h * HEADDIM + t];
        if (t == 0) { sc[0] = dAb[row * NHEADS + h]; sc[1] = dtb[row * NHEADS + h]; }
        __syncthreads();

        const float xv   = xsh[p];
        const float coef = sc[1] * xv;
        const float dAv  = sc[0];
        float part = 0.f;
#pragma unroll
        for (int i = 0; i < 32; i++) {
            const int s = q + 4 * i;
            st[i] = fmaf(dAv, st[i], coef * Bsh[s]);
            part  = fmaf(st[i], Csh[s], part);
        }
        part += __shfl_down_sync(0xffffffffu, part, 2);
        part += __shfl_down_sync(0xffffffffu, part, 1);
        if (q == 0)
            y[(size_t)row * D_INNER + h * HEADDIM + p] = part + xv * Dh;
        __syncthreads();
    }
}

// ---------------------------------------------------------------------------
// y = y * silu(z); y *= rsqrt(mean(y^2)+1e-5) * norm_w; emit split tiles
// (K = D_INNER = 2048, kshift 11). One CTA per row, thread t owns 8 contig.
// ---------------------------------------------------------------------------
__global__ void __launch_bounds__(256)
gated_rmsnorm_split_kernel(const float* __restrict__ ybuf,
                           const float* __restrict__ zx,
                           const float* __restrict__ norm_w,
                           __nv_bfloat16* __restrict__ hi,
                           __nv_bfloat16* __restrict__ lo)
{
    const size_t row = blockIdx.x;
    const int t = threadIdx.x;
    const int d0 = t * 8;
    const float* yb = ybuf + row * D_INNER;
    const float* zb = zx   + row * DPROJ;

    float v[8];
    float ss = 0.f;
#pragma unroll
    for (int j = 0; j < 8; j += 4) {
        float4 yv = *(const float4*)(yb + d0 + j);
        float4 zv = *(const float4*)(zb + d0 + j);
        v[j + 0] = yv.x * (zv.x / (1.f + expf(-zv.x)));
        v[j + 1] = yv.y * (zv.y / (1.f + expf(-zv.y)));
        v[j + 2] = yv.z * (zv.z / (1.f + expf(-zv.z)));
        v[j + 3] = yv.w * (zv.w / (1.f + expf(-zv.w)));
        ss = fmaf(v[j+0], v[j+0], ss); ss = fmaf(v[j+1], v[j+1], ss);
        ss = fmaf(v[j+2], v[j+2], ss); ss = fmaf(v[j+3], v[j+3], ss);
    }
#pragma unroll
    for (int o = 16; o > 0; o >>= 1)
        ss += __shfl_down_sync(0xffffffffu, ss, o);

    __shared__ float red[8];
    __shared__ float s_scale;
    if ((t & 31) == 0) red[t >> 5] = ss;
    __syncthreads();
    if (t == 0) {
        float s = 0.f;
        for (int i = 0; i < 8; i++) s += red[i];
        s_scale = rsqrtf(s / (float)D_INNER + 1e-5f);
    }
    __syncthreads();
    const float scale = s_scale;

#pragma unroll
    for (int j = 0; j < 8; j += 2) {
        int d = d0 + j;
        float v0 = v[j]     * scale * norm_w[d];
        float v1 = v[j + 1] * scale * norm_w[d + 1];
        split_store(hi, lo, tile_off(row, d, D_INNER >> 6), v0, v1);
    }
}

// ---------------------------------------------------------------------------
// Host-side orchestration
// ---------------------------------------------------------------------------
struct MambaW {
    const float *in_proj, *conv_w, *conv_b, *dt_bias, *A_log, *D, *norm_w, *out_proj;
};

extern "C" void kernel_launch(void* const* d_in, const int* in_sizes, int n_in,
                              void* d_out, int out_size)
{
    const float* x      = (const float*)d_in[0];
    const float* w_in1  = (const float*)d_in[1];
    const float* b_in1  = (const float*)d_in[2];
    const float* w_in2  = (const float*)d_in[3];
    const float* b_in2  = (const float*)d_in[4];
    MambaW m1 = { (const float*)d_in[5],  (const float*)d_in[6],  (const float*)d_in[7],
                  (const float*)d_in[8],  (const float*)d_in[9],  (const float*)d_in[10],
                  (const float*)d_in[11], (const float*)d_in[12] };
    MambaW m2 = { (const float*)d_in[13], (const float*)d_in[14], (const float*)d_in[15],
                  (const float*)d_in[16], (const float*)d_in[17], (const float*)d_in[18],
                  (const float*)d_in[19], (const float*)d_in[20] };
    const float* w_out1 = (const float*)d_in[21];
    const float* b_out1 = (const float*)d_in[22];
    const float* w_out2 = (const float*)d_in[23];
    const float* b_out2 = (const float*)d_in[24];
    float* out = (float*)d_out;

    cudaFuncSetAttribute(tc_gemm_kernel<0, 0>,
                         cudaFuncAttributeMaxDynamicSharedMemorySize, TCG_SMEM);
    cudaFuncSetAttribute(tc_gemm_kernel<0, 1>,
                         cudaFuncAttributeMaxDynamicSharedMemorySize, TCG_SMEM);
    cudaFuncSetAttribute(tc_gemm_kernel<1, 0>,
                         cudaFuncAttributeMaxDynamicSharedMemorySize, TCG_SMEM);
    cudaFuncSetAttribute(tc_gemm_kernel<1, 1>,
                         cudaFuncAttributeMaxDynamicSharedMemorySize, TCG_SMEM);

    float *a, *zx, *xbc, *dtb, *dAb, *ybuf;
    __nv_bfloat16 *whi, *wlo, *p1h, *p1l, *p2h, *p2l;
    cudaGetSymbolAddress((void**)&a,    g_a);
    cudaGetSymbolAddress((void**)&zx,   g_zx);
    cudaGetSymbolAddress((void**)&xbc,  g_xbc);
    cudaGetSymbolAddress((void**)&dtb,  g_dt);
    cudaGetSymbolAddress((void**)&dAb,  g_dA);
    cudaGetSymbolAddress((void**)&ybuf, g_y);
    cudaGetSymbolAddress((void**)&whi,  g_whi);
    cudaGetSymbolAddress((void**)&wlo,  g_wlo);
    cudaGetSymbolAddress((void**)&p1h,  g_p1hi);
    cudaGetSymbolAddress((void**)&p1l,  g_p1lo);
    cudaGetSymbolAddress((void**)&p2h,  g_p2hi);
    cudaGetSymbolAddress((void**)&p2l,  g_p2lo);

    // ---- weight preprocessing
    auto tsp = [&](const float* W, size_t off, int K, int N, int Npad) {
        transpose_split_kernel<<<dim3(Npad / 32, K / 64), 256>>>(
            W, whi + off, wlo + off, K, N);
    };
    tsp(w_in1,       OFF_WIN1,    1024, 8192, 8192);
    tsp(w_in2,       OFF_WIN2,    8192, 8192, 8192);
    tsp(m1.in_proj,  OFF_M1_INP,  1024, DPROJ, 4480);
    tsp(m2.in_proj,  OFF_M2_INP,  1024, DPROJ, 4480);
    tsp(m1.out_proj, OFF_M1_OUTP, 2048, 1024, 1024);
    tsp(m2.out_proj, OFF_M2_OUTP, 2048, 1024, 1024);
    tsp(w_out1,      OFF_WOUT1,   8192, 1024, 1024);

    // ---- split x -> p1 (256 x 1024, kshift 10)
    split_a_kernel<<<(BATCH * 1024 / 4 + 255) / 256, 256>>>(x, p1h, p1l,
                                                            BATCH * 1024 / 4, 10);

    // ---- MLP in
    // a_tiles = relu(x @ w_in1 + b_in1), consumer K'=8192 (ksh 13) -> p2
    tc_gemm_kernel<1, 1><<<dim3(64, 2), 512, TCG_SMEM>>>(
        p1h, p1l, whi + OFF_WIN1, wlo + OFF_WIN1, b_in1,
        nullptr, p2h, p2l, 13, BATCH, 8192, 1024);
    // h_tiles = a @ w_in2 + b_in2, consumer K'=1024 (ksh 10) -> p1
    tc_gemm_kernel<0, 1><<<dim3(64, 2), 512, TCG_SMEM>>>(
        p2h, p2l, whi + OFF_WIN2, wlo + OFF_WIN2, b_in2,
        nullptr, p1h, p1l, 10, BATCH, 8192, 8192);

    // ---- 2x Mamba2 layers (h tiles live in p1 as (2048, 1024))
    const MambaW* layers[2] = { &m1, &m2 };
    const size_t inp_off[2]  = { OFF_M1_INP,  OFF_M2_INP };
    const size_t outp_off[2] = { OFF_M1_OUTP, OFF_M2_OUTP };
    for (int li = 0; li < 2; li++) {
        const MambaW& p = *layers[li];
        // zx = h @ in_proj (fp32 out)
        tc_gemm_kernel<0, 0><<<dim3(35, 16), 512, TCG_SMEM>>>(
            p1h, p1l, whi + inp_off[li], wlo + inp_off[li], nullptr,
            zx, nullptr, nullptr, 0, ROWS, DPROJ, 1024);
        conv_silu_kernel<<<dim3(CONV_DIM / 256, BATCH), 256>>>(zx, p.conv_w,
                                                               p.conv_b, xbc);
        dt_kernel<<<(ROWS * NHEADS) / 256, 256>>>(zx, p.dt_bias, p.A_log, dtb, dAb);
        scan_kernel<<<dim3(BATCH, NHEADS), 256>>>(xbc, dtb, dAb, p.D, ybuf);
        // gated rmsnorm -> y tiles (2048 x 2048, ksh 11) -> p2
        gated_rmsnorm_split_kernel<<<ROWS, 256>>>(ybuf, zx, p.norm_w, p2h, p2l);
        // h = y @ out_proj; consumer: inproj K'=1024 (li=0) or out1 K'=8192 (li=1)
        int ksh_next = (li == 0) ? 10 : 13;
        tc_gemm_kernel<0, 1><<<dim3(8, 16), 512, TCG_SMEM>>>(
            p2h, p2l, whi + outp_off[li], wlo + outp_off[li], nullptr,
            nullptr, p1h, p1l, ksh_next, ROWS, 1024, 2048);
    }

    // ---- MLP out: a = relu(h @ w_out1 + b_out1) fp32; out = a @ w_out2 + b_out2
    tc_gemm_kernel<1, 0><<<dim3(8, 2), 512, TCG_SMEM>>>(
        p1h, p1l, whi + OFF_WOUT1, wlo + OFF_WOUT1, b_out1,
        a, nullptr, nullptr, 0, BATCH, 1024, 8192);
    gemm_kernel<0><<<dim3(1, (BATCH + BM - 1) / BM), 256>>>(a, w_out2, b_out2, out,
                                                            BATCH, 2, 1024);
}

// round 9
// speedup vs baseline: 2.9115x; 1.0798x over previous
#include <cuda_runtime.h>
#include <cuda_bf16.h>
#include <cstdint>

// ---------------------------------------------------------------------------
// Problem dimensions (fixed by the reference)
// ---------------------------------------------------------------------------
#define BATCH    256
#define SEQL     8
#define HIDD     1024            // HID
#define D_INNER  2048
#define DSTATE   128
#define NHEADS   32
#define HEADDIM  64
#define CONV_DIM 2304            // D_INNER + 2*DSTATE
#define DPROJ    4384            // 2*D_INNER + 2*DSTATE + NHEADS
#define ROWS     (BATCH * SEQL)  // 2048

// ---------------------------------------------------------------------------
// Scratch (static device buffers; no allocation allowed in kernel_launch)
// ---------------------------------------------------------------------------
__device__ float g_a  [BATCH * 8192];     // fp32 intermediate (out1 output)
__device__ float g_zx [ROWS  * DPROJ];    // zxbcdt (2048 x 4384)
__device__ float g_y  [ROWS  * D_INNER];  // SSM output (2048 x 2048)

// Two ping-pong split-bf16 tiled activation buffers (max 2048x2048)
#define AMAX 4194304
__device__ __nv_bfloat16 g_p1hi[AMAX];
__device__ __nv_bfloat16 g_p1lo[AMAX];
__device__ __nv_bfloat16 g_p2hi[AMAX];
__device__ __nv_bfloat16 g_p2lo[AMAX];

// Split-bf16 tiled weights (tiles of 128 n-rows x 64 k-halves, SW128-swizzled,
// one (nb,kc) tile = 16KB contiguous). N padded to mult of 128.
#define OFF_WIN1     0ULL
#define OFF_WIN2     8388608ULL      // win1: 8192*1024
#define OFF_M1_INP   75497472ULL     // win2: 8192*8192
#define OFF_M2_INP   80084992ULL     // inproj: 4480*1024
#define OFF_M1_OUTP  84672512ULL
#define OFF_M2_OUTP  86769664ULL     // outproj: 1024*2048
#define OFF_WOUT1    88866816ULL
#define WT_TOTAL     97255424ULL     // + wout1: 1024*8192
__device__ __nv_bfloat16 g_whi[WT_TOTAL];
__device__ __nv_bfloat16 g_wlo[WT_TOTAL];

// ---------------------------------------------------------------------------
// PTX helpers
// ---------------------------------------------------------------------------
__device__ __forceinline__ uint32_t smem_u32(const void* p) {
    uint32_t a;
    asm("{ .reg .u64 t; cvta.to.shared.u64 t, %1; cvt.u32.u64 %0, t; }"
        : "=r"(a) : "l"(p));
    return a;
}

#define MBARRIER_INIT(addr, count) \
    asm volatile("mbarrier.init.shared.b64 [%0], %1;" \
                 :: "r"((uint32_t)(addr)), "r"((uint32_t)(count)) : "memory")
#define MBARRIER_INVAL(addr) \
    asm volatile("mbarrier.inval.shared.b64 [%0];" \
                 :: "r"((uint32_t)(addr)) : "memory")
#define MBARRIER_EXPECT_TX(addr, bytes) \
    asm volatile("mbarrier.arrive.expect_tx.shared.b64 _, [%0], %1;" \
                 :: "r"((uint32_t)(addr)), "r"((uint32_t)(bytes)) : "memory")

#define MBARRIER_WAIT_PARITY(addr, par) do {                                   \
    uint32_t _m = (uint32_t)(addr), _p = (uint32_t)(par), _d;                  \
    asm volatile(                                                              \
        "{\n\t.reg .pred p;\n\t"                                               \
        "mbarrier.try_wait.parity.acquire.cta.shared::cta.b64 p, [%1], %2;\n\t"\
        "selp.b32 %0, 1, 0, p;\n\t}"                                           \
        : "=r"(_d) : "r"(_m), "r"(_p) : "memory");                             \
    if (!_d) {                                                                 \
        asm volatile(                                                          \
            "{\n\t.reg .pred P1;\n\t"                                          \
            "WL_%=:\n\t"                                                       \
            "mbarrier.try_wait.parity.acquire.cta.shared::cta.b64 P1, [%0], %1, 0x989680;\n\t" \
            "@P1 bra.uni WD_%=;\n\t"                                           \
            "bra.uni WL_%=;\n\t"                                               \
            "WD_%=:\n\t}"                                                      \
            :: "r"(_m), "r"(_p) : "memory");                                   \
    }                                                                          \
} while (0)

__device__ __forceinline__ void bulk_g2s(uint32_t sdst, const void* gsrc,
                                         uint32_t bytes, uint32_t mbar) {
    asm volatile(
        "cp.async.bulk.shared::cluster.global.mbarrier::complete_tx::bytes "
        "[%0], [%1], %2, [%3];"
        :: "r"(sdst), "l"(gsrc), "r"(bytes), "r"(mbar) : "memory");
}

#define LDSM4(r, addr) \
    asm volatile("ldmatrix.sync.aligned.m8n8.x4.shared.b16 {%0,%1,%2,%3}, [%4];" \
                 : "=r"((r)[0]), "=r"((r)[1]), "=r"((r)[2]), "=r"((r)[3]) \
                 : "r"(addr))

#define MMA_BF16(ACCP, A0, A1, A2, A3, B0, B1)                              \
    asm volatile(                                                           \
        "mma.sync.aligned.m16n8k16.row.col.f32.bf16.bf16.f32 "              \
        "{%0,%1,%2,%3}, {%4,%5,%6,%7}, {%8,%9}, {%0,%1,%2,%3};\n"           \
        : "+f"((ACCP)[0]), "+f"((ACCP)[1]), "+f"((ACCP)[2]), "+f"((ACCP)[3])\
        : "r"(A0), "r"(A1), "r"(A2), "r"(A3), "r"(B0), "r"(B1))

// Split-tile address: element (row mr, col kk) of an (M,Kc) operand in
// 128x64 swizzled tiles; returns offset in halves. kk must be even.
__device__ __forceinline__ size_t tile_off(size_t mr, int kk, int kc_n) {
    int mb = (int)(mr >> 7), r = (int)(mr & 127);
    int kc = kk >> 6, kl = kk & 63;
    uint32_t off = (uint32_t)(r * 128 + kl * 2);
    uint32_t sw  = off ^ ((uint32_t)(r & 7) << 4);
    return (((size_t)mb * kc_n + kc) << 13) + (sw >> 1);
}

__device__ __forceinline__ void split_store(__nv_bfloat16* hi, __nv_bfloat16* lo,
                                            size_t base, float v0, float v1) {
    __nv_bfloat16 h0 = __float2bfloat16(v0);
    __nv_bfloat16 h1 = __float2bfloat16(v1);
    *(__nv_bfloat162*)(hi + base) = __halves2bfloat162(h0, h1);
    *(__nv_bfloat162*)(lo + base) = __halves2bfloat162(
        __float2bfloat16(v0 - __bfloat162float(h0)),
        __float2bfloat16(v1 - __bfloat162float(h1)));
}

// ---------------------------------------------------------------------------
// Weight preprocessing: W (K,N) fp32 -> hi/lo bf16 tiles (128n x 64k, SW128).
// One CTA per OUTPUT TILE (128 n x 64 k). 256 threads.
// Phase 1: coalesced float4 loads of W[64k x 128n] -> smem (stride 129).
// Phase 2: conflict-free column reads -> packed 16B uint4 stores, warp writes
// 512B contiguous regions of the 16KB tile.
// Grid: (Npad/128, K/64). n >= N zero-filled.
// ---------------------------------------------------------------------------
__global__ void __launch_bounds__(256)
transpose_split_kernel(const float* __restrict__ W,
                       __nv_bfloat16* __restrict__ Thi,
                       __nv_bfloat16* __restrict__ Tlo,
                       int K, int N)
{
    __shared__ float s[64][129];
    const int tid = threadIdx.x;
    const int nbase = blockIdx.x * 128;
    const int kbase = blockIdx.y * 64;

    // Phase 1: 64 rows x 128 cols = 2048 float4 loads, 8 per thread
#pragma unroll
    for (int i = 0; i < 8; i++) {
        int idx = tid + i * 256;           // 0..2047
        int kk  = idx >> 5;                // 0..63
        int nn  = (idx & 31) * 4;          // 0..124
        int n   = nbase + nn;
        float4 v = make_float4(0.f, 0.f, 0.f, 0.f);
        if (n < N)                          // N % 4 == 0 -> all-or-nothing
            v = *(const float4*)(W + (size_t)(kbase + kk) * N + n);
        s[kk][nn + 0] = v.x; s[kk][nn + 1] = v.y;
        s[kk][nn + 2] = v.z; s[kk][nn + 3] = v.w;
    }
    __syncthreads();

    const size_t tile_base =
        ((size_t)blockIdx.x * (size_t)(K >> 6) + (size_t)blockIdx.y) << 13;

    // Phase 2: 128 n-rows x 8 k-chunks (8 halves = 16B each), 4 per thread
#pragma unroll
    for (int i = 0; i < 4; i++) {
        int idx = tid + i * 256;           // 0..1023
        int n   = idx >> 3;                // 0..127
        int kc8 = (idx & 7) * 8;           // 0,8,..,56

        float v[8];
#pragma unroll
        for (int j = 0; j < 8; j++) v[j] = s[kc8 + j][n];

        uint32_t hw[4], lw[4];
#pragma unroll
        for (int j = 0; j < 4; j++) {
            __nv_bfloat16 h0 = __float2bfloat16(v[2 * j]);
            __nv_bfloat16 h1 = __float2bfloat16(v[2 * j + 1]);
            __nv_bfloat162 hp = __halves2bfloat162(h0, h1);
            __nv_bfloat162 lp = __halves2bfloat162(
                __float2bfloat16(v[2 * j]     - __bfloat162float(h0)),
                __float2bfloat16(v[2 * j + 1] - __bfloat162float(h1)));
            hw[j] = *(uint32_t*)&hp;
            lw[j] = *(uint32_t*)&lp;
        }
        uint32_t off = (uint32_t)(n * 128 + kc8 * 2);
        uint32_t sw  = off ^ ((uint32_t)(n & 7) << 4);
        uint4* dh = (uint4*)(Thi + tile_base + (sw >> 1));
        uint4* dl = (uint4*)(Tlo + tile_base + (sw >> 1));
        *dh = make_uint4(hw[0], hw[1], hw[2], hw[3]);
        *dl = make_uint4(lw[0], lw[1], lw[2], lw[3]);
    }
}

// ---------------------------------------------------------------------------
// Activation split: A (M,K) fp32 -> hi/lo bf16 tiles. K = 1<<kshift.
// ---------------------------------------------------------------------------
__global__ void __launch_bounds__(256)
split_a_kernel(const float* __restrict__ A,
               __nv_bfloat16* __restrict__ hi, __nv_bfloat16* __restrict__ lo,
               int n4, int kshift)
{
    int idx = blockIdx.x * 256 + threadIdx.x;
    if (idx >= n4) return;
    const int K = 1 << kshift;
    int idx4 = idx << 2;
    size_t m = (size_t)(idx4 >> kshift);
    int k = idx4 & (K - 1);
    float4 v = ((const float4*)A)[idx];
    split_store(hi, lo, tile_off(m, k,     K >> 6), v.x, v.y);
    split_store(hi, lo, tile_off(m, k + 2, K >> 6), v.z, v.w);
}

// ---------------------------------------------------------------------------
// Split-bf16 GEMM on mma.sync.m16n8k16, 3-stage bulk-copy pipeline.
// (at the sm_103a legacy-HMMA ceiling; see round-8 post-mortem)
// OUT=0: C fp32 (M,N).  OUT=1: split tiles for consumer with K' = 1<<ksh.
// ---------------------------------------------------------------------------
#define TILE_BYTES  16384
#define STAGE_BYTES (4 * TILE_BYTES)          // Ah, Al, Bh, Bl
#define NSTAGE      3
#define TCG_SMEM    (NSTAGE * STAGE_BYTES)    // 196608

template <int ACT, int OUT>
__global__ void __launch_bounds__(512)
tc_gemm_kernel(const __nv_bfloat16* __restrict__ Ahi,
               const __nv_bfloat16* __restrict__ Alo,
               const __nv_bfloat16* __restrict__ Bhi,
               const __nv_bfloat16* __restrict__ Blo,
               const float* __restrict__ bias, float* __restrict__ C,
               __nv_bfloat16* __restrict__ Chi, __nv_bfloat16* __restrict__ Clo,
               int ksh, int M, int N, int K)
{
    extern __shared__ char dsm[];
    __shared__ uint64_t mbar[NSTAGE];

    const uint32_t sbase = smem_u32(dsm);
    uint32_t mb[NSTAGE];
#pragma unroll
    for (int i = 0; i < NSTAGE; i++) mb[i] = smem_u32(&mbar[i]);

    const int tid  = threadIdx.x;
    const int lane = tid & 31;
    const int warp = tid >> 5;
    const int wm   = warp >> 2;
    const int wn   = warp & 3;
    const int bm   = blockIdx.y * 128;
    const int bn   = blockIdx.x * 128;
    const int g    = lane >> 2;
    const int q    = lane & 3;

    const int ar = lane & 15;
    const int ac = (lane >> 4) * 16;
    const int br = (lane & 7) + ((lane >> 4) << 3);
    const int bc = ((lane >> 3) & 1) * 16;
    const uint32_t a_xor = (uint32_t)(ar & 7) << 4;
    const uint32_t b_xor = (uint32_t)(br & 7) << 4;
    uint32_t a_row_off[2], b_row_off[2];
#pragma unroll
    for (int mi = 0; mi < 2; mi++)
        a_row_off[mi] = (uint32_t)((wm * 32 + mi * 16 + ar) * 128);
#pragma unroll
    for (int nj = 0; nj < 2; nj++)
        b_row_off[nj] = (uint32_t)((wn * 32 + nj * 16 + br) * 128);

    if (tid == 0)
#pragma unroll
        for (int i = 0; i < NSTAGE; i++) MBARRIER_INIT(mb[i], 1);
    __syncthreads();

    const int kcn = K >> 6;
    const size_t a_tile0 = (size_t)blockIdx.y * kcn;
    const size_t b_tile0 = (size_t)blockIdx.x * kcn;

    auto fill = [&](int c, int s) {            // tid 0 only
        MBARRIER_EXPECT_TX(mb[s], 4 * TILE_BYTES);
        const uint32_t st = sbase + s * STAGE_BYTES;
        const size_t ao = (a_tile0 + c) << 13;
        const size_t bo = (b_tile0 + c) << 13;
        bulk_g2s(st,                   Ahi + ao, TILE_BYTES, mb[s]);
        bulk_g2s(st + TILE_BYTES,      Alo + ao, TILE_BYTES, mb[s]);
        bulk_g2s(st + 2 * TILE_BYTES,  Bhi + bo, TILE_BYTES, mb[s]);
        bulk_g2s(st + 3 * TILE_BYTES,  Blo + bo, TILE_BYTES, mb[s]);
    };

    float acc[2][4][4];
#pragma unroll
    for (int mi = 0; mi < 2; mi++)
#pragma unroll
        for (int ni = 0; ni < 4; ni++)
#pragma unroll
            for (int f = 0; f < 4; f++) acc[mi][ni][f] = 0.f;

    if (tid == 0)
        for (int c = 0; c < NSTAGE && c < kcn; c++) fill(c, c);

    int ph[NSTAGE] = {0, 0, 0};
    int s = 0;
    for (int c = 0; c < kcn; c++) {
        MBARRIER_WAIT_PARITY(mb[s], ph[s]);
        ph[s] ^= 1;

        const uint32_t st = sbase + s * STAGE_BYTES;
        const uint32_t Ah = st;
        const uint32_t Al = st + TILE_BYTES;
        const uint32_t Bh = st + 2 * TILE_BYTES;
        const uint32_t Bl = st + 3 * TILE_BYTES;

#pragma unroll
        for (int ks = 0; ks < 4; ks++) {
            const uint32_t kb = ks * 32;
            uint32_t ah[2][4], al[2][4];
#pragma unroll
            for (int mi = 0; mi < 2; mi++) {
                uint32_t off = a_row_off[mi] + ((kb + ac) ^ a_xor);
                LDSM4(ah[mi], Ah + off);
                LDSM4(al[mi], Al + off);
            }
            uint32_t bh[2][4], bl[2][4];
#pragma unroll
            for (int nj = 0; nj < 2; nj++) {
                uint32_t off = b_row_off[nj] + ((kb + bc) ^ b_xor);
                LDSM4(bh[nj], Bh + off);
                LDSM4(bl[nj], Bl + off);
            }
#pragma unroll
            for (int mi = 0; mi < 2; mi++)
#pragma unroll
                for (int nj = 0; nj < 2; nj++)
#pragma unroll
                    for (int hf = 0; hf < 2; hf++) {
                        float* ap = acc[mi][nj * 2 + hf];
                        MMA_BF16(ap, ah[mi][0], ah[mi][1], ah[mi][2], ah[mi][3],
                                 bh[nj][hf * 2], bh[nj][hf * 2 + 1]);
                        MMA_BF16(ap, ah[mi][0], ah[mi][1], ah[mi][2], ah[mi][3],
                                 bl[nj][hf * 2], bl[nj][hf * 2 + 1]);
                        MMA_BF16(ap, al[mi][0], al[mi][1], al[mi][2], al[mi][3],
                                 bh[nj][hf * 2], bh[nj][hf * 2 + 1]);
                    }
        }
        __syncthreads();                       // all reads of stage s done
        if (tid == 0 && c + NSTAGE < kcn) fill(c + NSTAGE, s);
        s = (s == NSTAGE - 1) ? 0 : s + 1;
    }

    // ---- epilogue (N even everywhere -> pairwise guard ok)
    const int Kc = 1 << ksh;
#pragma unroll
    for (int mi = 0; mi < 2; mi++) {
        const int m0 = bm + wm * 32 + mi * 16;
#pragma unroll
        for (int ni = 0; ni < 4; ni++) {
            const int n = bn + wn * 32 + ni * 8 + 2 * q;
            if (n >= N) continue;
            float b0 = bias ? bias[n]     : 0.f;
            float b1 = bias ? bias[n + 1] : 0.f;
#pragma unroll
            for (int hf = 0; hf < 2; hf++) {
                const int m = m0 + g + hf * 8;
                float v0 = acc[mi][ni][hf * 2 + 0] + b0;
                float v1 = acc[mi][ni][hf * 2 + 1] + b1;
                if (ACT == 1) { v0 = fmaxf(v0, 0.f); v1 = fmaxf(v1, 0.f); }
                if (OUT == 0) {
                    *(float2*)(C + (size_t)m * N + n) = make_float2(v0, v1);
                } else {
                    size_t flat = (size_t)m * N + n;
                    size_t mr = flat >> ksh;
                    int kk = (int)(flat & (Kc - 1));
                    split_store(Chi, Clo, tile_off(mr, kk, Kc >> 6), v0, v1);
                }
            }
        }
    }

    __syncthreads();
    if (tid == 0)
#pragma unroll
        for (int i = 0; i < NSTAGE; i++) MBARRIER_INVAL(mb[i]);
}

// ---------------------------------------------------------------------------
// Fused conv+SiLU+dt+scan. One CTA per (batch, head), 256 threads.
// Stages conv(B,C) for all 8 steps, conv(x) for this head's 64 channels,
// and dt/dA in smem; then a barrier-free register scan.
// ---------------------------------------------------------------------------
__global__ void __launch_bounds__(256)
fused_scan_kernel(const float* __restrict__ zx,
                  const float* __restrict__ conv_w,
                  const float* __restrict__ conv_b,
                  const float* __restrict__ dt_bias,
                  const float* __restrict__ A_log,
                  const float* __restrict__ Dp,
                  float* __restrict__ y)
{
    const int b = blockIdx.x;
    const int h = blockIdx.y;
    const int t = threadIdx.x;

    __shared__ float Bsh[SEQL][DSTATE];     // 4 KB
    __shared__ float Csh[SEQL][DSTATE];     // 4 KB
    __shared__ float xsh[SEQL][HEADDIM];    // 2 KB
    __shared__ float dts[SEQL], dAs[SEQL];

    const float* zrow = zx + (size_t)b * SEQL * DPROJ;

    // conv+silu for B/C channels: thread t -> channel (2048 + t) of xBC
    {
        const int ch  = 2048 + t;              // xBC channel
        const int src = D_INNER + ch;          // zx column
        const float w0 = conv_w[ch * 4 + 0], w1 = conv_w[ch * 4 + 1];
        const float w2 = conv_w[ch * 4 + 2], w3 = conv_w[ch * 4 + 3];
        const float bb = conv_b[ch];
        float v[SEQL];
#pragma unroll
        for (int l = 0; l < SEQL; l++) v[l] = zrow[(size_t)l * DPROJ + src];
#pragma unroll
        for (int l = 0; l < SEQL; l++) {
            float sv = bb + v[l] * w3;
            if (l >= 1) sv += v[l - 1] * w2;
            if (l >= 2) sv += v[l - 2] * w1;
            if (l >= 3) sv += v[l - 3] * w0;
            sv = sv / (1.f + expf(-sv));
            if (t < 128) Bsh[l][t] = sv;
            else         Csh[l][t - 128] = sv;
        }
    }
    // conv+silu for this head's x channels: threads 0..63 -> channel h*64+t
    if (t < HEADDIM) {
        const int ch  = h * HEADDIM + t;
        const int src = D_INNER + ch;
        const float w0 = conv_w[ch * 4 + 0], w1 = conv_w[ch * 4 + 1];
        const float w2 = conv_w[ch * 4 + 2], w3 = conv_w[ch * 4 + 3];
        const float bb = conv_b[ch];
        float v[SEQL];
#pragma unroll
        for (int l = 0; l < SEQL; l++) v[l] = zrow[(size_t)l * DPROJ + src];
#pragma unroll
        for (int l = 0; l < SEQL; l++) {
            float sv = bb + v[l] * w3;
            if (l >= 1) sv += v[l - 1] * w2;
            if (l >= 2) sv += v[l - 2] * w1;
            if (l >= 3) sv += v[l - 3] * w0;
            xsh[l][t] = sv / (1.f + expf(-sv));
        }
    }
    // dt/dA: threads 64..71 -> timestep l = t-64
    if (t >= 64 && t < 64 + SEQL) {
        const int l = t - 64;
        float xr = zrow[(size_t)l * DPROJ + (D_INNER + CONV_DIM) + h] + dt_bias[h];
        float dt = (xr > 20.f) ? xr : log1pf(expf(xr));
        dts[l] = dt;
        dAs[l] = expf(-expf(A_log[h]) * dt);
    }
    __syncthreads();

    // register scan: thread owns p = t>>2, s-subset q + 4i
    const int p = t >> 2;
    const int q = t & 3;
    float st[32];
#pragma unroll
    for (int i = 0; i < 32; i++) st[i] = 0.f;
    const float Dh = Dp[h];

#pragma unroll
    for (int l = 0; l < SEQL; l++) {
        const float xv   = xsh[l][p];
        const float coef = dts[l] * xv;
        const float dAv  = dAs[l];
        float part = 0.f;
#pragma unroll
        for (int i = 0; i < 32; i++) {
            const int sidx = q + 4 * i;
            st[i] = fmaf(dAv, st[i], coef * Bsh[l][sidx]);
            part  = fmaf(st[i], Csh[l][sidx], part);
        }
        part += __shfl_down_sync(0xffffffffu, part, 2);
        part += __shfl_down_sync(0xffffffffu, part, 1);
        if (q == 0)
            y[((size_t)b * SEQL + l) * D_INNER + h * HEADDIM + p] = part + xv * Dh;
    }
}

// ---------------------------------------------------------------------------
// y = y * silu(z); y *= rsqrt(mean(y^2)+1e-5) * norm_w; emit split tiles
// (K = D_INNER = 2048). One CTA per row, thread t owns 8 contiguous cols.
// ---------------------------------------------------------------------------
__global__ void __launch_bounds__(256)
gated_rmsnorm_split_kernel(const float* __restrict__ ybuf,
                           const float* __restrict__ zx,
                           const float* __restrict__ norm_w,
                           __nv_bfloat16* __restrict__ hi,
                           __nv_bfloat16* __restrict__ lo)
{
    const size_t row = blockIdx.x;
    const int t = threadIdx.x;
    const int d0 = t * 8;
    const float* yb = ybuf + row * D_INNER;
    const float* zb = zx   + row * DPROJ;

    float v[8];
    float ss = 0.f;
#pragma unroll
    for (int j = 0; j < 8; j += 4) {
        float4 yv = *(const float4*)(yb + d0 + j);
        float4 zv = *(const float4*)(zb + d0 + j);
        v[j + 0] = yv.x * (zv.x / (1.f + expf(-zv.x)));
        v[j + 1] = yv.y * (zv.y / (1.f + expf(-zv.y)));
        v[j + 2] = yv.z * (zv.z / (1.f + expf(-zv.z)));
        v[j + 3] = yv.w * (zv.w / (1.f + expf(-zv.w)));
        ss = fmaf(v[j+0], v[j+0], ss); ss = fmaf(v[j+1], v[j+1], ss);
        ss = fmaf(v[j+2], v[j+2], ss); ss = fmaf(v[j+3], v[j+3], ss);
    }
#pragma unroll
    for (int o = 16; o > 0; o >>= 1)
        ss += __shfl_down_sync(0xffffffffu, ss, o);

    __shared__ float red[8];
    __shared__ float s_scale;
    if ((t & 31) == 0) red[t >> 5] = ss;
    __syncthreads();
    if (t == 0) {
        float s = 0.f;
        for (int i = 0; i < 8; i++) s += red[i];
        s_scale = rsqrtf(s / (float)D_INNER + 1e-5f);
    }
    __syncthreads();
    const float scale = s_scale;

#pragma unroll
    for (int j = 0; j < 8; j += 2) {
        int d = d0 + j;
        float v0 = v[j]     * scale * norm_w[d];
        float v1 = v[j + 1] * scale * norm_w[d + 1];
        split_store(hi, lo, tile_off(row, d, D_INNER >> 6), v0, v1);
    }
}

// ---------------------------------------------------------------------------
// Final tiny layer: out[m][j] = sum_k A[m][k] * W[k][j] + b[j], N=2, K=1024.
// One CTA per m, 256 threads x float4.
// ---------------------------------------------------------------------------
__global__ void __launch_bounds__(256)
final_kernel(const float* __restrict__ A, const float* __restrict__ W,
             const float* __restrict__ bias, float* __restrict__ out)
{
    const int m = blockIdx.x;
    const int t = threadIdx.x;
    float4 a = ((const float4*)(A + (size_t)m * 1024))[t];
    const float4 w0 = ((const float4*)W)[2 * t];      // k=4t..4t+1 cols 0,1
    const float4 w1 = ((const float4*)W)[2 * t + 1];  // k=4t+2..4t+3
    float s0 = a.x * w0.x + a.y * w0.z + a.z * w1.x + a.w * w1.z;
    float s1 = a.x * w0.y + a.y * w0.w + a.z * w1.y + a.w * w1.w;
#pragma unroll
    for (int o = 16; o > 0; o >>= 1) {
        s0 += __shfl_down_sync(0xffffffffu, s0, o);
        s1 += __shfl_down_sync(0xffffffffu, s1, o);
    }
    __shared__ float r0[8], r1[8];
    if ((t & 31) == 0) { r0[t >> 5] = s0; r1[t >> 5] = s1; }
    __syncthreads();
    if (t == 0) {
        float a0 = 0.f, a1 = 0.f;
        for (int i = 0; i < 8; i++) { a0 += r0[i]; a1 += r1[i]; }
        out[m * 2 + 0] = a0 + bias[0];
        out[m * 2 + 1] = a1 + bias[1];
    }
}

// ---------------------------------------------------------------------------
// Host-side orchestration
// ---------------------------------------------------------------------------
struct MambaW {
    const float *in_proj, *conv_w, *conv_b, *dt_bias, *A_log, *D, *norm_w, *out_proj;
};

extern "C" void kernel_launch(void* const* d_in, const int* in_sizes, int n_in,
                              void* d_out, int out_size)
{
    const float* x      = (const float*)d_in[0];
    const float* w_in1  = (const float*)d_in[1];
    const float* b_in1  = (const float*)d_in[2];
    const float* w_in2  = (const float*)d_in[3];
    const float* b_in2  = (const float*)d_in[4];
    MambaW m1 = { (const float*)d_in[5],  (const float*)d_in[6],  (const float*)d_in[7],
                  (const float*)d_in[8],  (const float*)d_in[9],  (const float*)d_in[10],
                  (const float*)d_in[11], (const float*)d_in[12] };
    MambaW m2 = { (const float*)d_in[13], (const float*)d_in[14], (const float*)d_in[15],
                  (const float*)d_in[16], (const float*)d_in[17], (const float*)d_in[18],
                  (const float*)d_in[19], (const float*)d_in[20] };
    const float* w_out1 = (const float*)d_in[21];
    const float* b_out1 = (const float*)d_in[22];
    const float* w_out2 = (const float*)d_in[23];
    const float* b_out2 = (const float*)d_in[24];
    float* out = (float*)d_out;

    cudaFuncSetAttribute(tc_gemm_kernel<0, 0>,
                         cudaFuncAttributeMaxDynamicSharedMemorySize, TCG_SMEM);
    cudaFuncSetAttribute(tc_gemm_kernel<0, 1>,
                         cudaFuncAttributeMaxDynamicSharedMemorySize, TCG_SMEM);
    cudaFuncSetAttribute(tc_gemm_kernel<1, 0>,
                         cudaFuncAttributeMaxDynamicSharedMemorySize, TCG_SMEM);
    cudaFuncSetAttribute(tc_gemm_kernel<1, 1>,
                         cudaFuncAttributeMaxDynamicSharedMemorySize, TCG_SMEM);

    float *a, *zx, *ybuf;
    __nv_bfloat16 *whi, *wlo, *p1h, *p1l, *p2h, *p2l;
    cudaGetSymbolAddress((void**)&a,    g_a);
    cudaGetSymbolAddress((void**)&zx,   g_zx);
    cudaGetSymbolAddress((void**)&ybuf, g_y);
    cudaGetSymbolAddress((void**)&whi,  g_whi);
    cudaGetSymbolAddress((void**)&wlo,  g_wlo);
    cudaGetSymbolAddress((void**)&p1h,  g_p1hi);
    cudaGetSymbolAddress((void**)&p1l,  g_p1lo);
    cudaGetSymbolAddress((void**)&p2h,  g_p2hi);
    cudaGetSymbolAddress((void**)&p2l,  g_p2lo);

    // ---- weight preprocessing (one CTA per 128x64 output tile)
    auto tsp = [&](const float* W, size_t off, int K, int N, int Npad) {
        transpose_split_kernel<<<dim3(Npad / 128, K / 64), 256>>>(
            W, whi + off, wlo + off, K, N);
    };
    tsp(w_in1,       OFF_WIN1,    1024, 8192, 8192);
    tsp(w_in2,       OFF_WIN2,    8192, 8192, 8192);
    tsp(m1.in_proj,  OFF_M1_INP,  1024, DPROJ, 4480);
    tsp(m2.in_proj,  OFF_M2_INP,  1024, DPROJ, 4480);
    tsp(m1.out_proj, OFF_M1_OUTP, 2048, 1024, 1024);
    tsp(m2.out_proj, OFF_M2_OUTP, 2048, 1024, 1024);
    tsp(w_out1,      OFF_WOUT1,   8192, 1024, 1024);

    // ---- split x -> p1 (256 x 1024, kshift 10)
    split_a_kernel<<<(BATCH * 1024 / 4 + 255) / 256, 256>>>(x, p1h, p1l,
                                                            BATCH * 1024 / 4, 10);

    // ---- MLP in
    tc_gemm_kernel<1, 1><<<dim3(64, 2), 512, TCG_SMEM>>>(
        p1h, p1l, whi + OFF_WIN1, wlo + OFF_WIN1, b_in1,
        nullptr, p2h, p2l, 13, BATCH, 8192, 1024);
    tc_gemm_kernel<0, 1><<<dim3(64, 2), 512, TCG_SMEM>>>(
        p2h, p2l, whi + OFF_WIN2, wlo + OFF_WIN2, b_in2,
        nullptr, p1h, p1l, 10, BATCH, 8192, 8192);

    // ---- 2x Mamba2 layers (h tiles live in p1 as (2048, 1024))
    const MambaW* layers[2] = { &m1, &m2 };
    const size_t inp_off[2]  = { OFF_M1_INP,  OFF_M2_INP };
    const size_t outp_off[2] = { OFF_M1_OUTP, OFF_M2_OUTP };
    for (int li = 0; li < 2; li++) {
        const MambaW& p = *layers[li];
        tc_gemm_kernel<0, 0><<<dim3(35, 16), 512, TCG_SMEM>>>(
            p1h, p1l, whi + inp_off[li], wlo + inp_off[li], nullptr,
            zx, nullptr, nullptr, 0, ROWS, DPROJ, 1024);
        fused_scan_kernel<<<dim3(BATCH, NHEADS), 256>>>(
            zx, p.conv_w, p.conv_b, p.dt_bias, p.A_log, p.D, ybuf);
        gated_rmsnorm_split_kernel<<<ROWS, 256>>>(ybuf, zx, p.norm_w, p2h, p2l);
        int ksh_next = (li == 0) ? 10 : 13;
        tc_gemm_kernel<0, 1><<<dim3(8, 16), 512, TCG_SMEM>>>(
            p2h, p2l, whi + outp_off[li], wlo + outp_off[li], nullptr,
            nullptr, p1h, p1l, ksh_next, ROWS, 1024, 2048);
    }

    // ---- MLP out
    tc_gemm_kernel<1, 0><<<dim3(8, 2), 512, TCG_SMEM>>>(
        p1h, p1l, whi + OFF_WOUT1, wlo + OFF_WOUT1, b_out1,
        a, nullptr, nullptr, 0, BATCH, 1024, 8192);
    final_kernel<<<BATCH, 256>>>(a, w_out2, b_out2, out);
}

// round 10
// speedup vs baseline: 3.3821x; 1.1617x over previous
#include <cuda_runtime.h>
#include <cuda_bf16.h>
#include <cstdint>

// ---------------------------------------------------------------------------
// Problem dimensions (fixed by the reference)
// ---------------------------------------------------------------------------
#define BATCH    256
#define SEQL     8
#define HIDD     1024            // HID
#define D_INNER  2048
#define DSTATE   128
#define NHEADS   32
#define HEADDIM  64
#define CONV_DIM 2304            // D_INNER + 2*DSTATE
#define DPROJ    4384            // 2*D_INNER + 2*DSTATE + NHEADS
#define ROWS     (BATCH * SEQL)  // 2048

// ---------------------------------------------------------------------------
// Scratch (static device buffers; no allocation allowed in kernel_launch)
// ---------------------------------------------------------------------------
__device__ float g_a   [BATCH * 8192];    // fp32 intermediate (out1 output)
__device__ float g_zx  [ROWS  * DPROJ];   // zxbcdt (2048 x 4384)
__device__ float g_y   [ROWS  * D_INNER]; // SSM output (2048 x 2048)
__device__ float g_part[8388608];         // split-K partials (max 4x256x8192)

// Two ping-pong split-bf16 tiled activation buffers (max 2048x2048)
#define AMAX 4194304
__device__ __nv_bfloat16 g_p1hi[AMAX];
__device__ __nv_bfloat16 g_p1lo[AMAX];
__device__ __nv_bfloat16 g_p2hi[AMAX];
__device__ __nv_bfloat16 g_p2lo[AMAX];

// Split-bf16 tiled weights. B tile = 64 k-rows x 128 n-cols, (K,N) layout,
// 256B per k-row, 16B chunks xor-swizzled by (k&7)<<4. One tile = 16KB
// contiguous; tile index = nb * (K/64) + kc. N padded to mult of 128.
#define OFF_WIN1     0ULL
#define OFF_WIN2     8388608ULL      // win1: 8192*1024
#define OFF_M1_INP   75497472ULL     // win2: 8192*8192
#define OFF_M2_INP   80084992ULL     // inproj: 4480*1024
#define OFF_M1_OUTP  84672512ULL
#define OFF_M2_OUTP  86769664ULL     // outproj: 1024*2048
#define OFF_WOUT1    88866816ULL
#define WT_TOTAL     97255424ULL     // + wout1: 1024*8192
__device__ __nv_bfloat16 g_whi[WT_TOTAL];
__device__ __nv_bfloat16 g_wlo[WT_TOTAL];

// ---------------------------------------------------------------------------
// PTX helpers
// ---------------------------------------------------------------------------
__device__ __forceinline__ uint32_t smem_u32(const void* p) {
    uint32_t a;
    asm("{ .reg .u64 t; cvta.to.shared.u64 t, %1; cvt.u32.u64 %0, t; }"
        : "=r"(a) : "l"(p));
    return a;
}

#define MBARRIER_INIT(addr, count) \
    asm volatile("mbarrier.init.shared.b64 [%0], %1;" \
                 :: "r"((uint32_t)(addr)), "r"((uint32_t)(count)) : "memory")
#define MBARRIER_INVAL(addr) \
    asm volatile("mbarrier.inval.shared.b64 [%0];" \
                 :: "r"((uint32_t)(addr)) : "memory")
#define MBARRIER_EXPECT_TX(addr, bytes) \
    asm volatile("mbarrier.arrive.expect_tx.shared.b64 _, [%0], %1;" \
                 :: "r"((uint32_t)(addr)), "r"((uint32_t)(bytes)) : "memory")

#define MBARRIER_WAIT_PARITY(addr, par) do {                                   \
    uint32_t _m = (uint32_t)(addr), _p = (uint32_t)(par), _d;                  \
    asm volatile(                                                              \
        "{\n\t.reg .pred p;\n\t"                                               \
        "mbarrier.try_wait.parity.acquire.cta.shared::cta.b64 p, [%1], %2;\n\t"\
        "selp.b32 %0, 1, 0, p;\n\t}"                                           \
        : "=r"(_d) : "r"(_m), "r"(_p) : "memory");                             \
    if (!_d) {                                                                 \
        asm volatile(                                                          \
            "{\n\t.reg .pred P1;\n\t"                                          \
            "WL_%=:\n\t"                                                       \
            "mbarrier.try_wait.parity.acquire.cta.shared::cta.b64 P1, [%0], %1, 0x989680;\n\t" \
            "@P1 bra.uni WD_%=;\n\t"                                           \
            "bra.uni WL_%=;\n\t"                                               \
            "WD_%=:\n\t}"                                                      \
            :: "r"(_m), "r"(_p) : "memory");                                   \
    }                                                                          \
} while (0)

__device__ __forceinline__ void bulk_g2s(uint32_t sdst, const void* gsrc,
                                         uint32_t bytes, uint32_t mbar) {
    asm volatile(
        "cp.async.bulk.shared::cluster.global.mbarrier::complete_tx::bytes "
        "[%0], [%1], %2, [%3];"
        :: "r"(sdst), "l"(gsrc), "r"(bytes), "r"(mbar) : "memory");
}

#define LDSM4(r, addr) \
    asm volatile("ldmatrix.sync.aligned.m8n8.x4.shared.b16 {%0,%1,%2,%3}, [%4];" \
                 : "=r"((r)[0]), "=r"((r)[1]), "=r"((r)[2]), "=r"((r)[3]) \
                 : "r"(addr))

#define LDSM4T(r, addr) \
    asm volatile("ldmatrix.sync.aligned.m8n8.x4.trans.shared.b16 {%0,%1,%2,%3}, [%4];" \
                 : "=r"((r)[0]), "=r"((r)[1]), "=r"((r)[2]), "=r"((r)[3]) \
                 : "r"(addr))

#define MMA_BF16(ACCP, A0, A1, A2, A3, B0, B1)                              \
    asm volatile(                                                           \
        "mma.sync.aligned.m16n8k16.row.col.f32.bf16.bf16.f32 "              \
        "{%0,%1,%2,%3}, {%4,%5,%6,%7}, {%8,%9}, {%0,%1,%2,%3};\n"           \
        : "+f"((ACCP)[0]), "+f"((ACCP)[1]), "+f"((ACCP)[2]), "+f"((ACCP)[3])\
        : "r"(A0), "r"(A1), "r"(A2), "r"(A3), "r"(B0), "r"(B1))

// A-side split-tile address: element (row mr, col kk) of an (M,Kc) operand in
// 128x64 swizzled tiles; returns offset in halves. kk must be even.
__device__ __forceinline__ size_t tile_off(size_t mr, int kk, int kc_n) {
    int mb = (int)(mr >> 7), r = (int)(mr & 127);
    int kc = kk >> 6, kl = kk & 63;
    uint32_t off = (uint32_t)(r * 128 + kl * 2);
    uint32_t sw  = off ^ ((uint32_t)(r & 7) << 4);
    return (((size_t)mb * kc_n + kc) << 13) + (sw >> 1);
}

__device__ __forceinline__ void split_store(__nv_bfloat16* hi, __nv_bfloat16* lo,
                                            size_t base, float v0, float v1) {
    __nv_bfloat16 h0 = __float2bfloat16(v0);
    __nv_bfloat16 h1 = __float2bfloat16(v1);
    *(__nv_bfloat162*)(hi + base) = __halves2bfloat162(h0, h1);
    *(__nv_bfloat162*)(lo + base) = __halves2bfloat162(
        __float2bfloat16(v0 - __bfloat162float(h0)),
        __float2bfloat16(v1 - __bfloat162float(h1)));
}

// ---------------------------------------------------------------------------
// Weight preprocessing: W (K,N) fp32 -> hi/lo bf16 (K,N) tiles. NO TRANSPOSE:
// pure streaming convert, coalesced both sides.
// Tile (nb,kc): 64 k-rows x 128 n-cols; within tile, byte (k,c) stored at
// k*256 + (c ^ ((k&7)<<4)), 16B chunk granularity.
// Grid: (Npad/128, K/64), 256 threads, 4 chunks of 8 elems per thread.
// ---------------------------------------------------------------------------
__global__ void __launch_bounds__(256)
convert_b_kernel(const float* __restrict__ W,
                 __nv_bfloat16* __restrict__ Thi,
                 __nv_bfloat16* __restrict__ Tlo,
                 int K, int N)
{
    const int tid   = threadIdx.x;
    const int nbase = blockIdx.x * 128;
    const int kbase = blockIdx.y * 64;
    const size_t tile_h =
        ((size_t)blockIdx.x * (size_t)(K >> 6) + (size_t)blockIdx.y) << 13;

#pragma unroll
    for (int i = 0; i < 4; i++) {
        int id = tid + i * 256;            // 0..1023
        int k  = id >> 4;                  // 0..63
        int ch = id & 15;                  // 0..15 (8-elem chunk)
        int n  = nbase + ch * 8;
        float4 v0 = make_float4(0.f, 0.f, 0.f, 0.f);
        float4 v1 = v0;
        if (n < N) {                       // chunk-aligned edges (N % 8 == 0)
            const float* src = W + (size_t)(kbase + k) * N + n;
            v0 = *(const float4*)src;
            v1 = *(const float4*)(src + 4);
        }
        float vv[8] = {v0.x, v0.y, v0.z, v0.w, v1.x, v1.y, v1.z, v1.w};
        uint32_t hw[4], lw[4];
#pragma unroll
        for (int j = 0; j < 4; j++) {
            __nv_bfloat16 h0 = __float2bfloat16(vv[2 * j]);
            __nv_bfloat16 h1 = __float2bfloat16(vv[2 * j + 1]);
            __nv_bfloat162 hp = __halves2bfloat162(h0, h1);
            __nv_bfloat162 lp = __halves2bfloat162(
                __float2bfloat16(vv[2 * j]     - __bfloat162float(h0)),
                __float2bfloat16(vv[2 * j + 1] - __bfloat162float(h1)));
            hw[j] = *(uint32_t*)&hp;
            lw[j] = *(uint32_t*)&lp;
        }
        uint32_t c = ((uint32_t)ch * 16) ^ (((uint32_t)k & 7) << 4);
        size_t off_h = tile_h + ((k * 256 + c) >> 1);
        *(uint4*)(Thi + off_h) = make_uint4(hw[0], hw[1], hw[2], hw[3]);
        *(uint4*)(Tlo + off_h) = make_uint4(lw[0], lw[1], lw[2], lw[3]);
    }
}

// ---------------------------------------------------------------------------
// Activation split: A (M,K) fp32 -> hi/lo bf16 A-tiles. K = 1<<kshift.
// ---------------------------------------------------------------------------
__global__ void __launch_bounds__(256)
split_a_kernel(const float* __restrict__ A,
               __nv_bfloat16* __restrict__ hi, __nv_bfloat16* __restrict__ lo,
               int n4, int kshift)
{
    int idx = blockIdx.x * 256 + threadIdx.x;
    if (idx >= n4) return;
    const int K = 1 << kshift;
    int idx4 = idx << 2;
    size_t m = (size_t)(idx4 >> kshift);
    int k = idx4 & (K - 1);
    float4 v = ((const float4*)A)[idx];
    split_store(hi, lo, tile_off(m, k,     K >> 6), v.x, v.y);
    split_store(hi, lo, tile_off(m, k + 2, K >> 6), v.z, v.w);
}

// ---------------------------------------------------------------------------
// Split-bf16 GEMM on mma.sync.m16n8k16, 3-stage bulk-copy pipeline, split-K.
// A tiles: (M,K) 128x64h layout (old swizzle, non-trans LDSM).
// B tiles: (K,N) 64x128 layout (chunk swizzle, LDSM.T).
// OUT=0: C fp32 (M,N) + bias/act.  OUT=1: split tiles, K'=1<<ksh, + bias/act.
// OUT=2: fp32 partial at C + blockIdx.z*M*N (no bias/act).
// kcn_per = slabs per z-block; slab index = blockIdx.z*kcn_per + c.
// ---------------------------------------------------------------------------
#define TILE_BYTES  16384
#define STAGE_BYTES (4 * TILE_BYTES)          // Ah, Al, Bh, Bl
#define NSTAGE      3
#define TCG_SMEM    (NSTAGE * STAGE_BYTES)    // 196608

template <int ACT, int OUT>
__global__ void __launch_bounds__(512)
tc_gemm_kernel(const __nv_bfloat16* __restrict__ Ahi,
               const __nv_bfloat16* __restrict__ Alo,
               const __nv_bfloat16* __restrict__ Bhi,
               const __nv_bfloat16* __restrict__ Blo,
               const float* __restrict__ bias, float* __restrict__ C,
               __nv_bfloat16* __restrict__ Chi, __nv_bfloat16* __restrict__ Clo,
               int ksh, int kcn_per, int M, int N, int K)
{
    extern __shared__ char dsm[];
    __shared__ uint64_t mbar[NSTAGE];

    const uint32_t sbase = smem_u32(dsm);
    uint32_t mb[NSTAGE];
#pragma unroll
    for (int i = 0; i < NSTAGE; i++) mb[i] = smem_u32(&mbar[i]);

    const int tid  = threadIdx.x;
    const int lane = tid & 31;
    const int warp = tid >> 5;
    const int wm   = warp >> 2;
    const int wn   = warp & 3;
    const int bm   = blockIdx.y * 128;
    const int bn   = blockIdx.x * 128;
    const int g    = lane >> 2;
    const int q    = lane & 3;

    // A fragment addressing (old layout, non-trans LDSM)
    const int ar = lane & 15;
    const int ac = (lane >> 4) * 16;
    const uint32_t a_xor = (uint32_t)(ar & 7) << 4;
    uint32_t a_row_off[2];
#pragma unroll
    for (int mi = 0; mi < 2; mi++)
        a_row_off[mi] = (uint32_t)((wm * 32 + mi * 16 + ar) * 128);

    // B fragment addressing ((K,N) layout, LDSM.T)
    // address-order tiles: (k0-7,n0-7),(k8-15,n0-7),(k0-7,n8-15),(k8-15,n8-15)
    const int bk_off = (lane & 7) + (((lane >> 3) & 1) << 3);  // 0..15
    const int bn_off = (lane >> 4) << 3;                       // 0 or 8
    const uint32_t bkb = (uint32_t)bk_off * 256;
    uint32_t b_cx[2];
#pragma unroll
    for (int nj = 0; nj < 2; nj++)
        b_cx[nj] = ((uint32_t)((wn * 32 + nj * 16 + bn_off) * 2))
                   ^ (((uint32_t)lane & 7) << 4);

    if (tid == 0)
#pragma unroll
        for (int i = 0; i < NSTAGE; i++) MBARRIER_INIT(mb[i], 1);
    __syncthreads();

    const int kcn = K >> 6;                       // total slabs
    const int koff = blockIdx.z * kcn_per;        // this z-block's first slab
    const size_t a_tile0 = (size_t)blockIdx.y * kcn + koff;
    const size_t b_tile0 = (size_t)blockIdx.x * kcn + koff;

    auto fill = [&](int c, int s) {               // tid 0 only
        MBARRIER_EXPECT_TX(mb[s], 4 * TILE_BYTES);
        const uint32_t st = sbase + s * STAGE_BYTES;
        const size_t ao = (a_tile0 + c) << 13;
        const size_t bo = (b_tile0 + c) << 13;
        bulk_g2s(st,                   Ahi + ao, TILE_BYTES, mb[s]);
        bulk_g2s(st + TILE_BYTES,      Alo + ao, TILE_BYTES, mb[s]);
        bulk_g2s(st + 2 * TILE_BYTES,  Bhi + bo, TILE_BYTES, mb[s]);
        bulk_g2s(st + 3 * TILE_BYTES,  Blo + bo, TILE_BYTES, mb[s]);
    };

    float acc[2][4][4];
#pragma unroll
    for (int mi = 0; mi < 2; mi++)
#pragma unroll
        for (int ni = 0; ni < 4; ni++)
#pragma unroll
            for (int f = 0; f < 4; f++) acc[mi][ni][f] = 0.f;

    if (tid == 0)
        for (int c = 0; c < NSTAGE && c < kcn_per; c++) fill(c, c);

    int ph[NSTAGE] = {0, 0, 0};
    int s = 0;
    for (int c = 0; c < kcn_per; c++) {
        MBARRIER_WAIT_PARITY(mb[s], ph[s]);
        ph[s] ^= 1;

        const uint32_t st = sbase + s * STAGE_BYTES;
        const uint32_t Ah = st;
        const uint32_t Al = st + TILE_BYTES;
        const uint32_t Bh = st + 2 * TILE_BYTES;
        const uint32_t Bl = st + 3 * TILE_BYTES;

#pragma unroll
        for (int ks = 0; ks < 4; ks++) {
            uint32_t ah[2][4], al[2][4];
#pragma unroll
            for (int mi = 0; mi < 2; mi++) {
                uint32_t off = a_row_off[mi] + ((ks * 32 + ac) ^ a_xor);
                LDSM4(ah[mi], Ah + off);
                LDSM4(al[mi], Al + off);
            }
            uint32_t bh[2][4], bl[2][4];
            const uint32_t bko = bkb + (uint32_t)ks * 4096;   // 16 k-rows
#pragma unroll
            for (int nj = 0; nj < 2; nj++) {
                uint32_t off = bko + b_cx[nj];
                LDSM4T(bh[nj], Bh + off);
                LDSM4T(bl[nj], Bl + off);
            }
#pragma unroll
            for (int mi = 0; mi < 2; mi++)
#pragma unroll
                for (int nj = 0; nj < 2; nj++)
#pragma unroll
                    for (int hf = 0; hf < 2; hf++) {
                        float* ap = acc[mi][nj * 2 + hf];
                        MMA_BF16(ap, ah[mi][0], ah[mi][1], ah[mi][2], ah[mi][3],
                                 bh[nj][hf * 2], bh[nj][hf * 2 + 1]);
                        MMA_BF16(ap, ah[mi][0], ah[mi][1], ah[mi][2], ah[mi][3],
                                 bl[nj][hf * 2], bl[nj][hf * 2 + 1]);
                        MMA_BF16(ap, al[mi][0], al[mi][1], al[mi][2], al[mi][3],
                                 bh[nj][hf * 2], bh[nj][hf * 2 + 1]);
                    }
        }
        __syncthreads();                        // all reads of stage s done
        if (tid == 0 && c + NSTAGE < kcn_per) fill(c + NSTAGE, s);
        s = (s == NSTAGE - 1) ? 0 : s + 1;
    }

    // ---- epilogue (N even everywhere -> pairwise guard ok)
    const int Kc = 1 << ksh;
    float* Cp = (OUT == 2) ? (C + (size_t)blockIdx.z * M * N) : C;
#pragma unroll
    for (int mi = 0; mi < 2; mi++) {
        const int m0 = bm + wm * 32 + mi * 16;
#pragma unroll
        for (int ni = 0; ni < 4; ni++) {
            const int n = bn + wn * 32 + ni * 8 + 2 * q;
            if (n >= N) continue;
            float b0 = 0.f, b1 = 0.f;
            if (OUT != 2 && bias) { b0 = bias[n]; b1 = bias[n + 1]; }
#pragma unroll
            for (int hf = 0; hf < 2; hf++) {
                const int m = m0 + g + hf * 8;
                float v0 = acc[mi][ni][hf * 2 + 0] + b0;
                float v1 = acc[mi][ni][hf * 2 + 1] + b1;
                if (OUT != 2 && ACT == 1) {
                    v0 = fmaxf(v0, 0.f); v1 = fmaxf(v1, 0.f);
                }
                if (OUT == 1) {
                    size_t flat = (size_t)m * N + n;
                    size_t mr = flat >> ksh;
                    int kk = (int)(flat & (Kc - 1));
                    split_store(Chi, Clo, tile_off(mr, kk, Kc >> 6), v0, v1);
                } else {
                    *(float2*)(Cp + (size_t)m * N + n) = make_float2(v0, v1);
                }
            }
        }
    }

    __syncthreads();
    if (tid == 0)
#pragma unroll
        for (int i = 0; i < NSTAGE; i++) MBARRIER_INVAL(mb[i]);
}

// ---------------------------------------------------------------------------
// Split-K reduce: sum nsplit partials, add bias, act; OUT=0 fp32, OUT=1 tiles.
// N must be a power of two here (8192 or 1024).
// ---------------------------------------------------------------------------
template <int ACT, int OUT>
__global__ void __launch_bounds__(256)
reduce_kernel(const float* __restrict__ P, int nsplit, size_t MN,
              const float* __restrict__ bias, int nmask,
              float* __restrict__ C,
              __nv_bfloat16* __restrict__ Chi, __nv_bfloat16* __restrict__ Clo,
              int ksh)
{
    size_t f = ((size_t)blockIdx.x * 256 + threadIdx.x) * 2;
    if (f >= MN) return;
    float v0 = 0.f, v1 = 0.f;
#pragma unroll 4
    for (int z = 0; z < nsplit; z++) {
        float2 p = *(const float2*)(P + (size_t)z * MN + f);
        v0 += p.x; v1 += p.y;
    }
    if (bias) {
        int n = (int)(f & nmask);
        v0 += bias[n]; v1 += bias[n + 1];
    }
    if (ACT == 1) { v0 = fmaxf(v0, 0.f); v1 = fmaxf(v1, 0.f); }
    if (OUT == 0) {
        *(float2*)(C + f) = make_float2(v0, v1);
    } else {
        size_t mr = f >> ksh;
        int kk = (int)(f & ((1 << ksh) - 1));
        split_store(Chi, Clo, tile_off(mr, kk, (1 << ksh) >> 6), v0, v1);
    }
}

// ---------------------------------------------------------------------------
// Fused conv+SiLU+dt+scan. One CTA per (batch, head), 256 threads.
// ---------------------------------------------------------------------------
__global__ void __launch_bounds__(256)
fused_scan_kernel(const float* __restrict__ zx,
                  const float* __restrict__ conv_w,
                  const float* __restrict__ conv_b,
                  const float* __restrict__ dt_bias,
                  const float* __restrict__ A_log,
                  const float* __restrict__ Dp,
                  float* __restrict__ y)
{
    const int b = blockIdx.x;
    const int h = blockIdx.y;
    const int t = threadIdx.x;

    __shared__ float Bsh[SEQL][DSTATE];
    __shared__ float Csh[SEQL][DSTATE];
    __shared__ float xsh[SEQL][HEADDIM];
    __shared__ float dts[SEQL], dAs[SEQL];

    const float* zrow = zx + (size_t)b * SEQL * DPROJ;

    {
        const int ch  = 2048 + t;
        const int src = D_INNER + ch;
        const float w0 = conv_w[ch * 4 + 0], w1 = conv_w[ch * 4 + 1];
        const float w2 = conv_w[ch * 4 + 2], w3 = conv_w[ch * 4 + 3];
        const float bb = conv_b[ch];
        float v[SEQL];
#pragma unroll
        for (int l = 0; l < SEQL; l++) v[l] = zrow[(size_t)l * DPROJ + src];
#pragma unroll
        for (int l = 0; l < SEQL; l++) {
            float sv = bb + v[l] * w3;
            if (l >= 1) sv += v[l - 1] * w2;
            if (l >= 2) sv += v[l - 2] * w1;
            if (l >= 3) sv += v[l - 3] * w0;
            sv = sv / (1.f + expf(-sv));
            if (t < 128) Bsh[l][t] = sv;
            else         Csh[l][t - 128] = sv;
        }
    }
    if (t < HEADDIM) {
        const int ch  = h * HEADDIM + t;
        const int src = D_INNER + ch;
        const float w0 = conv_w[ch * 4 + 0], w1 = conv_w[ch * 4 + 1];
        const float w2 = conv_w[ch * 4 + 2], w3 = conv_w[ch * 4 + 3];
        const float bb = conv_b[ch];
        float v[SEQL];
#pragma unroll
        for (int l = 0; l < SEQL; l++) v[l] = zrow[(size_t)l * DPROJ + src];
#pragma unroll
        for (int l = 0; l < SEQL; l++) {
            float sv = bb + v[l] * w3;
            if (l >= 1) sv += v[l - 1] * w2;
            if (l >= 2) sv += v[l - 2] * w1;
            if (l >= 3) sv += v[l - 3] * w0;
            xsh[l][t] = sv / (1.f + expf(-sv));
        }
    }
    if (t >= 64 && t < 64 + SEQL) {
        const int l = t - 64;
        float xr = zrow[(size_t)l * DPROJ + (D_INNER + CONV_DIM) + h] + dt_bias[h];
        float dt = (xr > 20.f) ? xr : log1pf(expf(xr));
        dts[l] = dt;
        dAs[l] = expf(-expf(A_log[h]) * dt);
    }
    __syncthreads();

    const int p = t >> 2;
    const int q = t & 3;
    float st[32];
#pragma unroll
    for (int i = 0; i < 32; i++) st[i] = 0.f;
    const float Dh = Dp[h];

#pragma unroll
    for (int l = 0; l < SEQL; l++) {
        const float xv   = xsh[l][p];
        const float coef = dts[l] * xv;
        const float dAv  = dAs[l];
        float part = 0.f;
#pragma unroll
        for (int i = 0; i < 32; i++) {
            const int sidx = q + 4 * i;
            st[i] = fmaf(dAv, st[i], coef * Bsh[l][sidx]);
            part  = fmaf(st[i], Csh[l][sidx], part);
        }
        part += __shfl_down_sync(0xffffffffu, part, 2);
        part += __shfl_down_sync(0xffffffffu, part, 1);
        if (q == 0)
            y[((size_t)b * SEQL + l) * D_INNER + h * HEADDIM + p] = part + xv * Dh;
    }
}

// ---------------------------------------------------------------------------
// y = y * silu(z); y *= rsqrt(mean(y^2)+1e-5) * norm_w; emit split A-tiles.
// ---------------------------------------------------------------------------
__global__ void __launch_bounds__(256)
gated_rmsnorm_split_kernel(const float* __restrict__ ybuf,
                           const float* __restrict__ zx,
                           const float* __restrict__ norm_w,
                           __nv_bfloat16* __restrict__ hi,
                           __nv_bfloat16* __restrict__ lo)
{
    const size_t row = blockIdx.x;
    const int t = threadIdx.x;
    const int d0 = t * 8;
    const float* yb = ybuf + row * D_INNER;
    const float* zb = zx   + row * DPROJ;

    float v[8];
    float ss = 0.f;
#pragma unroll
    for (int j = 0; j < 8; j += 4) {
        float4 yv = *(const float4*)(yb + d0 + j);
        float4 zv = *(const float4*)(zb + d0 + j);
        v[j + 0] = yv.x * (zv.x / (1.f + expf(-zv.x)));
        v[j + 1] = yv.y * (zv.y / (1.f + expf(-zv.y)));
        v[j + 2] = yv.z * (zv.z / (1.f + expf(-zv.z)));
        v[j + 3] = yv.w * (zv.w / (1.f + expf(-zv.w)));
        ss = fmaf(v[j+0], v[j+0], ss); ss = fmaf(v[j+1], v[j+1], ss);
        ss = fmaf(v[j+2], v[j+2], ss); ss = fmaf(v[j+3], v[j+3], ss);
    }
#pragma unroll
    for (int o = 16; o > 0; o >>= 1)
        ss += __shfl_down_sync(0xffffffffu, ss, o);

    __shared__ float red[8];
    __shared__ float s_scale;
    if ((t & 31) == 0) red[t >> 5] = ss;
    __syncthreads();
    if (t == 0) {
        float s = 0.f;
        for (int i = 0; i < 8; i++) s += red[i];
        s_scale = rsqrtf(s / (float)D_INNER + 1e-5f);
    }
    __syncthreads();
    const float scale = s_scale;

#pragma unroll
    for (int j = 0; j < 8; j += 2) {
        int d = d0 + j;
        float v0 = v[j]     * scale * norm_w[d];
        float v1 = v[j + 1] * scale * norm_w[d + 1];
        split_store(hi, lo, tile_off(row, d, D_INNER >> 6), v0, v1);
    }
}

// ---------------------------------------------------------------------------
// Final tiny layer: out = A(256x1024) @ W(1024x2) + b. One CTA per row.
// ---------------------------------------------------------------------------
__global__ void __launch_bounds__(256)
final_kernel(const float* __restrict__ A, const float* __restrict__ W,
             const float* __restrict__ bias, float* __restrict__ out)
{
    const int m = blockIdx.x;
    const int t = threadIdx.x;
    float4 a = ((const float4*)(A + (size_t)m * 1024))[t];
    const float4 w0 = ((const float4*)W)[2 * t];
    const float4 w1 = ((const float4*)W)[2 * t + 1];
    float s0 = a.x * w0.x + a.y * w0.z + a.z * w1.x + a.w * w1.z;
    float s1 = a.x * w0.y + a.y * w0.w + a.z * w1.y + a.w * w1.w;
#pragma unroll
    for (int o = 16; o > 0; o >>= 1) {
        s0 += __shfl_down_sync(0xffffffffu, s0, o);
        s1 += __shfl_down_sync(0xffffffffu, s1, o);
    }
    __shared__ float r0[8], r1[8];
    if ((t & 31) == 0) { r0[t >> 5] = s0; r1[t >> 5] = s1; }
    __syncthreads();
    if (t == 0) {
        float a0 = 0.f, a1 = 0.f;
        for (int i = 0; i < 8; i++) { a0 += r0[i]; a1 += r1[i]; }
        out[m * 2 + 0] = a0 + bias[0];
        out[m * 2 + 1] = a1 + bias[1];
    }
}

// ---------------------------------------------------------------------------
// Host-side orchestration
// ---------------------------------------------------------------------------
struct MambaW {
    const float *in_proj, *conv_w, *conv_b, *dt_bias, *A_log, *D, *norm_w, *out_proj;
};

extern "C" void kernel_launch(void* const* d_in, const int* in_sizes, int n_in,
                              void* d_out, int out_size)
{
    const float* x      = (const float*)d_in[0];
    const float* w_in1  = (const float*)d_in[1];
    const float* b_in1  = (const float*)d_in[2];
    const float* w_in2  = (const float*)d_in[3];
    const float* b_in2  = (const float*)d_in[4];
    MambaW m1 = { (const float*)d_in[5],  (const float*)d_in[6],  (const float*)d_in[7],
                  (const float*)d_in[8],  (const float*)d_in[9],  (const float*)d_in[10],
                  (const float*)d_in[11], (const float*)d_in[12] };
    MambaW m2 = { (const float*)d_in[13], (const float*)d_in[14], (const float*)d_in[15],
                  (const float*)d_in[16], (const float*)d_in[17], (const float*)d_in[18],
                  (const float*)d_in[19], (const float*)d_in[20] };
    const float* w_out1 = (const float*)d_in[21];
    const float* b_out1 = (const float*)d_in[22];
    const float* w_out2 = (const float*)d_in[23];
    const float* b_out2 = (const float*)d_in[24];
    float* out = (float*)d_out;

    cudaFuncSetAttribute(tc_gemm_kernel<0, 0>,
                         cudaFuncAttributeMaxDynamicSharedMemorySize, TCG_SMEM);
    cudaFuncSetAttribute(tc_gemm_kernel<0, 1>,
                         cudaFuncAttributeMaxDynamicSharedMemorySize, TCG_SMEM);
    cudaFuncSetAttribute(tc_gemm_kernel<0, 2>,
                         cudaFuncAttributeMaxDynamicSharedMemorySize, TCG_SMEM);
    cudaFuncSetAttribute(tc_gemm_kernel<1, 0>,
                         cudaFuncAttributeMaxDynamicSharedMemorySize, TCG_SMEM);

    float *a, *zx, *ybuf, *part;
    __nv_bfloat16 *whi, *wlo, *p1h, *p1l, *p2h, *p2l;
    cudaGetSymbolAddress((void**)&a,    g_a);
    cudaGetSymbolAddress((void**)&zx,   g_zx);
    cudaGetSymbolAddress((void**)&ybuf, g_y);
    cudaGetSymbolAddress((void**)&part, g_part);
    cudaGetSymbolAddress((void**)&whi,  g_whi);
    cudaGetSymbolAddress((void**)&wlo,  g_wlo);
    cudaGetSymbolAddress((void**)&p1h,  g_p1hi);
    cudaGetSymbolAddress((void**)&p1l,  g_p1lo);
    cudaGetSymbolAddress((void**)&p2h,  g_p2hi);
    cudaGetSymbolAddress((void**)&p2l,  g_p2lo);

    // ---- weight preprocessing (streaming convert, no transpose)
    auto cvt = [&](const float* W, size_t off, int K, int N, int Npad) {
        convert_b_kernel<<<dim3(Npad / 128, K / 64), 256>>>(
            W, whi + off, wlo + off, K, N);
    };
    cvt(w_in1,       OFF_WIN1,    1024, 8192, 8192);
    cvt(w_in2,       OFF_WIN2,    8192, 8192, 8192);
    cvt(m1.in_proj,  OFF_M1_INP,  1024, DPROJ, 4480);
    cvt(m2.in_proj,  OFF_M2_INP,  1024, DPROJ, 4480);
    cvt(m1.out_proj, OFF_M1_OUTP, 2048, 1024, 1024);
    cvt(m2.out_proj, OFF_M2_OUTP, 2048, 1024, 1024);
    cvt(w_out1,      OFF_WOUT1,   8192, 1024, 1024);

    // ---- split x -> p1 (256 x 1024, kshift 10)
    split_a_kernel<<<(BATCH * 1024 / 4 + 255) / 256, 256>>>(x, p1h, p1l,
                                                            BATCH * 1024 / 4, 10);

    const size_t MN_256x8192 = (size_t)BATCH * 8192;   // 2,097,152
    const size_t MN_2048x1024 = (size_t)ROWS * 1024;   // 2,097,152
    const size_t MN_256x1024 = (size_t)BATCH * 1024;   //   262,144

    // ---- MLP in (split-K x4)
    // win1: partials, then reduce(relu? no—relu yes) -> p2 tiles ksh13
    tc_gemm_kernel<0, 2><<<dim3(64, 2, 4), 512, TCG_SMEM>>>(
        p1h, p1l, whi + OFF_WIN1, wlo + OFF_WIN1, nullptr,
        part, nullptr, nullptr, 13, 4, BATCH, 8192, 1024);
    reduce_kernel<1, 1><<<(unsigned)(MN_256x8192 / 512), 256>>>(
        part, 4, MN_256x8192, b_in1, 8191, nullptr, p2h, p2l, 13);
    // win2: partials x4, reduce -> p1 tiles ksh10
    tc_gemm_kernel<0, 2><<<dim3(64, 2, 4), 512, TCG_SMEM>>>(
        p2h, p2l, whi + OFF_WIN2, wlo + OFF_WIN2, nullptr,
        part, nullptr, nullptr, 10, 32, BATCH, 8192, 8192);
    reduce_kernel<0, 1><<<(unsigned)(MN_256x8192 / 512), 256>>>(
        part, 4, MN_256x8192, b_in2, 8191, nullptr, p1h, p1l, 10);

    // ---- 2x Mamba2 layers (h tiles live in p1 as (2048, 1024))
    const MambaW* layers[2] = { &m1, &m2 };
    const size_t inp_off[2]  = { OFF_M1_INP,  OFF_M2_INP };
    const size_t outp_off[2] = { OFF_M1_OUTP, OFF_M2_OUTP };
    for (int li = 0; li < 2; li++) {
        const MambaW& p = *layers[li];
        // zx = h @ in_proj (fp32 out, 560 CTAs, no split)
        tc_gemm_kernel<0, 0><<<dim3(35, 16, 1), 512, TCG_SMEM>>>(
            p1h, p1l, whi + inp_off[li], wlo + inp_off[li], nullptr,
            zx, nullptr, nullptr, 0, 16, ROWS, DPROJ, 1024);
        fused_scan_kernel<<<dim3(BATCH, NHEADS), 256>>>(
            zx, p.conv_w, p.conv_b, p.dt_bias, p.A_log, p.D, ybuf);
        gated_rmsnorm_split_kernel<<<ROWS, 256>>>(ybuf, zx, p.norm_w, p2h, p2l);
        // h = y @ out_proj: split-K x4, reduce -> p1 tiles
        int ksh_next = (li == 0) ? 10 : 13;
        tc_gemm_kernel<0, 2><<<dim3(8, 16, 4), 512, TCG_SMEM>>>(
            p2h, p2l, whi + outp_off[li], wlo + outp_off[li], nullptr,
            part, nullptr, nullptr, ksh_next, 8, ROWS, 1024, 2048);
        reduce_kernel<0, 1><<<(unsigned)(MN_2048x1024 / 512), 256>>>(
            part, 4, MN_2048x1024, nullptr, 1023, nullptr, p1h, p1l, ksh_next);
    }

    // ---- MLP out: split-K x16, reduce(relu+bias) -> fp32 a; final dot
    tc_gemm_kernel<0, 2><<<dim3(8, 2, 16), 512, TCG_SMEM>>>(
        p1h, p1l, whi + OFF_WOUT1, wlo + OFF_WOUT1, nullptr,
        part, nullptr, nullptr, 0, 8, BATCH, 1024, 8192);
    reduce_kernel<1, 0><<<(unsigned)(MN_256x1024 / 512), 256>>>(
        part, 16, MN_256x1024, b_out1, 1023, a, nullptr, nullptr, 0);
    final_kernel<<<BATCH, 256>>>(a, w_out2, b_out2, out);
}

// round 11
// speedup vs baseline: 3.4483x; 1.0196x over previous
#include <cuda_runtime.h>
#include <cuda_bf16.h>
#include <cstdint>

// ---------------------------------------------------------------------------
// Problem dimensions (fixed by the reference)
// ---------------------------------------------------------------------------
#define BATCH    256
#define SEQL     8
#define HIDD     1024            // HID
#define D_INNER  2048
#define DSTATE   128
#define NHEADS   32
#define HEADDIM  64
#define CONV_DIM 2304            // D_INNER + 2*DSTATE
#define DPROJ    4384            // 2*D_INNER + 2*DSTATE + NHEADS
#define ROWS     (BATCH * SEQL)  // 2048

// ---------------------------------------------------------------------------
// Scratch (static device buffers; no allocation allowed in kernel_launch)
// ---------------------------------------------------------------------------
__device__ float g_a   [BATCH * 8192];    // fp32 intermediate (out1 output)
__device__ float g_zx  [ROWS  * DPROJ];   // zxbcdt (2048 x 4384)
__device__ float g_y   [ROWS  * D_INNER]; // SSM output (2048 x 2048)
__device__ float g_part[8388608];         // split-K partials

// Two ping-pong split-bf16 tiled activation buffers (max 2048x2048)
#define AMAX 4194304
__device__ __nv_bfloat16 g_p1hi[AMAX];
__device__ __nv_bfloat16 g_p1lo[AMAX];
__device__ __nv_bfloat16 g_p2hi[AMAX];
__device__ __nv_bfloat16 g_p2lo[AMAX];

// Split-bf16 tiled weights. B tile = 64 k-rows x 256 n-cols, (K,N) layout,
// 512B per k-row, 16B chunks xor-swizzled by (k&7)<<4. One tile = 32KB
// contiguous; tile index = nb * (K/64) + kc. N padded to mult of 256.
#define OFF_WIN1     0ULL
#define OFF_WIN2     8388608ULL      // win1: 8192*1024
#define OFF_M1_INP   75497472ULL     // win2: 8192*8192
#define OFF_M2_INP   80216064ULL     // inproj: 4608*1024
#define OFF_M1_OUTP  84934656ULL
#define OFF_M2_OUTP  87031808ULL     // outproj: 1024*2048
#define OFF_WOUT1    89128960ULL
#define WT_TOTAL     97517568ULL     // + wout1: 1024*8192
__device__ __nv_bfloat16 g_whi[WT_TOTAL];
__device__ __nv_bfloat16 g_wlo[WT_TOTAL];

// ---------------------------------------------------------------------------
// PTX helpers
// ---------------------------------------------------------------------------
__device__ __forceinline__ uint32_t smem_u32(const void* p) {
    uint32_t a;
    asm("{ .reg .u64 t; cvta.to.shared.u64 t, %1; cvt.u32.u64 %0, t; }"
        : "=r"(a) : "l"(p));
    return a;
}

#define MBARRIER_INIT(addr, count) \
    asm volatile("mbarrier.init.shared.b64 [%0], %1;" \
                 :: "r"((uint32_t)(addr)), "r"((uint32_t)(count)) : "memory")
#define MBARRIER_INVAL(addr) \
    asm volatile("mbarrier.inval.shared.b64 [%0];" \
                 :: "r"((uint32_t)(addr)) : "memory")
#define MBARRIER_EXPECT_TX(addr, bytes) \
    asm volatile("mbarrier.arrive.expect_tx.shared.b64 _, [%0], %1;" \
                 :: "r"((uint32_t)(addr)), "r"((uint32_t)(bytes)) : "memory")

#define MBARRIER_WAIT_PARITY(addr, par) do {                                   \
    uint32_t _m = (uint32_t)(addr), _p = (uint32_t)(par), _d;                  \
    asm volatile(                                                              \
        "{\n\t.reg .pred p;\n\t"                                               \
        "mbarrier.try_wait.parity.acquire.cta.shared::cta.b64 p, [%1], %2;\n\t"\
        "selp.b32 %0, 1, 0, p;\n\t}"                                           \
        : "=r"(_d) : "r"(_m), "r"(_p) : "memory");                             \
    if (!_d) {                                                                 \
        asm volatile(                                                          \
            "{\n\t.reg .pred P1;\n\t"                                          \
            "WL_%=:\n\t"                                                       \
            "mbarrier.try_wait.parity.acquire.cta.shared::cta.b64 P1, [%0], %1, 0x989680;\n\t" \
            "@P1 bra.uni WD_%=;\n\t"                                           \
            "bra.uni WL_%=;\n\t"                                               \
            "WD_%=:\n\t}"                                                      \
            :: "r"(_m), "r"(_p) : "memory");                                   \
    }                                                                          \
} while (0)

__device__ __forceinline__ void bulk_g2s(uint32_t sdst, const void* gsrc,
                                         uint32_t bytes, uint32_t mbar) {
    asm volatile(
        "cp.async.bulk.shared::cluster.global.mbarrier::complete_tx::bytes "
        "[%0], [%1], %2, [%3];"
        :: "r"(sdst), "l"(gsrc), "r"(bytes), "r"(mbar) : "memory");
}

#define LDSM4(r, addr) \
    asm volatile("ldmatrix.sync.aligned.m8n8.x4.shared.b16 {%0,%1,%2,%3}, [%4];" \
                 : "=r"((r)[0]), "=r"((r)[1]), "=r"((r)[2]), "=r"((r)[3]) \
                 : "r"(addr))

#define LDSM4T(r, addr) \
    asm volatile("ldmatrix.sync.aligned.m8n8.x4.trans.shared.b16 {%0,%1,%2,%3}, [%4];" \
                 : "=r"((r)[0]), "=r"((r)[1]), "=r"((r)[2]), "=r"((r)[3]) \
                 : "r"(addr))

#define MMA_BF16(ACCP, A0, A1, A2, A3, B0, B1)                              \
    asm volatile(                                                           \
        "mma.sync.aligned.m16n8k16.row.col.f32.bf16.bf16.f32 "              \
        "{%0,%1,%2,%3}, {%4,%5,%6,%7}, {%8,%9}, {%0,%1,%2,%3};\n"           \
        : "+f"((ACCP)[0]), "+f"((ACCP)[1]), "+f"((ACCP)[2]), "+f"((ACCP)[3])\
        : "r"(A0), "r"(A1), "r"(A2), "r"(A3), "r"(B0), "r"(B1))

// A-side split-tile address: element (row mr, col kk) of an (M,Kc) operand in
// 128x64 swizzled tiles; returns offset in halves. kk must be even.
__device__ __forceinline__ size_t tile_off(size_t mr, int kk, int kc_n) {
    int mb = (int)(mr >> 7), r = (int)(mr & 127);
    int kc = kk >> 6, kl = kk & 63;
    uint32_t off = (uint32_t)(r * 128 + kl * 2);
    uint32_t sw  = off ^ ((uint32_t)(r & 7) << 4);
    return (((size_t)mb * kc_n + kc) << 13) + (sw >> 1);
}

__device__ __forceinline__ void split_store(__nv_bfloat16* hi, __nv_bfloat16* lo,
                                            size_t base, float v0, float v1) {
    __nv_bfloat16 h0 = __float2bfloat16(v0);
    __nv_bfloat16 h1 = __float2bfloat16(v1);
    *(__nv_bfloat162*)(hi + base) = __halves2bfloat162(h0, h1);
    *(__nv_bfloat162*)(lo + base) = __halves2bfloat162(
        __float2bfloat16(v0 - __bfloat162float(h0)),
        __float2bfloat16(v1 - __bfloat162float(h1)));
}

// ---------------------------------------------------------------------------
// Weight preprocessing: W (K,N) fp32 -> hi/lo bf16 (K,N) tiles (64k x 256n,
// 512B rows, 16B-chunk xor swizzle). Pure streaming convert, coalesced.
// Grid: (Npad/256, K/64), 256 threads, 8 chunks of 8 elems per thread.
// ---------------------------------------------------------------------------
__global__ void __launch_bounds__(256)
convert_b_kernel(const float* __restrict__ W,
                 __nv_bfloat16* __restrict__ Thi,
                 __nv_bfloat16* __restrict__ Tlo,
                 int K, int N)
{
    const int tid   = threadIdx.x;
    const int nbase = blockIdx.x * 256;
    const int kbase = blockIdx.y * 64;
    const size_t tile_h =
        ((size_t)blockIdx.x * (size_t)(K >> 6) + (size_t)blockIdx.y) << 14;

#pragma unroll
    for (int i = 0; i < 8; i++) {
        int id = tid + i * 256;            // 0..2047
        int k  = id >> 5;                  // 0..63
        int ch = id & 31;                  // 0..31 (8-elem chunk)
        int n  = nbase + ch * 8;
        float4 v0 = make_float4(0.f, 0.f, 0.f, 0.f);
        float4 v1 = v0;
        if (n < N) {                       // N % 8 == 0 -> chunk all-or-nothing
            const float* src = W + (size_t)(kbase + k) * N + n;
            v0 = *(const float4*)src;
            v1 = *(const float4*)(src + 4);
        }
        float vv[8] = {v0.x, v0.y, v0.z, v0.w, v1.x, v1.y, v1.z, v1.w};
        uint32_t hw[4], lw[4];
#pragma unroll
        for (int j = 0; j < 4; j++) {
            __nv_bfloat16 h0 = __float2bfloat16(vv[2 * j]);
            __nv_bfloat16 h1 = __float2bfloat16(vv[2 * j + 1]);
            __nv_bfloat162 hp = __halves2bfloat162(h0, h1);
            __nv_bfloat162 lp = __halves2bfloat162(
                __float2bfloat16(vv[2 * j]     - __bfloat162float(h0)),
                __float2bfloat16(vv[2 * j + 1] - __bfloat162float(h1)));
            hw[j] = *(uint32_t*)&hp;
            lw[j] = *(uint32_t*)&lp;
        }
        uint32_t c = ((uint32_t)ch * 16) ^ (((uint32_t)k & 7) << 4);
        size_t off_h = tile_h + ((k * 512 + c) >> 1);
        *(uint4*)(Thi + off_h) = make_uint4(hw[0], hw[1], hw[2], hw[3]);
        *(uint4*)(Tlo + off_h) = make_uint4(lw[0], lw[1], lw[2], lw[3]);
    }
}

// ---------------------------------------------------------------------------
// Activation split: A (M,K) fp32 -> hi/lo bf16 A-tiles. K = 1<<kshift.
// ---------------------------------------------------------------------------
__global__ void __launch_bounds__(256)
split_a_kernel(const float* __restrict__ A,
               __nv_bfloat16* __restrict__ hi, __nv_bfloat16* __restrict__ lo,
               int n4, int kshift)
{
    int idx = blockIdx.x * 256 + threadIdx.x;
    if (idx >= n4) return;
    const int K = 1 << kshift;
    int idx4 = idx << 2;
    size_t m = (size_t)(idx4 >> kshift);
    int k = idx4 & (K - 1);
    float4 v = ((const float4*)A)[idx];
    split_store(hi, lo, tile_off(m, k,     K >> 6), v.x, v.y);
    split_store(hi, lo, tile_off(m, k + 2, K >> 6), v.z, v.w);
}

// ---------------------------------------------------------------------------
// Split-bf16 GEMM, CTA tile 128x256, 16 warps (4M x 4N), warp tile 32x64.
// A tiles: (M,K) 128x64h (LDSM). B tiles: (K,N) 64x256 (LDSM.T).
// 2-stage bulk-copy pipeline. Split-K via blockIdx.z.
// OUT=0: C fp32 + bias/act. OUT=1: split tiles (K'=1<<ksh) + bias/act.
// OUT=2: fp32 partial at C + z*M*N (no bias/act).
// ---------------------------------------------------------------------------
#define A_TILE_B    16384
#define B_TILE_B    32768
#define STAGE_BYTES (2 * A_TILE_B + 2 * B_TILE_B)   // 98304
#define NSTAGE      2
#define TCG_SMEM    (NSTAGE * STAGE_BYTES)          // 196608

template <int ACT, int OUT>
__global__ void __launch_bounds__(512)
tc_gemm_kernel(const __nv_bfloat16* __restrict__ Ahi,
               const __nv_bfloat16* __restrict__ Alo,
               const __nv_bfloat16* __restrict__ Bhi,
               const __nv_bfloat16* __restrict__ Blo,
               const float* __restrict__ bias, float* __restrict__ C,
               __nv_bfloat16* __restrict__ Chi, __nv_bfloat16* __restrict__ Clo,
               int ksh, int kcn_per, int M, int N, int K)
{
    extern __shared__ char dsm[];
    __shared__ uint64_t mbar[NSTAGE];

    const uint32_t sbase = smem_u32(dsm);
    uint32_t mb[NSTAGE];
#pragma unroll
    for (int i = 0; i < NSTAGE; i++) mb[i] = smem_u32(&mbar[i]);

    const int tid  = threadIdx.x;
    const int lane = tid & 31;
    const int warp = tid >> 5;
    const int wm   = warp & 3;                 // 0..3 (M dir)
    const int wn   = warp >> 2;                // 0..3 (N dir)
    const int bm   = blockIdx.y * 128;
    const int bn   = blockIdx.x * 256;
    const int g    = lane >> 2;
    const int q    = lane & 3;

    // A fragment addressing (128x64h tile, non-trans LDSM)
    const int ar = lane & 15;
    const int ac = (lane >> 4) * 16;
    const uint32_t a_xor = (uint32_t)(ar & 7) << 4;
    uint32_t a_row_off[2];
#pragma unroll
    for (int mi = 0; mi < 2; mi++)
        a_row_off[mi] = (uint32_t)((wm * 32 + mi * 16 + ar) * 128);

    // B fragment addressing (64x256 tile, 512B rows, LDSM.T)
    const int bk  = (lane & 7) + (((lane >> 3) & 1) << 3);   // 0..15
    const int bno = (lane >> 4) << 3;                        // 0 or 8
    const uint32_t b_xor = ((uint32_t)bk & 7) << 4;
    const uint32_t bkb   = (uint32_t)bk * 512;
    uint32_t b_cn[4];
#pragma unroll
    for (int nj = 0; nj < 4; nj++)
        b_cn[nj] = ((uint32_t)((wn * 64 + nj * 16 + bno) * 2)) ^ b_xor;

    if (tid == 0)
#pragma unroll
        for (int i = 0; i < NSTAGE; i++) MBARRIER_INIT(mb[i], 1);
    __syncthreads();

    const int kcn = K >> 6;
    const int koff = blockIdx.z * kcn_per;
    const size_t a_tile0 = (size_t)blockIdx.y * kcn + koff;
    const size_t b_tile0 = (size_t)blockIdx.x * kcn + koff;

    auto fill = [&](int c, int s) {            // tid 0 only
        MBARRIER_EXPECT_TX(mb[s], STAGE_BYTES);
        const uint32_t st = sbase + s * STAGE_BYTES;
        const size_t ao = (a_tile0 + c) << 13;
        const size_t bo = (b_tile0 + c) << 14;
        bulk_g2s(st,                Ahi + ao, A_TILE_B, mb[s]);
        bulk_g2s(st + A_TILE_B,     Alo + ao, A_TILE_B, mb[s]);
        bulk_g2s(st + 2 * A_TILE_B, Bhi + bo, B_TILE_B, mb[s]);
        bulk_g2s(st + 2 * A_TILE_B + B_TILE_B, Blo + bo, B_TILE_B, mb[s]);
    };

    float acc[2][8][4];
#pragma unroll
    for (int mi = 0; mi < 2; mi++)
#pragma unroll
        for (int ni = 0; ni < 8; ni++)
#pragma unroll
            for (int f = 0; f < 4; f++) acc[mi][ni][f] = 0.f;

    if (tid == 0)
        for (int c = 0; c < NSTAGE && c < kcn_per; c++) fill(c, c);

    int ph[NSTAGE] = {0, 0};
    int s = 0;
    for (int c = 0; c < kcn_per; c++) {
        MBARRIER_WAIT_PARITY(mb[s], ph[s]);
        ph[s] ^= 1;

        const uint32_t st = sbase + s * STAGE_BYTES;
        const uint32_t Ah = st;
        const uint32_t Al = st + A_TILE_B;
        const uint32_t Bh = st + 2 * A_TILE_B;
        const uint32_t Bl = Bh + B_TILE_B;

#pragma unroll
        for (int ks = 0; ks < 4; ks++) {
            uint32_t ah[2][4], al[2][4];
#pragma unroll
            for (int mi = 0; mi < 2; mi++) {
                uint32_t off = a_row_off[mi] + ((ks * 32 + ac) ^ a_xor);
                LDSM4(ah[mi], Ah + off);
                LDSM4(al[mi], Al + off);
            }
            const uint32_t bko = bkb + (uint32_t)ks * 8192;   // 16 k-rows
#pragma unroll
            for (int nj = 0; nj < 4; nj++) {
                uint32_t bh[4], bl[4];
                uint32_t off = bko + b_cn[nj];
                LDSM4T(bh, Bh + off);
                LDSM4T(bl, Bl + off);
#pragma unroll
                for (int mi = 0; mi < 2; mi++)
#pragma unroll
                    for (int hf = 0; hf < 2; hf++) {
                        float* ap = acc[mi][nj * 2 + hf];
                        MMA_BF16(ap, ah[mi][0], ah[mi][1], ah[mi][2], ah[mi][3],
                                 bh[hf * 2], bh[hf * 2 + 1]);
                        MMA_BF16(ap, ah[mi][0], ah[mi][1], ah[mi][2], ah[mi][3],
                                 bl[hf * 2], bl[hf * 2 + 1]);
                        MMA_BF16(ap, al[mi][0], al[mi][1], al[mi][2], al[mi][3],
                                 bh[hf * 2], bh[hf * 2 + 1]);
                    }
            }
        }
        __syncthreads();                        // all reads of stage s done
        if (tid == 0 && c + NSTAGE < kcn_per) fill(c + NSTAGE, s);
        s ^= 1;
    }

    // ---- epilogue (N even everywhere -> pairwise guard ok)
    const int Kc = 1 << ksh;
    float* Cp = (OUT == 2) ? (C + (size_t)blockIdx.z * M * N) : C;
#pragma unroll
    for (int mi = 0; mi < 2; mi++) {
        const int m0 = bm + wm * 32 + mi * 16;
#pragma unroll
        for (int ni = 0; ni < 8; ni++) {
            const int n = bn + wn * 64 + ni * 8 + 2 * q;
            if (n >= N) continue;
            float b0 = 0.f, b1 = 0.f;
            if (OUT != 2 && bias) { b0 = bias[n]; b1 = bias[n + 1]; }
#pragma unroll
            for (int hf = 0; hf < 2; hf++) {
                const int m = m0 + g + hf * 8;
                float v0 = acc[mi][ni][hf * 2 + 0] + b0;
                float v1 = acc[mi][ni][hf * 2 + 1] + b1;
                if (OUT != 2 && ACT == 1) {
                    v0 = fmaxf(v0, 0.f); v1 = fmaxf(v1, 0.f);
                }
                if (OUT == 1) {
                    size_t flat = (size_t)m * N + n;
                    size_t mr = flat >> ksh;
                    int kk = (int)(flat & (Kc - 1));
                    split_store(Chi, Clo, tile_off(mr, kk, Kc >> 6), v0, v1);
                } else {
                    *(float2*)(Cp + (size_t)m * N + n) = make_float2(v0, v1);
                }
            }
        }
    }

    __syncthreads();
    if (tid == 0)
#pragma unroll
        for (int i = 0; i < NSTAGE; i++) MBARRIER_INVAL(mb[i]);
}

// ---------------------------------------------------------------------------
// Split-K reduce: sum nsplit partials, add bias, act; OUT=0 fp32, OUT=1 tiles.
// ---------------------------------------------------------------------------
template <int ACT, int OUT>
__global__ void __launch_bounds__(256)
reduce_kernel(const float* __restrict__ P, int nsplit, size_t MN,
              const float* __restrict__ bias, int nmask,
              float* __restrict__ C,
              __nv_bfloat16* __restrict__ Chi, __nv_bfloat16* __restrict__ Clo,
              int ksh)
{
    size_t f = ((size_t)blockIdx.x * 256 + threadIdx.x) * 2;
    if (f >= MN) return;
    float v0 = 0.f, v1 = 0.f;
#pragma unroll 4
    for (int z = 0; z < nsplit; z++) {
        float2 p = *(const float2*)(P + (size_t)z * MN + f);
        v0 += p.x; v1 += p.y;
    }
    if (bias) {
        int n = (int)(f & nmask);
        v0 += bias[n]; v1 += bias[n + 1];
    }
    if (ACT == 1) { v0 = fmaxf(v0, 0.f); v1 = fmaxf(v1, 0.f); }
    if (OUT == 0) {
        *(float2*)(C + f) = make_float2(v0, v1);
    } else {
        size_t mr = f >> ksh;
        int kk = (int)(f & ((1 << ksh) - 1));
        split_store(Chi, Clo, tile_off(mr, kk, (1 << ksh) >> 6), v0, v1);
    }
}

// ---------------------------------------------------------------------------
// Fused conv+SiLU+dt+scan. One CTA per (batch, head), 256 threads.
// ---------------------------------------------------------------------------
__global__ void __launch_bounds__(256)
fused_scan_kernel(const float* __restrict__ zx,
                  const float* __restrict__ conv_w,
                  const float* __restrict__ conv_b,
                  const float* __restrict__ dt_bias,
                  const float* __restrict__ A_log,
                  const float* __restrict__ Dp,
                  float* __restrict__ y)
{
    const int b = blockIdx.x;
    const int h = blockIdx.y;
    const int t = threadIdx.x;

    __shared__ float Bsh[SEQL][DSTATE];
    __shared__ float Csh[SEQL][DSTATE];
    __shared__ float xsh[SEQL][HEADDIM];
    __shared__ float dts[SEQL], dAs[SEQL];

    const float* zrow = zx + (size_t)b * SEQL * DPROJ;

    {
        const int ch  = 2048 + t;
        const int src = D_INNER + ch;
        const float w0 = conv_w[ch * 4 + 0], w1 = conv_w[ch * 4 + 1];
        const float w2 = conv_w[ch * 4 + 2], w3 = conv_w[ch * 4 + 3];
        const float bb = conv_b[ch];
        float v[SEQL];
#pragma unroll
        for (int l = 0; l < SEQL; l++) v[l] = zrow[(size_t)l * DPROJ + src];
#pragma unroll
        for (int l = 0; l < SEQL; l++) {
            float sv = bb + v[l] * w3;
            if (l >= 1) sv += v[l - 1] * w2;
            if (l >= 2) sv += v[l - 2] * w1;
            if (l >= 3) sv += v[l - 3] * w0;
            sv = sv / (1.f + expf(-sv));
            if (t < 128) Bsh[l][t] = sv;
            else         Csh[l][t - 128] = sv;
        }
    }
    if (t < HEADDIM) {
        const int ch  = h * HEADDIM + t;
        const int src = D_INNER + ch;
        const float w0 = conv_w[ch * 4 + 0], w1 = conv_w[ch * 4 + 1];
        const float w2 = conv_w[ch * 4 + 2], w3 = conv_w[ch * 4 + 3];
        const float bb = conv_b[ch];
        float v[SEQL];
#pragma unroll
        for (int l = 0; l < SEQL; l++) v[l] = zrow[(size_t)l * DPROJ + src];
#pragma unroll
        for (int l = 0; l < SEQL; l++) {
            float sv = bb + v[l] * w3;
            if (l >= 1) sv += v[l - 1] * w2;
            if (l >= 2) sv += v[l - 2] * w1;
            if (l >= 3) sv += v[l - 3] * w0;
            xsh[l][t] = sv / (1.f + expf(-sv));
        }
    }
    if (t >= 64 && t < 64 + SEQL) {
        const int l = t - 64;
        float xr = zrow[(size_t)l * DPROJ + (D_INNER + CONV_DIM) + h] + dt_bias[h];
        float dt = (xr > 20.f) ? xr : log1pf(expf(xr));
        dts[l] = dt;
        dAs[l] = expf(-expf(A_log[h]) * dt);
    }
    __syncthreads();

    const int p = t >> 2;
    const int q = t & 3;
    float st[32];
#pragma unroll
    for (int i = 0; i < 32; i++) st[i] = 0.f;
    const float Dh = Dp[h];

#pragma unroll
    for (int l = 0; l < SEQL; l++) {
        const float xv   = xsh[l][p];
        const float coef = dts[l] * xv;
        const float dAv  = dAs[l];
        float part = 0.f;
#pragma unroll
        for (int i = 0; i < 32; i++) {
            const int sidx = q + 4 * i;
            st[i] = fmaf(dAv, st[i], coef * Bsh[l][sidx]);
            part  = fmaf(st[i], Csh[l][sidx], part);
        }
        part += __shfl_down_sync(0xffffffffu, part, 2);
        part += __shfl_down_sync(0xffffffffu, part, 1);
        if (q == 0)
            y[((size_t)b * SEQL + l) * D_INNER + h * HEADDIM + p] = part + xv * Dh;
    }
}

// ---------------------------------------------------------------------------
// y = y * silu(z); y *= rsqrt(mean(y^2)+1e-5) * norm_w; emit split A-tiles.
// ---------------------------------------------------------------------------
__global__ void __launch_bounds__(256)
gated_rmsnorm_split_kernel(const float* __restrict__ ybuf,
                           const float* __restrict__ zx,
                           const float* __restrict__ norm_w,
                           __nv_bfloat16* __restrict__ hi,
                           __nv_bfloat16* __restrict__ lo)
{
    const size_t row = blockIdx.x;
    const int t = threadIdx.x;
    const int d0 = t * 8;
    const float* yb = ybuf + row * D_INNER;
    const float* zb = zx   + row * DPROJ;

    float v[8];
    float ss = 0.f;
#pragma unroll
    for (int j = 0; j < 8; j += 4) {
        float4 yv = *(const float4*)(yb + d0 + j);
        float4 zv = *(const float4*)(zb + d0 + j);
        v[j + 0] = yv.x * (zv.x / (1.f + expf(-zv.x)));
        v[j + 1] = yv.y * (zv.y / (1.f + expf(-zv.y)));
        v[j + 2] = yv.z * (zv.z / (1.f + expf(-zv.z)));
        v[j + 3] = yv.w * (zv.w / (1.f + expf(-zv.w)));
        ss = fmaf(v[j+0], v[j+0], ss); ss = fmaf(v[j+1], v[j+1], ss);
        ss = fmaf(v[j+2], v[j+2], ss); ss = fmaf(v[j+3], v[j+3], ss);
    }
#pragma unroll
    for (int o = 16; o > 0; o >>= 1)
        ss += __shfl_down_sync(0xffffffffu, ss, o);

    __shared__ float red[8];
    __shared__ float s_scale;
    if ((t & 31) == 0) red[t >> 5] = ss;
    __syncthreads();
    if (t == 0) {
        float s = 0.f;
        for (int i = 0; i < 8; i++) s += red[i];
        s_scale = rsqrtf(s / (float)D_INNER + 1e-5f);
    }
    __syncthreads();
    const float scale = s_scale;

#pragma unroll
    for (int j = 0; j < 8; j += 2) {
        int d = d0 + j;
        float v0 = v[j]     * scale * norm_w[d];
        float v1 = v[j + 1] * scale * norm_w[d + 1];
        split_store(hi, lo, tile_off(row, d, D_INNER >> 6), v0, v1);
    }
}

// ---------------------------------------------------------------------------
// Final tiny layer: out = A(256x1024) @ W(1024x2) + b. One CTA per row.
// ---------------------------------------------------------------------------
__global__ void __launch_bounds__(256)
final_kernel(const float* __restrict__ A, const float* __restrict__ W,
             const float* __restrict__ bias, float* __restrict__ out)
{
    const int m = blockIdx.x;
    const int t = threadIdx.x;
    float4 a = ((const float4*)(A + (size_t)m * 1024))[t];
    const float4 w0 = ((const float4*)W)[2 * t];
    const float4 w1 = ((const float4*)W)[2 * t + 1];
    float s0 = a.x * w0.x + a.y * w0.z + a.z * w1.x + a.w * w1.z;
    float s1 = a.x * w0.y + a.y * w0.w + a.z * w1.y + a.w * w1.w;
#pragma unroll
    for (int o = 16; o > 0; o >>= 1) {
        s0 += __shfl_down_sync(0xffffffffu, s0, o);
        s1 += __shfl_down_sync(0xffffffffu, s1, o);
    }
    __shared__ float r0[8], r1[8];
    if ((t & 31) == 0) { r0[t >> 5] = s0; r1[t >> 5] = s1; }
    __syncthreads();
    if (t == 0) {
        float a0 = 0.f, a1 = 0.f;
        for (int i = 0; i < 8; i++) { a0 += r0[i]; a1 += r1[i]; }
        out[m * 2 + 0] = a0 + bias[0];
        out[m * 2 + 1] = a1 + bias[1];
    }
}

// ---------------------------------------------------------------------------
// Host-side orchestration
// ---------------------------------------------------------------------------
struct MambaW {
    const float *in_proj, *conv_w, *conv_b, *dt_bias, *A_log, *D, *norm_w, *out_proj;
};

extern "C" void kernel_launch(void* const* d_in, const int* in_sizes, int n_in,
                              void* d_out, int out_size)
{
    const float* x      = (const float*)d_in[0];
    const float* w_in1  = (const float*)d_in[1];
    const float* b_in1  = (const float*)d_in[2];
    const float* w_in2  = (const float*)d_in[3];
    const float* b_in2  = (const float*)d_in[4];
    MambaW m1 = { (const float*)d_in[5],  (const float*)d_in[6],  (const float*)d_in[7],
                  (const float*)d_in[8],  (const float*)d_in[9],  (const float*)d_in[10],
                  (const float*)d_in[11], (const float*)d_in[12] };
    MambaW m2 = { (const float*)d_in[13], (const float*)d_in[14], (const float*)d_in[15],
                  (const float*)d_in[16], (const float*)d_in[17], (const float*)d_in[18],
                  (const float*)d_in[19], (const float*)d_in[20] };
    const float* w_out1 = (const float*)d_in[21];
    const float* b_out1 = (const float*)d_in[22];
    const float* w_out2 = (const float*)d_in[23];
    const float* b_out2 = (const float*)d_in[24];
    float* out = (float*)d_out;

    cudaFuncSetAttribute(tc_gemm_kernel<0, 0>,
                         cudaFuncAttributeMaxDynamicSharedMemorySize, TCG_SMEM);
    cudaFuncSetAttribute(tc_gemm_kernel<0, 1>,
                         cudaFuncAttributeMaxDynamicSharedMemorySize, TCG_SMEM);
    cudaFuncSetAttribute(tc_gemm_kernel<0, 2>,
                         cudaFuncAttributeMaxDynamicSharedMemorySize, TCG_SMEM);
    cudaFuncSetAttribute(tc_gemm_kernel<1, 0>,
                         cudaFuncAttributeMaxDynamicSharedMemorySize, TCG_SMEM);

    float *a, *zx, *ybuf, *part;
    __nv_bfloat16 *whi, *wlo, *p1h, *p1l, *p2h, *p2l;
    cudaGetSymbolAddress((void**)&a,    g_a);
    cudaGetSymbolAddress((void**)&zx,   g_zx);
    cudaGetSymbolAddress((void**)&ybuf, g_y);
    cudaGetSymbolAddress((void**)&part, g_part);
    cudaGetSymbolAddress((void**)&whi,  g_whi);
    cudaGetSymbolAddress((void**)&wlo,  g_wlo);
    cudaGetSymbolAddress((void**)&p1h,  g_p1hi);
    cudaGetSymbolAddress((void**)&p1l,  g_p1lo);
    cudaGetSymbolAddress((void**)&p2h,  g_p2hi);
    cudaGetSymbolAddress((void**)&p2l,  g_p2lo);

    // ---- weight preprocessing (streaming convert, no transpose)
    auto cvt = [&](const float* W, size_t off, int K, int N, int Npad) {
        convert_b_kernel<<<dim3(Npad / 256, K / 64), 256>>>(
            W, whi + off, wlo + off, K, N);
    };
    cvt(w_in1,       OFF_WIN1,    1024, 8192, 8192);
    cvt(w_in2,       OFF_WIN2,    8192, 8192, 8192);
    cvt(m1.in_proj,  OFF_M1_INP,  1024, DPROJ, 4608);
    cvt(m2.in_proj,  OFF_M2_INP,  1024, DPROJ, 4608);
    cvt(m1.out_proj, OFF_M1_OUTP, 2048, 1024, 1024);
    cvt(m2.out_proj, OFF_M2_OUTP, 2048, 1024, 1024);
    cvt(w_out1,      OFF_WOUT1,   8192, 1024, 1024);

    // ---- split x -> p1 (256 x 1024, kshift 10)
    split_a_kernel<<<(BATCH * 1024 / 4 + 255) / 256, 256>>>(x, p1h, p1l,
                                                            BATCH * 1024 / 4, 10);

    const size_t MN_256x8192  = (size_t)BATCH * 8192;
    const size_t MN_2048x1024 = (size_t)ROWS * 1024;
    const size_t MN_256x1024  = (size_t)BATCH * 1024;

    // ---- MLP in (split-K x4)
    tc_gemm_kernel<0, 2><<<dim3(32, 2, 4), 512, TCG_SMEM>>>(
        p1h, p1l, whi + OFF_WIN1, wlo + OFF_WIN1, nullptr,
        part, nullptr, nullptr, 13, 4, BATCH, 8192, 1024);
    reduce_kernel<1, 1><<<(unsigned)(MN_256x8192 / 512), 256>>>(
        part, 4, MN_256x8192, b_in1, 8191, nullptr, p2h, p2l, 13);
    tc_gemm_kernel<0, 2><<<dim3(32, 2, 4), 512, TCG_SMEM>>>(
        p2h, p2l, whi + OFF_WIN2, wlo + OFF_WIN2, nullptr,
        part, nullptr, nullptr, 10, 32, BATCH, 8192, 8192);
    reduce_kernel<0, 1><<<(unsigned)(MN_256x8192 / 512), 256>>>(
        part, 4, MN_256x8192, b_in2, 8191, nullptr, p1h, p1l, 10);

    // ---- 2x Mamba2 layers (h tiles live in p1 as (2048, 1024))
    const MambaW* layers[2] = { &m1, &m2 };
    const size_t inp_off[2]  = { OFF_M1_INP,  OFF_M2_INP };
    const size_t outp_off[2] = { OFF_M1_OUTP, OFF_M2_OUTP };
    for (int li = 0; li < 2; li++) {
        const MambaW& p = *layers[li];
        // zx = h @ in_proj (fp32 out, 288 CTAs, no split)
        tc_gemm_kernel<0, 0><<<dim3(18, 16, 1), 512, TCG_SMEM>>>(
            p1h, p1l, whi + inp_off[li], wlo + inp_off[li], nullptr,
            zx, nullptr, nullptr, 0, 16, ROWS, DPROJ, 1024);
        fused_scan_kernel<<<dim3(BATCH, NHEADS), 256>>>(
            zx, p.conv_w, p.conv_b, p.dt_bias, p.A_log, p.D, ybuf);
        gated_rmsnorm_split_kernel<<<ROWS, 256>>>(ybuf, zx, p.norm_w, p2h, p2l);
        // h = y @ out_proj: split-K x4, reduce -> p1 tiles
        int ksh_next = (li == 0) ? 10 : 13;
        tc_gemm_kernel<0, 2><<<dim3(4, 16, 4), 512, TCG_SMEM>>>(
            p2h, p2l, whi + outp_off[li], wlo + outp_off[li], nullptr,
            part, nullptr, nullptr, ksh_next, 8, ROWS, 1024, 2048);
        reduce_kernel<0, 1><<<(unsigned)(MN_2048x1024 / 512), 256>>>(
            part, 4, MN_2048x1024, nullptr, 1023, nullptr, p1h, p1l, ksh_next);
    }

    // ---- MLP out: split-K x32, reduce(relu+bias) -> fp32 a; final dot
    tc_gemm_kernel<0, 2><<<dim3(4, 2, 32), 512, TCG_SMEM>>>(
        p1h, p1l, whi + OFF_WOUT1, wlo + OFF_WOUT1, nullptr,
        part, nullptr, nullptr, 0, 4, BATCH, 1024, 8192);
    reduce_kernel<1, 0><<<(unsigned)(MN_256x1024 / 512), 256>>>(
        part, 32, MN_256x1024, b_out1, 1023, a, nullptr, nullptr, 0);
    final_kernel<<<BATCH, 256>>>(a, w_out2, b_out2, out);
}